// round 2
// baseline (speedup 1.0000x reference)
#include <cuda_runtime.h>
#include <cstdint>
#include <cstddef>

// Problem constants
#define B_ 256
#define L_ 512
#define D_ 768
#define H_ 1000
#define HP_ 1024   // hidden padded to 1024 (pad cols have aw2=0 -> contribute 0)
#define XDIM 2324  // 2*768 + 768 + 20

// ---------------- scratch (static device globals; no allocation) ----------------
__device__ float g_aw1p[D_ * HP_];   // padded + tf32-rounded aw1, [k][h] row-major
__device__ float g_ab1p[HP_];
__device__ float g_aw2p[HP_];
__device__ float g_attns[B_ * L_];
__device__ int   g_spans[B_ * 2];    // normalized int32 spans
__device__ float g_x [B_ * XDIM];
__device__ float g_h1[B_ * 1024];
__device__ float g_h2[B_ * 512];
__device__ float g_h3[B_ * 256];

__device__ __forceinline__ uint32_t f2tf(float x) {
    uint32_t r;
    asm("cvt.rna.tf32.f32 %0, %1;" : "=r"(r) : "f"(x));
    return r;
}

// ---------------- spans normalization: int32-vs-int64 sniff ---------------------
// JAX with x64 disabled downcasts jnp.int64 -> int32, so spans is most likely
// int32. Detect robustly: read first 512 ints (safe under both dtypes). If ALL
// odd-indexed ints are zero, buffer is int64 (high words of values < 512);
// otherwise int32 (odd ints are random `end` values, never all zero).
__global__ void prep_spans(const int* __restrict__ sp) {
    int t = threadIdx.x;                 // 0..255 == batch index
    int odd = sp[2 * t + 1];
    int any_odd = __syncthreads_or(odd != 0);
    if (any_odd) {                       // int32 layout
        g_spans[2 * t]     = sp[2 * t];
        g_spans[2 * t + 1] = sp[2 * t + 1];
    } else {                             // int64 layout (little-endian low words)
        g_spans[2 * t]     = sp[4 * t];
        g_spans[2 * t + 1] = sp[4 * t + 2];
    }
}

// ---------------- prep: pad aw1/ab1/aw2 to 1024 hidden, round aw1 to tf32 ------
__global__ void prep_pad(const float* __restrict__ aw1, const float* __restrict__ ab1,
                         const float* __restrict__ aw2) {
    int gid = blockIdx.x * 256 + threadIdx.x;
    if (gid < D_ * HP_) {
        int k = gid >> 10, h = gid & 1023;
        float v = (h < H_) ? aw1[k * H_ + h] : 0.f;
        g_aw1p[gid] = __uint_as_float(f2tf(v));
    }
    if (gid < HP_) {
        g_ab1p[gid] = (gid < H_) ? ab1[gid] : 0.f;
        g_aw2p[gid] = (gid < H_) ? aw2[gid] : 0.f;
    }
}

// ---------------- attn scores: masked tiles, tf32 mma ---------------------------
// grid (L/128, B), 256 threads (8 warps = 4 m-warps x 2 n-warps)
// per block: 128 positions x (1024 hidden in 8 chunks of 128) x K=768 (chunks of 32)
#define TM 128
#define TN 128
#define TKC 32

__global__ void __launch_bounds__(256) attn_kernel(const float* __restrict__ E) {
    int b  = blockIdx.y;
    int t0 = blockIdx.x * TM;
    int s = g_spans[b * 2], e = g_spans[b * 2 + 1];
    if (e < t0 || s > t0 + TM - 1) return;   // tile disjoint from span: skip

    __shared__ float As[TM][TKC + 4];    // 128 x 36 (conflict-free frag reads)
    __shared__ float Bs[TKC][TN + 8];    // 32 x 136 (conflict-free frag reads)
    __shared__ float acc_s[TM];

    int tid  = threadIdx.x;
    int warp = tid >> 5, lane = tid & 31;
    int g = lane >> 2, tig = lane & 3;
    int wm = warp & 3, wn = warp >> 2;

    if (tid < TM) acc_s[tid] = 0.f;

    const float* Eb = E + ((size_t)b * L_ + t0) * D_;

    for (int nc = 0; nc < HP_ / TN; nc++) {
        int n0 = nc * TN;
        float c[2][8][4];
        #pragma unroll
        for (int i = 0; i < 2; i++)
            #pragma unroll
            for (int j = 0; j < 8; j++)
                #pragma unroll
                for (int q = 0; q < 4; q++) c[i][j][q] = 0.f;

        for (int kc = 0; kc < D_; kc += TKC) {
            __syncthreads();   // protect smem from previous iteration's readers
            // A tile: 128x32 from E, convert to tf32. 4 float4 per thread.
            {
                int m  = tid >> 1;                  // row (2 threads per row)
                int q0 = (tid & 1) * 16;            // starting float col
                #pragma unroll
                for (int r = 0; r < 4; r++) {
                    float4 v = *(const float4*)(Eb + (size_t)m * D_ + kc + q0 + r * 4);
                    As[m][q0 + r * 4 + 0] = __uint_as_float(f2tf(v.x));
                    As[m][q0 + r * 4 + 1] = __uint_as_float(f2tf(v.y));
                    As[m][q0 + r * 4 + 2] = __uint_as_float(f2tf(v.z));
                    As[m][q0 + r * 4 + 3] = __uint_as_float(f2tf(v.w));
                }
            }
            // B tile: 32x128 from padded aw1 (already tf32). 4 float4 per thread.
            {
                int row = tid >> 3;                 // 8 threads per 128-wide row
                int q0  = (tid & 7) * 16;
                #pragma unroll
                for (int r = 0; r < 4; r++) {
                    float4 v = *(const float4*)(g_aw1p + (size_t)(kc + row) * HP_ + n0 + q0 + r * 4);
                    *(float4*)&Bs[row][q0 + r * 4] = v;
                }
            }
            __syncthreads();

            #pragma unroll
            for (int ks = 0; ks < 4; ks++) {
                int k = ks * 8;
                uint32_t a[2][4], bb[8][2];
                #pragma unroll
                for (int i = 0; i < 2; i++) {
                    int mb = wm * 32 + i * 16;
                    a[i][0] = __float_as_uint(As[mb + g     ][k + tig    ]);
                    a[i][1] = __float_as_uint(As[mb + g +  8][k + tig    ]);
                    a[i][2] = __float_as_uint(As[mb + g     ][k + tig + 4]);
                    a[i][3] = __float_as_uint(As[mb + g +  8][k + tig + 4]);
                }
                #pragma unroll
                for (int j = 0; j < 8; j++) {
                    int nb = wn * 64 + j * 8;
                    bb[j][0] = __float_as_uint(Bs[k + tig    ][nb + g]);
                    bb[j][1] = __float_as_uint(Bs[k + tig + 4][nb + g]);
                }
                #pragma unroll
                for (int i = 0; i < 2; i++)
                    #pragma unroll
                    for (int j = 0; j < 8; j++)
                        asm volatile(
                            "mma.sync.aligned.m16n8k8.row.col.f32.tf32.tf32.f32 "
                            "{%0,%1,%2,%3}, {%4,%5,%6,%7}, {%8,%9}, {%0,%1,%2,%3};\n"
                            : "+f"(c[i][j][0]), "+f"(c[i][j][1]),
                              "+f"(c[i][j][2]), "+f"(c[i][j][3])
                            : "r"(a[i][0]), "r"(a[i][1]), "r"(a[i][2]), "r"(a[i][3]),
                              "r"(bb[j][0]), "r"(bb[j][1]));
            }
        }
        // epilogue: lrelu(c + b1) * aw2, reduce over hidden chunk into per-row acc
        #pragma unroll
        for (int i = 0; i < 2; i++) {
            float ra = 0.f, rb = 0.f;
            #pragma unroll
            for (int j = 0; j < 8; j++) {
                int col0 = n0 + wn * 64 + j * 8 + tig * 2;
                float b1a = g_ab1p[col0], b1b = g_ab1p[col0 + 1];
                float w2a = g_aw2p[col0], w2b = g_aw2p[col0 + 1];
                float z;
                z = c[i][j][0] + b1a; ra += (z > 0.f ? z : 0.01f * z) * w2a;
                z = c[i][j][1] + b1b; ra += (z > 0.f ? z : 0.01f * z) * w2b;
                z = c[i][j][2] + b1a; rb += (z > 0.f ? z : 0.01f * z) * w2a;
                z = c[i][j][3] + b1b; rb += (z > 0.f ? z : 0.01f * z) * w2b;
            }
            ra += __shfl_xor_sync(0xffffffffu, ra, 1);
            ra += __shfl_xor_sync(0xffffffffu, ra, 2);
            rb += __shfl_xor_sync(0xffffffffu, rb, 1);
            rb += __shfl_xor_sync(0xffffffffu, rb, 2);
            if (tig == 0) {
                atomicAdd(&acc_s[wm * 32 + i * 16 + g    ], ra);
                atomicAdd(&acc_s[wm * 32 + i * 16 + 8 + g], rb);
            }
        }
    }
    __syncthreads();
    // ab2 is a uniform logit offset -> softmax-invariant, dropped
    if (tid < TM) g_attns[b * L_ + t0 + tid] = acc_s[tid];
}

// ---------------- softmax over span + weighted reduce + build concat x ----------
// grid (B), 256 threads
__global__ void __launch_bounds__(256) softmax_build(const float* __restrict__ E,
                                                     const float* __restrict__ width_emb) {
    int b = blockIdx.x;
    int tid = threadIdx.x;
    int s = g_spans[b * 2], e = g_spans[b * 2 + 1];
    int width = e - s + 1;

    __shared__ float ws[L_];
    __shared__ float red[256];

    // max over masked logits
    float lm = -1e30f;
    for (int l = s + tid; l <= e; l += 256) lm = fmaxf(lm, g_attns[b * L_ + l]);
    red[tid] = lm; __syncthreads();
    for (int st = 128; st > 0; st >>= 1) {
        if (tid < st) red[tid] = fmaxf(red[tid], red[tid + st]);
        __syncthreads();
    }
    float mx = red[0];
    __syncthreads();
    // exp + sum
    float ls = 0.f;
    for (int l = s + tid; l <= e; l += 256) {
        float ev = __expf(g_attns[b * L_ + l] - mx);
        ws[l - s] = ev;
        ls += ev;
    }
    red[tid] = ls; __syncthreads();
    for (int st = 128; st > 0; st >>= 1) {
        if (tid < st) red[tid] += red[tid + st];
        __syncthreads();
    }
    float inv = 1.f / red[0];

    // attn_embeds = sum_l w_l * E[b,l,:]   (each thread owns dims tid, tid+256, tid+512)
    float a0 = 0.f, a1 = 0.f, a2 = 0.f;
    const float* Ebase = E + (size_t)b * L_ * D_;
    for (int l = 0; l < width; l++) {
        float wv = ws[l];
        const float* row = Ebase + (size_t)(s + l) * D_;
        a0 += wv * row[tid];
        a1 += wv * row[tid + 256];
        a2 += wv * row[tid + 512];
    }
    float* xb = g_x + (size_t)b * XDIM;
    xb[1536 + tid      ] = a0 * inv;
    xb[1536 + tid + 256] = a1 * inv;
    xb[1536 + tid + 512] = a2 * inv;

    // se = [E[b,start,:], E[b,end,:]]
    const float* rs = Ebase + (size_t)s * D_;
    const float* re = Ebase + (size_t)e * D_;
    for (int d = tid; d < D_; d += 256) { xb[d] = rs[d]; xb[D_ + d] = re[d]; }

    // width embedding
    if (tid < 20) {
        const int bins[15] = {1,2,3,4,5,6,7,8,12,16,20,24,32,64,128};
        int idx = 0;
        #pragma unroll
        for (int j = 0; j < 15; j++) idx += (width > bins[j]) ? 1 : 0;
        xb[2304 + tid] = width_emb[idx * 20 + tid];
    }
}

// ---------------- generic tiled fp32 GEMM with bias + optional leaky relu -------
// grid (ceil(N/64), ceil(M/64)), 256 threads, 4x4 microtile
template<int ACT>
__global__ void __launch_bounds__(256) gemm_bias(const float* __restrict__ A,
                                                 const float* __restrict__ W,
                                                 const float* __restrict__ bias,
                                                 float* __restrict__ C,
                                                 int M, int N, int K) {
    __shared__ float As[16][65];
    __shared__ float Bs[16][64];
    int tid = threadIdx.x;
    int ttx = tid & 15, tty = tid >> 4;
    int bm = blockIdx.y * 64, bn = blockIdx.x * 64;
    float acc[4][4] = {};

    for (int k0 = 0; k0 < K; k0 += 16) {
        #pragma unroll
        for (int r = 0; r < 4; r++) {
            int idx = tid * 4 + r;
            int m = idx >> 4, k = idx & 15;
            float v = 0.f;
            if (bm + m < M && k0 + k < K) v = A[(size_t)(bm + m) * K + k0 + k];
            As[k][m] = v;
        }
        #pragma unroll
        for (int r = 0; r < 4; r++) {
            int idx = tid * 4 + r;
            int k = idx >> 6, n = idx & 63;
            float v = 0.f;
            if (k0 + k < K && bn + n < N) v = W[(size_t)(k0 + k) * N + bn + n];
            Bs[k][n] = v;
        }
        __syncthreads();
        #pragma unroll
        for (int kk = 0; kk < 16; kk++) {
            float ra[4], rb[4];
            #pragma unroll
            for (int i = 0; i < 4; i++) ra[i] = As[kk][tty * 4 + i];
            #pragma unroll
            for (int j = 0; j < 4; j++) rb[j] = Bs[kk][ttx * 4 + j];
            #pragma unroll
            for (int i = 0; i < 4; i++)
                #pragma unroll
                for (int j = 0; j < 4; j++) acc[i][j] += ra[i] * rb[j];
        }
        __syncthreads();
    }
    #pragma unroll
    for (int i = 0; i < 4; i++) {
        int row = bm + tty * 4 + i;
        if (row >= M) continue;
        #pragma unroll
        for (int j = 0; j < 4; j++) {
            int col = bn + ttx * 4 + j;
            if (col >= N) continue;
            float v = acc[i][j] + bias[col];
            if (ACT) v = v > 0.f ? v : 0.01f * v;
            C[(size_t)row * N + col] = v;
        }
    }
}

// ---------------- launch ---------------------------------------------------------
extern "C" void kernel_launch(void* const* d_in, const int* in_sizes, int n_in,
                              void* d_out, int out_size) {
    const float* embeds    = (const float*)d_in[0];
    const int*   spans_raw = (const int*)d_in[1];
    const float* aw1       = (const float*)d_in[2];
    const float* ab1       = (const float*)d_in[3];
    const float* aw2       = (const float*)d_in[4];
    // d_in[5] = ab2 : uniform logit offset, softmax-invariant -> unused
    const float* width_emb = (const float*)d_in[6];
    const float* sw1 = (const float*)d_in[7];
    const float* sb1 = (const float*)d_in[8];
    const float* sw2 = (const float*)d_in[9];
    const float* sb2 = (const float*)d_in[10];
    const float* sw3 = (const float*)d_in[11];
    const float* sb3 = (const float*)d_in[12];
    const float* sw4 = (const float*)d_in[13];
    const float* sb4 = (const float*)d_in[14];
    float* out = (float*)d_out;

    float *x, *h1, *h2, *h3;
    cudaGetSymbolAddress((void**)&x,  g_x);
    cudaGetSymbolAddress((void**)&h1, g_h1);
    cudaGetSymbolAddress((void**)&h2, g_h2);
    cudaGetSymbolAddress((void**)&h3, g_h3);

    prep_spans<<<1, 256>>>(spans_raw);
    prep_pad<<<(D_ * HP_ + 255) / 256, 256>>>(aw1, ab1, aw2);
    attn_kernel<<<dim3(L_ / TM, B_), 256>>>(embeds);
    softmax_build<<<B_, 256>>>(embeds, width_emb);
    gemm_bias<1><<<dim3(1024 / 64, B_ / 64), 256>>>(x,  sw1, sb1, h1, B_, 1024, XDIM);
    gemm_bias<1><<<dim3(512  / 64, B_ / 64), 256>>>(h1, sw2, sb2, h2, B_, 512, 1024);
    gemm_bias<1><<<dim3(256  / 64, B_ / 64), 256>>>(h2, sw3, sb3, h3, B_, 256, 512);
    gemm_bias<0><<<dim3(1,         B_ / 64), 256>>>(h3, sw4, sb4, out, B_, 30, 256);
}

// round 4
// speedup vs baseline: 1.7758x; 1.7758x over previous
#include <cuda_runtime.h>
#include <cstdint>
#include <cstddef>

// Problem constants
#define B_ 256
#define L_ 512
#define D_ 768
#define H_ 1000
#define HP_ 1024
#define XDIM 2324
#define XPAD 2336

// attn tiling
#define KC 32
#define NKC 24          // 768/32
#define TM 128
#define NCP 4           // 1024 hidden / 256 per pass

// packed B tile geometry (float2 units)
#define BT_TSTRIDE 260              // per tig-row stride (bank-conflict-free)
#define BT_KSSTRIDE (4*BT_TSTRIDE)  // 1040
#define BT_TILE (4*BT_KSSTRIDE)     // 4160 float2 per (kc,nc) tile
#define A_RSTRIDE 20                // float2 per A row

// ---------------- scratch -------------------------------------------------------
__device__ int    g_spans[B_ * 2];
__device__ int    g_ntiles;
__device__ int    g_pos[B_ * L_];
__device__ float  g_attns[B_ * L_];
__device__ float  g_ab1p[HP_];
__device__ float  g_aw2p[HP_];
__device__ float4 g_aw1pk4[NKC * NCP * 2080];   // packed pair-layout aw1 tiles
__device__ float  g_x [B_ * XPAD];
__device__ float  g_sw1p[XPAD * 1024];
__device__ float  g_part[8 * 256 * 1024];
__device__ float  g_h1[B_ * 1024];
__device__ float  g_h2[B_ * 512];
__device__ float  g_h3[B_ * 256];

__device__ __forceinline__ uint32_t f2tf(float x) {
    uint32_t r;
    asm("cvt.rna.tf32.f32 %0, %1;" : "=r"(r) : "f"(x));
    return r;
}
__device__ __forceinline__ float tfv(float x) { return __uint_as_float(f2tf(x)); }

__device__ __forceinline__ void cp16(void* smem_dst, const void* gsrc) {
    uint32_t s = (uint32_t)__cvta_generic_to_shared(smem_dst);
    asm volatile("cp.async.cg.shared.global [%0], [%1], 16;\n" :: "r"(s), "l"(gsrc));
}
#define CP_COMMIT asm volatile("cp.async.commit_group;\n" ::: "memory")
#define CP_WAIT0  asm volatile("cp.async.wait_group 0;\n" ::: "memory")

__device__ __forceinline__ void mma_tf32(float* c, uint32_t a0, uint32_t a1,
                                         uint32_t a2, uint32_t a3,
                                         uint32_t b0, uint32_t b1) {
    asm volatile(
        "mma.sync.aligned.m16n8k8.row.col.f32.tf32.tf32.f32 "
        "{%0,%1,%2,%3}, {%4,%5,%6,%7}, {%8,%9}, {%0,%1,%2,%3};\n"
        : "+f"(c[0]), "+f"(c[1]), "+f"(c[2]), "+f"(c[3])
        : "r"(a0), "r"(a1), "r"(a2), "r"(a3), "r"(b0), "r"(b1));
}

// ---------------- preps ---------------------------------------------------------
__global__ void prep_spans(const int* __restrict__ sp) {
    int t = threadIdx.x;
    int odd = sp[2 * t + 1];
    int any_odd = __syncthreads_or(odd != 0);
    if (any_odd) { g_spans[2 * t] = sp[2 * t];     g_spans[2 * t + 1] = sp[2 * t + 1]; }
    else         { g_spans[2 * t] = sp[4 * t];     g_spans[2 * t + 1] = sp[4 * t + 2]; }
}

__global__ void prep_compact() {
    __shared__ int offs[257];
    int t = threadIdx.x;
    int s = g_spans[2 * t], e = g_spans[2 * t + 1], w = e - s + 1;
    offs[t + 1] = w;
    if (t == 0) offs[0] = 0;
    __syncthreads();
    if (t == 0) {
        for (int i = 1; i <= 256; i++) offs[i] += offs[i - 1];
        g_ntiles = (offs[256] + 127) >> 7;
    }
    __syncthreads();
    int base = offs[t];
    for (int k = 0; k < w; k++) g_pos[base + k] = (t << 16) | (s + k);
    int total = offs[256], NT = (total + 127) >> 7;
    for (int idx = total + t; idx < NT * 128; idx += 256) g_pos[idx] = (int)0x80000000;
}

__global__ void zero_attns() {
    int i = blockIdx.x * 256 + threadIdx.x;
    if (i < B_ * L_) g_attns[i] = 0.f;
}

__global__ void prep_small(const float* __restrict__ ab1, const float* __restrict__ aw2) {
    int i = blockIdx.x * 256 + threadIdx.x;
    if (i < HP_) {
        g_ab1p[i] = (i < H_) ? ab1[i] : 0.f;
        g_aw2p[i] = (i < H_) ? aw2[i] : 0.f;
    }
}

// pack aw1 into the per-(kc,nc) smem pair-layout
__global__ void prep_packB(const float* __restrict__ aw1) {
    int idx = blockIdx.x * 256 + threadIdx.x;
    if (idx >= NKC * NCP * BT_TILE) return;
    int tile = idx / BT_TILE, within = idx % BT_TILE;
    int kc = tile / NCP, nc = tile % NCP;
    int ks = within / BT_KSSTRIDE, rem = within % BT_KSSTRIDE;
    int t = rem / BT_TSTRIDE, n = rem % BT_TSTRIDE;
    float x = 0.f, y = 0.f;
    if (n < 256) {
        int col = nc * 256 + n;
        if (col < H_) {
            int kr = kc * 32 + ks * 8 + t;
            x = aw1[(size_t)kr * H_ + col];
            y = aw1[(size_t)(kr + 4) * H_ + col];
        }
    }
    float2* dst = (float2*)g_aw1pk4;
    dst[idx] = make_float2(tfv(x), tfv(y));
}

__global__ void prep_sw1p(const float* __restrict__ sw1) {
    size_t i = (size_t)blockIdx.x * 256 + threadIdx.x;
    if (i < (size_t)XPAD * 1024) {
        int r = (int)(i >> 10), c2 = (int)(i & 1023);
        g_sw1p[i] = (r < XDIM) ? sw1[(size_t)r * 1024 + c2] : 0.f;
    }
}

// ---------------- attn: compacted tiles, paired-LDS.64 tf32 mma -----------------
#define ATTN_SMEM (13440 * 8 + 128 * 4)

__global__ void __launch_bounds__(256, 1) attn_kernel(const float* __restrict__ E) {
    int unit = blockIdx.x;
    int tile = unit >> 2, ncp = unit & 3;
    if (tile >= g_ntiles) return;

    extern __shared__ float2 sm[];
    float2* As[2] = { sm, sm + 2560 };
    float2* Bs[2] = { sm + 5120, sm + 9280 };
    int* pos = (int*)(sm + 13440);

    int tid = threadIdx.x;
    if (tid < 128) pos[tid] = g_pos[tile * 128 + tid];
    __syncthreads();

    int warp = tid >> 5, lane = tid & 31, g = lane >> 2, tig = lane & 3;
    int wm = warp >> 2, wn = warp & 3;

    int arow = tid >> 1, ah = tid & 1;
    int p = pos[arow];
    int ab = (p >> 16) & 0x7FFF, al = p & 0xFFFF;
    const float* aptr = E + ((size_t)ab * L_ + al) * D_ + ah * 16;

    float c[4][8][4] = {};
    float4 va[4];

    // prolog kc=0
    {
        const float4* src = g_aw1pk4 + (size_t)(0 * NCP + ncp) * 2080;
        float4* dstb = (float4*)Bs[0];
        #pragma unroll
        for (int k = 0; k < 9; k++) { int i = tid + k * 256; if (i < 2080) cp16(dstb + i, src + i); }
        CP_COMMIT;
        const float4* s4 = (const float4*)aptr;
        va[0] = s4[0]; va[1] = s4[1]; va[2] = s4[2]; va[3] = s4[3];
        float* v = (float*)va;
        #pragma unroll
        for (int ksl = 0; ksl < 2; ksl++) {
            int ks = 2 * ah + ksl;
            float4* d = (float4*)(As[0] + arow * A_RSTRIDE + ks * 4);
            d[0] = make_float4(tfv(v[8*ksl+0]), tfv(v[8*ksl+4]), tfv(v[8*ksl+1]), tfv(v[8*ksl+5]));
            d[1] = make_float4(tfv(v[8*ksl+2]), tfv(v[8*ksl+6]), tfv(v[8*ksl+3]), tfv(v[8*ksl+7]));
        }
        CP_WAIT0;
        __syncthreads();
    }

    for (int kc = 0; kc < NKC; kc++) {
        int cur = kc & 1, nxt = cur ^ 1;
        if (kc < NKC - 1) {
            const float4* src = g_aw1pk4 + (size_t)((kc + 1) * NCP + ncp) * 2080;
            float4* dstb = (float4*)Bs[nxt];
            #pragma unroll
            for (int k = 0; k < 9; k++) { int i = tid + k * 256; if (i < 2080) cp16(dstb + i, src + i); }
            CP_COMMIT;
            const float4* s4 = (const float4*)(aptr + (kc + 1) * 32);
            va[0] = s4[0]; va[1] = s4[1]; va[2] = s4[2]; va[3] = s4[3];
        }
        const float2* Ac = As[cur];
        const float2* Bc = Bs[cur];
        #pragma unroll
        for (int ks = 0; ks < 4; ks++) {
            float2 afr[4][2];
            float2 bfr[8];
            #pragma unroll
            for (int i = 0; i < 4; i++) {
                int r0 = wm * 64 + i * 16 + g;
                afr[i][0] = Ac[r0 * A_RSTRIDE + ks * 4 + tig];
                afr[i][1] = Ac[(r0 + 8) * A_RSTRIDE + ks * 4 + tig];
            }
            #pragma unroll
            for (int j = 0; j < 8; j++) {
                int n = wn * 64 + j * 8 + g;
                bfr[j] = Bc[ks * BT_KSSTRIDE + tig * BT_TSTRIDE + n];
            }
            #pragma unroll
            for (int i = 0; i < 4; i++)
                #pragma unroll
                for (int j = 0; j < 8; j++)
                    mma_tf32(c[i][j],
                             __float_as_uint(afr[i][0].x), __float_as_uint(afr[i][1].x),
                             __float_as_uint(afr[i][0].y), __float_as_uint(afr[i][1].y),
                             __float_as_uint(bfr[j].x),    __float_as_uint(bfr[j].y));
        }
        if (kc < NKC - 1) {
            CP_WAIT0;
            __syncthreads();
            float* v = (float*)va;
            #pragma unroll
            for (int ksl = 0; ksl < 2; ksl++) {
                int ks = 2 * ah + ksl;
                float4* d = (float4*)(As[nxt] + arow * A_RSTRIDE + ks * 4);
                d[0] = make_float4(tfv(v[8*ksl+0]), tfv(v[8*ksl+4]), tfv(v[8*ksl+1]), tfv(v[8*ksl+5]));
                d[1] = make_float4(tfv(v[8*ksl+2]), tfv(v[8*ksl+6]), tfv(v[8*ksl+3]), tfv(v[8*ksl+7]));
            }
            __syncthreads();
        }
    }

    int n0 = ncp * 256;
    #pragma unroll
    for (int i = 0; i < 4; i++) {
        float ra = 0.f, rb = 0.f;
        #pragma unroll
        for (int j = 0; j < 8; j++) {
            int col0 = n0 + wn * 64 + j * 8 + tig * 2;
            float b1a = g_ab1p[col0], b1b = g_ab1p[col0 + 1];
            float w2a = g_aw2p[col0], w2b = g_aw2p[col0 + 1];
            float z;
            z = c[i][j][0] + b1a; ra += (z > 0.f ? z : 0.01f * z) * w2a;
            z = c[i][j][1] + b1b; ra += (z > 0.f ? z : 0.01f * z) * w2b;
            z = c[i][j][2] + b1a; rb += (z > 0.f ? z : 0.01f * z) * w2a;
            z = c[i][j][3] + b1b; rb += (z > 0.f ? z : 0.01f * z) * w2b;
        }
        ra += __shfl_xor_sync(0xffffffffu, ra, 1);
        ra += __shfl_xor_sync(0xffffffffu, ra, 2);
        rb += __shfl_xor_sync(0xffffffffu, rb, 1);
        rb += __shfl_xor_sync(0xffffffffu, rb, 2);
        if (tig == 0) {
            int r0 = wm * 64 + i * 16 + g;
            int p0 = pos[r0], p1 = pos[r0 + 8];
            if (p0 >= 0) atomicAdd(&g_attns[((p0 >> 16) & 0x7FFF) * L_ + (p0 & 0xFFFF)], ra);
            if (p1 >= 0) atomicAdd(&g_attns[((p1 >> 16) & 0x7FFF) * L_ + (p1 & 0xFFFF)], rb);
        }
    }
}

// ---------------- softmax over span + weighted reduce + build concat x ----------
__global__ void __launch_bounds__(256) softmax_build(const float* __restrict__ E,
                                                     const float* __restrict__ width_emb) {
    int b = blockIdx.x;
    int tid = threadIdx.x, warp = tid >> 5, lane = tid & 31;
    int s = g_spans[b * 2], e = g_spans[b * 2 + 1];
    int width = e - s + 1;

    __shared__ float ws[L_];
    __shared__ float red[256];
    __shared__ float sacc[D_];

    float lm = -1e30f;
    for (int l = s + tid; l <= e; l += 256) lm = fmaxf(lm, g_attns[b * L_ + l]);
    red[tid] = lm; __syncthreads();
    for (int st = 128; st > 0; st >>= 1) {
        if (tid < st) red[tid] = fmaxf(red[tid], red[tid + st]);
        __syncthreads();
    }
    float mx = red[0];
    __syncthreads();
    float ls = 0.f;
    for (int l = s + tid; l <= e; l += 256) {
        float ev = __expf(g_attns[b * L_ + l] - mx);
        ws[l - s] = ev;
        ls += ev;
    }
    red[tid] = ls; __syncthreads();
    for (int st = 128; st > 0; st >>= 1) {
        if (tid < st) red[tid] += red[tid + st];
        __syncthreads();
    }
    float inv = 1.f / red[0];
    for (int d = tid; d < D_; d += 256) sacc[d] = 0.f;
    __syncthreads();

    float acc[24];
    #pragma unroll
    for (int c2 = 0; c2 < 24; c2++) acc[c2] = 0.f;
    const float* Ebase = E + (size_t)b * L_ * D_;
    for (int l = s + warp; l <= e; l += 8) {
        float wv = ws[l - s];
        const float* row = Ebase + (size_t)l * D_;
        #pragma unroll
        for (int c2 = 0; c2 < 24; c2++) acc[c2] += wv * row[c2 * 32 + lane];
    }
    #pragma unroll
    for (int c2 = 0; c2 < 24; c2++) atomicAdd(&sacc[c2 * 32 + lane], acc[c2]);
    __syncthreads();

    float* xb = g_x + (size_t)b * XPAD;
    for (int d = tid; d < D_; d += 256) xb[1536 + d] = sacc[d] * inv;

    const float* rs = Ebase + (size_t)s * D_;
    const float* re = Ebase + (size_t)e * D_;
    for (int d = tid; d < D_; d += 256) { xb[d] = rs[d]; xb[D_ + d] = re[d]; }

    if (tid < 20) {
        const int bins[15] = {1,2,3,4,5,6,7,8,12,16,20,24,32,64,128};
        int idx = 0;
        #pragma unroll
        for (int j = 0; j < 15; j++) idx += (width > bins[j]) ? 1 : 0;
        xb[2304 + tid] = width_emb[idx * 20 + tid];
    }
    if (tid < XPAD - XDIM) xb[XDIM + tid] = 0.f;
}

// ---------------- 3xTF32 GEMM with K-split partials -----------------------------
// fp32-accurate: x = hi + lo (tf32 each); c += ah*bh + ah*bl + al*bh.
// block 128x128, 8 warps 2x4, warp 64x32, K-chunk 16. M%128==0, N%128==0, K%16==0.
__global__ void __launch_bounds__(256) gemm_3x(const float* __restrict__ A,
                                               const float* __restrict__ Bw,
                                               float* __restrict__ part,
                                               int M, int N, int K, int S) {
    __shared__ float Ah[128][20], Al[128][20];
    __shared__ float Bh[16][136], Bl[16][136];
    int tid = threadIdx.x, warp = tid >> 5, lane = tid & 31, g = lane >> 2, tig = lane & 3;
    int wm = warp >> 2, wn = warp & 3;
    int bm = blockIdx.y * 128, bn = blockIdx.x * 128;
    int nch = K >> 4;
    int z = blockIdx.z;
    int c0 = (int)((long)nch * z / S), c1 = (int)((long)nch * (z + 1) / S);

    float c[4][4][4] = {};
    for (int ch = c0; ch < c1; ch++) {
        int k0 = ch * 16;
        {   // A: 128 rows x 16 cols; 2 threads/row, 8 floats each
            int r = tid >> 1, h = (tid & 1) * 8;
            const float* src = A + (size_t)(bm + r) * K + k0 + h;
            float4 v0 = *(const float4*)src, v1 = *(const float4*)(src + 4);
            float vv[8] = {v0.x, v0.y, v0.z, v0.w, v1.x, v1.y, v1.z, v1.w};
            #pragma unroll
            for (int q = 0; q < 8; q++) {
                float hi = tfv(vv[q]);
                Ah[r][h + q] = hi;
                Al[r][h + q] = tfv(vv[q] - hi);
            }
        }
        {   // B: 16 rows x 128 cols; 16 threads/row, 8 floats each
            int r = tid >> 4, cb = (tid & 15) * 8;
            const float* src = Bw + (size_t)(k0 + r) * N + bn + cb;
            float4 v0 = *(const float4*)src, v1 = *(const float4*)(src + 4);
            float vv[8] = {v0.x, v0.y, v0.z, v0.w, v1.x, v1.y, v1.z, v1.w};
            #pragma unroll
            for (int q = 0; q < 8; q++) {
                float hi = tfv(vv[q]);
                Bh[r][cb + q] = hi;
                Bl[r][cb + q] = tfv(vv[q] - hi);
            }
        }
        __syncthreads();
        #pragma unroll
        for (int ks = 0; ks < 2; ks++) {
            int k = ks * 8;
            uint32_t ah4[4][4], al4[4][4], bh2[4][2], bl2[4][2];
            #pragma unroll
            for (int i = 0; i < 4; i++) {
                int mr = wm * 64 + i * 16;
                ah4[i][0] = __float_as_uint(Ah[mr + g    ][k + tig    ]);
                ah4[i][1] = __float_as_uint(Ah[mr + g + 8][k + tig    ]);
                ah4[i][2] = __float_as_uint(Ah[mr + g    ][k + tig + 4]);
                ah4[i][3] = __float_as_uint(Ah[mr + g + 8][k + tig + 4]);
                al4[i][0] = __float_as_uint(Al[mr + g    ][k + tig    ]);
                al4[i][1] = __float_as_uint(Al[mr + g + 8][k + tig    ]);
                al4[i][2] = __float_as_uint(Al[mr + g    ][k + tig + 4]);
                al4[i][3] = __float_as_uint(Al[mr + g + 8][k + tig + 4]);
            }
            #pragma unroll
            for (int j = 0; j < 4; j++) {
                int n = wn * 32 + j * 8 + g;
                bh2[j][0] = __float_as_uint(Bh[k + tig    ][n]);
                bh2[j][1] = __float_as_uint(Bh[k + tig + 4][n]);
                bl2[j][0] = __float_as_uint(Bl[k + tig    ][n]);
                bl2[j][1] = __float_as_uint(Bl[k + tig + 4][n]);
            }
            #pragma unroll
            for (int i = 0; i < 4; i++)
                #pragma unroll
                for (int j = 0; j < 4; j++) {
                    mma_tf32(c[i][j], al4[i][0], al4[i][1], al4[i][2], al4[i][3], bh2[j][0], bh2[j][1]);
                    mma_tf32(c[i][j], ah4[i][0], ah4[i][1], ah4[i][2], ah4[i][3], bl2[j][0], bl2[j][1]);
                    mma_tf32(c[i][j], ah4[i][0], ah4[i][1], ah4[i][2], ah4[i][3], bh2[j][0], bh2[j][1]);
                }
        }
        __syncthreads();
    }
    float* dst = part + ((size_t)z * M + bm) * N + bn;
    #pragma unroll
    for (int i = 0; i < 4; i++)
        #pragma unroll
        for (int j = 0; j < 4; j++) {
            int row = wm * 64 + i * 16 + g, col = wn * 32 + j * 8 + tig * 2;
            dst[(size_t)row * N + col]       = c[i][j][0];
            dst[(size_t)row * N + col + 1]   = c[i][j][1];
            dst[(size_t)(row+8) * N + col]   = c[i][j][2];
            dst[(size_t)(row+8) * N + col+1] = c[i][j][3];
        }
}

template<int ACT>
__global__ void combine(const float* __restrict__ part, const float* __restrict__ bias,
                        float* __restrict__ out, int MN, int N, int S) {
    int i = blockIdx.x * 256 + threadIdx.x;
    if (i >= MN) return;
    float v = 0.f;
    for (int z = 0; z < S; z++) v += part[(size_t)z * MN + i];
    v += bias[i % N];
    if (ACT) v = v > 0.f ? v : 0.01f * v;
    out[i] = v;
}

// ---------------- small fp32 GEMM for the final 256x30 layer --------------------
__global__ void __launch_bounds__(256) gemm_last(const float* __restrict__ A,
                                                 const float* __restrict__ W,
                                                 const float* __restrict__ bias,
                                                 float* __restrict__ C) {
    int m = blockIdx.x;
    int tid = threadIdx.x;
    int col = tid % 30, seg = tid / 30;
    __shared__ float red[256];
    float v = 0.f;
    if (seg < 8) {
        const float* a = A + (size_t)m * 256 + seg * 32;
        const float* w = W + col;
        #pragma unroll
        for (int k = 0; k < 32; k++) v += a[k] * w[(size_t)(seg * 32 + k) * 30];
    }
    red[tid] = v;
    __syncthreads();
    if (tid < 30) {
        float acc = 0.f;
        #pragma unroll
        for (int s2 = 0; s2 < 8; s2++) acc += red[s2 * 30 + tid];
        C[(size_t)m * 30 + tid] = acc + bias[tid];
    }
}

// ---------------- launch ---------------------------------------------------------
extern "C" void kernel_launch(void* const* d_in, const int* in_sizes, int n_in,
                              void* d_out, int out_size) {
    const float* embeds    = (const float*)d_in[0];
    const int*   spans_raw = (const int*)d_in[1];
    const float* aw1       = (const float*)d_in[2];
    const float* ab1       = (const float*)d_in[3];
    const float* aw2       = (const float*)d_in[4];
    // d_in[5] = ab2 : uniform logit offset, softmax-invariant -> unused
    const float* width_emb = (const float*)d_in[6];
    const float* sw1 = (const float*)d_in[7];
    const float* sb1 = (const float*)d_in[8];
    const float* sw2 = (const float*)d_in[9];
    const float* sb2 = (const float*)d_in[10];
    const float* sw3 = (const float*)d_in[11];
    const float* sb3 = (const float*)d_in[12];
    const float* sw4 = (const float*)d_in[13];
    const float* sb4 = (const float*)d_in[14];
    float* out = (float*)d_out;

    float *x, *h1, *h2, *h3, *part, *sw1p;
    cudaGetSymbolAddress((void**)&x,    g_x);
    cudaGetSymbolAddress((void**)&h1,   g_h1);
    cudaGetSymbolAddress((void**)&h2,   g_h2);
    cudaGetSymbolAddress((void**)&h3,   g_h3);
    cudaGetSymbolAddress((void**)&part, g_part);
    cudaGetSymbolAddress((void**)&sw1p, g_sw1p);

    static int smem_set = 0;
    if (!smem_set) {
        cudaFuncSetAttribute(attn_kernel, cudaFuncAttributeMaxDynamicSharedMemorySize, ATTN_SMEM);
        smem_set = 1;
    }

    prep_spans<<<1, 256>>>(spans_raw);                                        // 1
    prep_compact<<<1, 256>>>();                                               // 2
    zero_attns<<<512, 256>>>();                                               // 3
    prep_small<<<4, 256>>>(ab1, aw2);                                         // 4
    prep_packB<<<(NKC * NCP * BT_TILE + 255) / 256, 256>>>(aw1);              // 5
    attn_kernel<<<4096, 256, ATTN_SMEM>>>(embeds);                            // 6 (profiled)
    prep_sw1p<<<(XPAD * 1024 + 255) / 256, 256>>>(sw1);                       // 7
    softmax_build<<<B_, 256>>>(embeds, width_emb);                            // 8
    gemm_3x<<<dim3(8, 2, 8), 256>>>(x,  sw1p, part, 256, 1024, XPAD, 8);
    combine<1><<<(256 * 1024) / 256, 256>>>(part, sb1, h1, 256 * 1024, 1024, 8);
    gemm_3x<<<dim3(4, 2, 4), 256>>>(h1, sw2,  part, 256, 512, 1024, 4);
    combine<1><<<(256 * 512) / 256, 256>>>(part, sb2, h2, 256 * 512, 512, 4);
    gemm_3x<<<dim3(2, 2, 2), 256>>>(h2, sw3,  part, 256, 256, 512, 2);
    combine<1><<<(256 * 256) / 256, 256>>>(part, sb3, h3, 256 * 256, 256, 2);
    gemm_last<<<256, 256>>>(h3, sw4, sb4, out);
}

// round 5
// speedup vs baseline: 1.7928x; 1.0096x over previous
#include <cuda_runtime.h>
#include <cstdint>
#include <cstddef>

// Problem constants
#define B_ 256
#define L_ 512
#define D_ 768
#define H_ 1000
#define HP_ 1024
#define XDIM 2324
#define XPAD 2336

// attn tiling
#define KC 32
#define NKC 24          // 768/32
#define TM 128
#define NCP 4           // 1024 hidden / 256 per pass

// packed B tile geometry (float2 units)
#define BT_TSTRIDE 260              // per tig-row stride (bank-conflict-free)
#define BT_KSSTRIDE (4*BT_TSTRIDE)  // 1040
#define BT_TILE (4*BT_KSSTRIDE)     // 4160 float2 per (kc,nc) tile
#define A_RSTRIDE 20                // float2 per A row

// ---------------- scratch -------------------------------------------------------
__device__ int    g_spans[B_ * 2];
__device__ int    g_ntiles;
__device__ int    g_pos[B_ * L_];
__device__ float  g_attns[B_ * L_];
__device__ float  g_ab1p[HP_];
__device__ float  g_aw2p[HP_];
__device__ float4 g_aw1pk4[NKC * NCP * 2080];   // packed pair-layout aw1 tiles
__device__ float  g_x [B_ * XPAD];
__device__ float  g_sw1p[XPAD * 1024];
__device__ float  g_part[8 * 256 * 1024];
__device__ float  g_h1[B_ * 1024];
__device__ float  g_h2[B_ * 512];
__device__ float  g_h3[B_ * 256];

__device__ __forceinline__ uint32_t f2tf(float x) {
    uint32_t r;
    asm("cvt.rna.tf32.f32 %0, %1;" : "=r"(r) : "f"(x));
    return r;
}
__device__ __forceinline__ float tfv(float x) { return __uint_as_float(f2tf(x)); }

__device__ __forceinline__ void cp16(void* smem_dst, const void* gsrc) {
    uint32_t s = (uint32_t)__cvta_generic_to_shared(smem_dst);
    asm volatile("cp.async.cg.shared.global [%0], [%1], 16;\n" :: "r"(s), "l"(gsrc));
}
#define CP_COMMIT asm volatile("cp.async.commit_group;\n" ::: "memory")
#define CP_WAIT0  asm volatile("cp.async.wait_group 0;\n" ::: "memory")

__device__ __forceinline__ void mma_tf32(float* c, uint32_t a0, uint32_t a1,
                                         uint32_t a2, uint32_t a3,
                                         uint32_t b0, uint32_t b1) {
    asm volatile(
        "mma.sync.aligned.m16n8k8.row.col.f32.tf32.tf32.f32 "
        "{%0,%1,%2,%3}, {%4,%5,%6,%7}, {%8,%9}, {%0,%1,%2,%3};\n"
        : "+f"(c[0]), "+f"(c[1]), "+f"(c[2]), "+f"(c[3])
        : "r"(a0), "r"(a1), "r"(a2), "r"(a3), "r"(b0), "r"(b1));
}

// ---------------- preps ---------------------------------------------------------
__global__ void prep_spans(const int* __restrict__ sp) {
    int t = threadIdx.x;
    int odd = sp[2 * t + 1];
    int any_odd = __syncthreads_or(odd != 0);
    if (any_odd) { g_spans[2 * t] = sp[2 * t];     g_spans[2 * t + 1] = sp[2 * t + 1]; }
    else         { g_spans[2 * t] = sp[4 * t];     g_spans[2 * t + 1] = sp[4 * t + 2]; }
}

__global__ void prep_compact() {
    __shared__ int offs[257];
    int t = threadIdx.x;
    int s = g_spans[2 * t], e = g_spans[2 * t + 1], w = e - s + 1;
    offs[t + 1] = w;
    if (t == 0) offs[0] = 0;
    __syncthreads();
    if (t == 0) {
        for (int i = 1; i <= 256; i++) offs[i] += offs[i - 1];
        g_ntiles = (offs[256] + 127) >> 7;
    }
    __syncthreads();
    int base = offs[t];
    for (int k = 0; k < w; k++) g_pos[base + k] = (t << 16) | (s + k);
    int total = offs[256], NT = (total + 127) >> 7;
    for (int idx = total + t; idx < NT * 128; idx += 256) g_pos[idx] = (int)0x80000000;
}

// fused: pack aw1 into per-(kc,nc) pair-layout + zero g_attns + pad ab1/aw2.
// grid 1560 x 256 = 399360 threads covers all index ranges.
__global__ void prep_packB(const float* __restrict__ aw1, const float* __restrict__ ab1,
                           const float* __restrict__ aw2) {
    int idx = blockIdx.x * 256 + threadIdx.x;
    if (idx < B_ * L_) g_attns[idx] = 0.f;                 // zero attns each replay
    if (idx < HP_) {
        g_ab1p[idx] = (idx < H_) ? ab1[idx] : 0.f;
        g_aw2p[idx] = (idx < H_) ? aw2[idx] : 0.f;
    }
    if (idx >= NKC * NCP * BT_TILE) return;
    int tile = idx / BT_TILE, within = idx % BT_TILE;
    int kc = tile / NCP, nc = tile % NCP;
    int ks = within / BT_KSSTRIDE, rem = within % BT_KSSTRIDE;
    int t = rem / BT_TSTRIDE, n = rem % BT_TSTRIDE;
    float x = 0.f, y = 0.f;
    if (n < 256) {
        int col = nc * 256 + n;
        if (col < H_) {
            int kr = kc * 32 + ks * 8 + t;
            x = aw1[(size_t)kr * H_ + col];
            y = aw1[(size_t)(kr + 4) * H_ + col];
        }
    }
    float2* dst = (float2*)g_aw1pk4;
    dst[idx] = make_float2(tfv(x), tfv(y));
}

__global__ void prep_sw1p(const float* __restrict__ sw1) {
    size_t i = (size_t)blockIdx.x * 256 + threadIdx.x;
    if (i < (size_t)XPAD * 1024) {
        int r = (int)(i >> 10), c2 = (int)(i & 1023);
        g_sw1p[i] = (r < XDIM) ? sw1[(size_t)r * 1024 + c2] : 0.f;
    }
}

// ---------------- attn: compacted tiles, paired-LDS.64 tf32 mma -----------------
// A-side feeds raw fp32 bits; HMMA truncates to tf32 in HW (error ~1e-5 at output).
#define ATTN_SMEM (13440 * 8 + 128 * 4)

__global__ void __launch_bounds__(256, 1) attn_kernel(const float* __restrict__ E) {
    int unit = blockIdx.x;
    int tile = unit >> 2, ncp = unit & 3;
    if (tile >= g_ntiles) return;

    extern __shared__ float2 sm[];
    float2* As[2] = { sm, sm + 2560 };
    float2* Bs[2] = { sm + 5120, sm + 9280 };
    int* pos = (int*)(sm + 13440);

    int tid = threadIdx.x;
    if (tid < 128) pos[tid] = g_pos[tile * 128 + tid];
    __syncthreads();

    int warp = tid >> 5, lane = tid & 31, g = lane >> 2, tig = lane & 3;
    int wm = warp >> 2, wn = warp & 3;

    int arow = tid >> 1, ah = tid & 1;
    int p = pos[arow];
    int ab = (p >> 16) & 0x7FFF, al = p & 0xFFFF;
    const float* aptr = E + ((size_t)ab * L_ + al) * D_ + ah * 16;

    float c[4][8][4] = {};
    float4 va[4];

    // prolog kc=0
    {
        const float4* src = g_aw1pk4 + (size_t)(0 * NCP + ncp) * 2080;
        float4* dstb = (float4*)Bs[0];
        #pragma unroll
        for (int k = 0; k < 9; k++) { int i = tid + k * 256; if (i < 2080) cp16(dstb + i, src + i); }
        CP_COMMIT;
        const float4* s4 = (const float4*)aptr;
        va[0] = s4[0]; va[1] = s4[1]; va[2] = s4[2]; va[3] = s4[3];
        float* v = (float*)va;
        #pragma unroll
        for (int ksl = 0; ksl < 2; ksl++) {
            int ks = 2 * ah + ksl;
            float4* d = (float4*)(As[0] + arow * A_RSTRIDE + ks * 4);
            d[0] = make_float4(v[8*ksl+0], v[8*ksl+4], v[8*ksl+1], v[8*ksl+5]);
            d[1] = make_float4(v[8*ksl+2], v[8*ksl+6], v[8*ksl+3], v[8*ksl+7]);
        }
        CP_WAIT0;
        __syncthreads();
    }

    for (int kc = 0; kc < NKC; kc++) {
        int cur = kc & 1, nxt = cur ^ 1;
        if (kc < NKC - 1) {
            const float4* src = g_aw1pk4 + (size_t)((kc + 1) * NCP + ncp) * 2080;
            float4* dstb = (float4*)Bs[nxt];
            #pragma unroll
            for (int k = 0; k < 9; k++) { int i = tid + k * 256; if (i < 2080) cp16(dstb + i, src + i); }
            CP_COMMIT;
            const float4* s4 = (const float4*)(aptr + (kc + 1) * 32);
            va[0] = s4[0]; va[1] = s4[1]; va[2] = s4[2]; va[3] = s4[3];
        }
        const float2* Ac = As[cur];
        const float2* Bc = Bs[cur];
        #pragma unroll
        for (int ks = 0; ks < 4; ks++) {
            float2 afr[4][2];
            float2 bfr[8];
            #pragma unroll
            for (int i = 0; i < 4; i++) {
                int r0 = wm * 64 + i * 16 + g;
                afr[i][0] = Ac[r0 * A_RSTRIDE + ks * 4 + tig];
                afr[i][1] = Ac[(r0 + 8) * A_RSTRIDE + ks * 4 + tig];
            }
            #pragma unroll
            for (int j = 0; j < 8; j++) {
                int n = wn * 64 + j * 8 + g;
                bfr[j] = Bc[ks * BT_KSSTRIDE + tig * BT_TSTRIDE + n];
            }
            #pragma unroll
            for (int i = 0; i < 4; i++)
                #pragma unroll
                for (int j = 0; j < 8; j++)
                    mma_tf32(c[i][j],
                             __float_as_uint(afr[i][0].x), __float_as_uint(afr[i][1].x),
                             __float_as_uint(afr[i][0].y), __float_as_uint(afr[i][1].y),
                             __float_as_uint(bfr[j].x),    __float_as_uint(bfr[j].y));
        }
        if (kc < NKC - 1) {
            CP_WAIT0;
            __syncthreads();
            float* v = (float*)va;
            #pragma unroll
            for (int ksl = 0; ksl < 2; ksl++) {
                int ks = 2 * ah + ksl;
                float4* d = (float4*)(As[nxt] + arow * A_RSTRIDE + ks * 4);
                d[0] = make_float4(v[8*ksl+0], v[8*ksl+4], v[8*ksl+1], v[8*ksl+5]);
                d[1] = make_float4(v[8*ksl+2], v[8*ksl+6], v[8*ksl+3], v[8*ksl+7]);
            }
            __syncthreads();
        }
    }

    int n0 = ncp * 256;
    #pragma unroll
    for (int i = 0; i < 4; i++) {
        float ra = 0.f, rb = 0.f;
        #pragma unroll
        for (int j = 0; j < 8; j++) {
            int col0 = n0 + wn * 64 + j * 8 + tig * 2;
            float b1a = g_ab1p[col0], b1b = g_ab1p[col0 + 1];
            float w2a = g_aw2p[col0], w2b = g_aw2p[col0 + 1];
            float z;
            z = c[i][j][0] + b1a; ra += (z > 0.f ? z : 0.01f * z) * w2a;
            z = c[i][j][1] + b1b; ra += (z > 0.f ? z : 0.01f * z) * w2b;
            z = c[i][j][2] + b1a; rb += (z > 0.f ? z : 0.01f * z) * w2a;
            z = c[i][j][3] + b1b; rb += (z > 0.f ? z : 0.01f * z) * w2b;
        }
        ra += __shfl_xor_sync(0xffffffffu, ra, 1);
        ra += __shfl_xor_sync(0xffffffffu, ra, 2);
        rb += __shfl_xor_sync(0xffffffffu, rb, 1);
        rb += __shfl_xor_sync(0xffffffffu, rb, 2);
        if (tig == 0) {
            int r0 = wm * 64 + i * 16 + g;
            int p0 = pos[r0], p1 = pos[r0 + 8];
            if (p0 >= 0) atomicAdd(&g_attns[((p0 >> 16) & 0x7FFF) * L_ + (p0 & 0xFFFF)], ra);
            if (p1 >= 0) atomicAdd(&g_attns[((p1 >> 16) & 0x7FFF) * L_ + (p1 & 0xFFFF)], rb);
        }
    }
}

// ---------------- softmax over span + weighted reduce + build concat x ----------
__global__ void __launch_bounds__(256) softmax_build(const float* __restrict__ E,
                                                     const float* __restrict__ width_emb) {
    int b = blockIdx.x;
    int tid = threadIdx.x, warp = tid >> 5, lane = tid & 31;
    int s = g_spans[b * 2], e = g_spans[b * 2 + 1];
    int width = e - s + 1;

    __shared__ float ws[L_];
    __shared__ float red[256];
    __shared__ float sacc[D_];

    float lm = -1e30f;
    for (int l = s + tid; l <= e; l += 256) lm = fmaxf(lm, g_attns[b * L_ + l]);
    red[tid] = lm; __syncthreads();
    for (int st = 128; st > 0; st >>= 1) {
        if (tid < st) red[tid] = fmaxf(red[tid], red[tid + st]);
        __syncthreads();
    }
    float mx = red[0];
    __syncthreads();
    float ls = 0.f;
    for (int l = s + tid; l <= e; l += 256) {
        float ev = __expf(g_attns[b * L_ + l] - mx);
        ws[l - s] = ev;
        ls += ev;
    }
    red[tid] = ls; __syncthreads();
    for (int st = 128; st > 0; st >>= 1) {
        if (tid < st) red[tid] += red[tid + st];
        __syncthreads();
    }
    float inv = 1.f / red[0];
    for (int d = tid; d < D_; d += 256) sacc[d] = 0.f;
    __syncthreads();

    float acc[24];
    #pragma unroll
    for (int c2 = 0; c2 < 24; c2++) acc[c2] = 0.f;
    const float* Ebase = E + (size_t)b * L_ * D_;
    for (int l = s + warp; l <= e; l += 8) {
        float wv = ws[l - s];
        const float* row = Ebase + (size_t)l * D_;
        #pragma unroll
        for (int c2 = 0; c2 < 24; c2++) acc[c2] += wv * row[c2 * 32 + lane];
    }
    #pragma unroll
    for (int c2 = 0; c2 < 24; c2++) atomicAdd(&sacc[c2 * 32 + lane], acc[c2]);
    __syncthreads();

    float* xb = g_x + (size_t)b * XPAD;
    for (int d = tid; d < D_; d += 256) xb[1536 + d] = sacc[d] * inv;

    const float* rs = Ebase + (size_t)s * D_;
    const float* re = Ebase + (size_t)e * D_;
    for (int d = tid; d < D_; d += 256) { xb[d] = rs[d]; xb[D_ + d] = re[d]; }

    if (tid < 20) {
        const int bins[15] = {1,2,3,4,5,6,7,8,12,16,20,24,32,64,128};
        int idx = 0;
        #pragma unroll
        for (int j = 0; j < 15; j++) idx += (width > bins[j]) ? 1 : 0;
        xb[2304 + tid] = width_emb[idx * 20 + tid];
    }
    if (tid < XPAD - XDIM) xb[XDIM + tid] = 0.f;
}

// ---------------- 3xTF32 GEMM with K-split partials -----------------------------
__global__ void __launch_bounds__(256) gemm_3x(const float* __restrict__ A,
                                               const float* __restrict__ Bw,
                                               float* __restrict__ part,
                                               int M, int N, int K, int S) {
    __shared__ float Ah[128][20], Al[128][20];
    __shared__ float Bh[16][136], Bl[16][136];
    int tid = threadIdx.x, warp = tid >> 5, lane = tid & 31, g = lane >> 2, tig = lane & 3;
    int wm = warp >> 2, wn = warp & 3;
    int bm = blockIdx.y * 128, bn = blockIdx.x * 128;
    int nch = K >> 4;
    int z = blockIdx.z;
    int c0 = (int)((long)nch * z / S), c1 = (int)((long)nch * (z + 1) / S);

    float c[4][4][4] = {};
    for (int ch = c0; ch < c1; ch++) {
        int k0 = ch * 16;
        {
            int r = tid >> 1, h = (tid & 1) * 8;
            const float* src = A + (size_t)(bm + r) * K + k0 + h;
            float4 v0 = *(const float4*)src, v1 = *(const float4*)(src + 4);
            float vv[8] = {v0.x, v0.y, v0.z, v0.w, v1.x, v1.y, v1.z, v1.w};
            #pragma unroll
            for (int q = 0; q < 8; q++) {
                float hi = tfv(vv[q]);
                Ah[r][h + q] = hi;
                Al[r][h + q] = tfv(vv[q] - hi);
            }
        }
        {
            int r = tid >> 4, cb = (tid & 15) * 8;
            const float* src = Bw + (size_t)(k0 + r) * N + bn + cb;
            float4 v0 = *(const float4*)src, v1 = *(const float4*)(src + 4);
            float vv[8] = {v0.x, v0.y, v0.z, v0.w, v1.x, v1.y, v1.z, v1.w};
            #pragma unroll
            for (int q = 0; q < 8; q++) {
                float hi = tfv(vv[q]);
                Bh[r][cb + q] = hi;
                Bl[r][cb + q] = tfv(vv[q] - hi);
            }
        }
        __syncthreads();
        #pragma unroll
        for (int ks = 0; ks < 2; ks++) {
            int k = ks * 8;
            uint32_t ah4[4][4], al4[4][4], bh2[4][2], bl2[4][2];
            #pragma unroll
            for (int i = 0; i < 4; i++) {
                int mr = wm * 64 + i * 16;
                ah4[i][0] = __float_as_uint(Ah[mr + g    ][k + tig    ]);
                ah4[i][1] = __float_as_uint(Ah[mr + g + 8][k + tig    ]);
                ah4[i][2] = __float_as_uint(Ah[mr + g    ][k + tig + 4]);
                ah4[i][3] = __float_as_uint(Ah[mr + g + 8][k + tig + 4]);
                al4[i][0] = __float_as_uint(Al[mr + g    ][k + tig    ]);
                al4[i][1] = __float_as_uint(Al[mr + g + 8][k + tig    ]);
                al4[i][2] = __float_as_uint(Al[mr + g    ][k + tig + 4]);
                al4[i][3] = __float_as_uint(Al[mr + g + 8][k + tig + 4]);
            }
            #pragma unroll
            for (int j = 0; j < 4; j++) {
                int n = wn * 32 + j * 8 + g;
                bh2[j][0] = __float_as_uint(Bh[k + tig    ][n]);
                bh2[j][1] = __float_as_uint(Bh[k + tig + 4][n]);
                bl2[j][0] = __float_as_uint(Bl[k + tig    ][n]);
                bl2[j][1] = __float_as_uint(Bl[k + tig + 4][n]);
            }
            #pragma unroll
            for (int i = 0; i < 4; i++)
                #pragma unroll
                for (int j = 0; j < 4; j++) {
                    mma_tf32(c[i][j], al4[i][0], al4[i][1], al4[i][2], al4[i][3], bh2[j][0], bh2[j][1]);
                    mma_tf32(c[i][j], ah4[i][0], ah4[i][1], ah4[i][2], ah4[i][3], bl2[j][0], bl2[j][1]);
                    mma_tf32(c[i][j], ah4[i][0], ah4[i][1], ah4[i][2], ah4[i][3], bh2[j][0], bh2[j][1]);
                }
        }
        __syncthreads();
    }
    float* dst = part + ((size_t)z * M + bm) * N + bn;
    #pragma unroll
    for (int i = 0; i < 4; i++)
        #pragma unroll
        for (int j = 0; j < 4; j++) {
            int row = wm * 64 + i * 16 + g, col = wn * 32 + j * 8 + tig * 2;
            dst[(size_t)row * N + col]       = c[i][j][0];
            dst[(size_t)row * N + col + 1]   = c[i][j][1];
            dst[(size_t)(row+8) * N + col]   = c[i][j][2];
            dst[(size_t)(row+8) * N + col+1] = c[i][j][3];
        }
}

template<int ACT>
__global__ void combine(const float* __restrict__ part, const float* __restrict__ bias,
                        float* __restrict__ out, int MN, int N, int S) {
    int i = blockIdx.x * 256 + threadIdx.x;
    if (i >= MN) return;
    float v = 0.f;
    for (int z = 0; z < S; z++) v += part[(size_t)z * MN + i];
    v += bias[i % N];
    if (ACT) v = v > 0.f ? v : 0.01f * v;
    out[i] = v;
}

// ---------------- small fp32 GEMM for the final 256x30 layer --------------------
__global__ void __launch_bounds__(256) gemm_last(const float* __restrict__ A,
                                                 const float* __restrict__ W,
                                                 const float* __restrict__ bias,
                                                 float* __restrict__ C) {
    int m = blockIdx.x;
    int tid = threadIdx.x;
    int col = tid % 30, seg = tid / 30;
    __shared__ float red[256];
    float v = 0.f;
    if (seg < 8) {
        const float* a = A + (size_t)m * 256 + seg * 32;
        const float* w = W + col;
        #pragma unroll
        for (int k = 0; k < 32; k++) v += a[k] * w[(size_t)(seg * 32 + k) * 30];
    }
    red[tid] = v;
    __syncthreads();
    if (tid < 30) {
        float acc = 0.f;
        #pragma unroll
        for (int s2 = 0; s2 < 8; s2++) acc += red[s2 * 30 + tid];
        C[(size_t)m * 30 + tid] = acc + bias[tid];
    }
}

// ---------------- launch ---------------------------------------------------------
extern "C" void kernel_launch(void* const* d_in, const int* in_sizes, int n_in,
                              void* d_out, int out_size) {
    const float* embeds    = (const float*)d_in[0];
    const int*   spans_raw = (const int*)d_in[1];
    const float* aw1       = (const float*)d_in[2];
    const float* ab1       = (const float*)d_in[3];
    const float* aw2       = (const float*)d_in[4];
    // d_in[5] = ab2 : uniform logit offset, softmax-invariant -> unused
    const float* width_emb = (const float*)d_in[6];
    const float* sw1 = (const float*)d_in[7];
    const float* sb1 = (const float*)d_in[8];
    const float* sw2 = (const float*)d_in[9];
    const float* sb2 = (const float*)d_in[10];
    const float* sw3 = (const float*)d_in[11];
    const float* sb3 = (const float*)d_in[12];
    const float* sw4 = (const float*)d_in[13];
    const float* sb4 = (const float*)d_in[14];
    float* out = (float*)d_out;

    float *x, *h1, *h2, *h3, *part, *sw1p;
    cudaGetSymbolAddress((void**)&x,    g_x);
    cudaGetSymbolAddress((void**)&h1,   g_h1);
    cudaGetSymbolAddress((void**)&h2,   g_h2);
    cudaGetSymbolAddress((void**)&h3,   g_h3);
    cudaGetSymbolAddress((void**)&part, g_part);
    cudaGetSymbolAddress((void**)&sw1p, g_sw1p);

    cudaFuncSetAttribute(attn_kernel, cudaFuncAttributeMaxDynamicSharedMemorySize, ATTN_SMEM);

    prep_spans<<<1, 256>>>(spans_raw);                                        // 1
    prep_compact<<<1, 256>>>();                                               // 2
    prep_packB<<<1560, 256>>>(aw1, ab1, aw2);                                 // 3 (fused zero+pad)
    attn_kernel<<<4096, 256, ATTN_SMEM>>>(embeds);                            // 4 <- profiled slot
    prep_sw1p<<<(XPAD * 1024 + 255) / 256, 256>>>(sw1);                       // 5
    softmax_build<<<B_, 256>>>(embeds, width_emb);                            // 6
    gemm_3x<<<dim3(8, 2, 8), 256>>>(x,  sw1p, part, 256, 1024, XPAD, 8);
    combine<1><<<(256 * 1024) / 256, 256>>>(part, sb1, h1, 256 * 1024, 1024, 8);
    gemm_3x<<<dim3(4, 2, 4), 256>>>(h1, sw2,  part, 256, 512, 1024, 4);
    combine<1><<<(256 * 512) / 256, 256>>>(part, sb2, h2, 256 * 512, 512, 4);
    gemm_3x<<<dim3(2, 2, 2), 256>>>(h2, sw3,  part, 256, 256, 512, 2);
    combine<1><<<(256 * 256) / 256, 256>>>(part, sb3, h3, 256 * 256, 256, 2);
    gemm_last<<<256, 256>>>(h3, sw4, sb4, out);
}

// round 7
// speedup vs baseline: 1.8653x; 1.0405x over previous
#include <cuda_runtime.h>
#include <cstdint>
#include <cstddef>

// Problem constants
#define B_ 256
#define L_ 512
#define D_ 768
#define H_ 1000
#define HP_ 1024
#define XDIM 2324
#define XPAD 2336

// attn tiling: block 128(M) x 128(N), K-chunks of 32, 8 ncp passes over 1024 hidden
#define NKC 24             // 768/32
#define NCPN 8             // 1024 / 128

// packed B tile geometry (float2 units), N=128 per tile
#define BT_TSTRIDE 132              // per tig-row stride (1056B == 32 mod 128 -> conflict-free)
#define BT_KSSTRIDE (4*BT_TSTRIDE)  // 528
#define BT_TILE (4*BT_KSSTRIDE)     // 2112 float2 per (kc,ncp) tile
#define A_RSTRIDE 20                // float2 per A row (160B == 32 mod 128)

// ---------------- scratch -------------------------------------------------------
__device__ int    g_spans[B_ * 2];
__device__ int    g_ntiles;
__device__ int    g_pos[B_ * L_];
__device__ float  g_attns[B_ * L_];
__device__ float  g_ab1p[HP_];
__device__ float  g_aw2p[HP_];
__device__ float2 g_aw1pk2[NKC * NCPN * BT_TILE];   // packed pair-layout aw1 tiles (tf32)
__device__ float  g_x [B_ * XPAD];
__device__ float  g_sw1p[XPAD * 1024];
__device__ float  g_part[8 * 256 * 1024];
__device__ float  g_h1[B_ * 1024];
__device__ float  g_h2[B_ * 512];
__device__ float  g_h3[B_ * 256];

__device__ __forceinline__ uint32_t f2tf(float x) {
    uint32_t r;
    asm("cvt.rna.tf32.f32 %0, %1;" : "=r"(r) : "f"(x));
    return r;
}
__device__ __forceinline__ float tfv(float x) { return __uint_as_float(f2tf(x)); }

__device__ __forceinline__ void cp16(void* smem_dst, const void* gsrc) {
    uint32_t s = (uint32_t)__cvta_generic_to_shared(smem_dst);
    asm volatile("cp.async.cg.shared.global [%0], [%1], 16;\n" :: "r"(s), "l"(gsrc));
}
#define CP_COMMIT asm volatile("cp.async.commit_group;\n" ::: "memory")
#define CP_WAIT0  asm volatile("cp.async.wait_group 0;\n" ::: "memory")

__device__ __forceinline__ void mma_tf32(float* c, uint32_t a0, uint32_t a1,
                                         uint32_t a2, uint32_t a3,
                                         uint32_t b0, uint32_t b1) {
    asm volatile(
        "mma.sync.aligned.m16n8k8.row.col.f32.tf32.tf32.f32 "
        "{%0,%1,%2,%3}, {%4,%5,%6,%7}, {%8,%9}, {%0,%1,%2,%3};\n"
        : "+f"(c[0]), "+f"(c[1]), "+f"(c[2]), "+f"(c[3])
        : "r"(a0), "r"(a1), "r"(a2), "r"(a3), "r"(b0), "r"(b1));
}

// ---------------- preps ---------------------------------------------------------
__global__ void prep_spans(const int* __restrict__ sp) {
    int t = threadIdx.x;
    int odd = sp[2 * t + 1];
    int any_odd = __syncthreads_or(odd != 0);
    if (any_odd) { g_spans[2 * t] = sp[2 * t];     g_spans[2 * t + 1] = sp[2 * t + 1]; }
    else         { g_spans[2 * t] = sp[4 * t];     g_spans[2 * t + 1] = sp[4 * t + 2]; }
}

__global__ void prep_compact() {
    __shared__ int offs[257];
    int t = threadIdx.x;
    int s = g_spans[2 * t], e = g_spans[2 * t + 1], w = e - s + 1;
    offs[t + 1] = w;
    if (t == 0) offs[0] = 0;
    __syncthreads();
    if (t == 0) {
        for (int i = 1; i <= 256; i++) offs[i] += offs[i - 1];
        g_ntiles = (offs[256] + 127) >> 7;
    }
    __syncthreads();
    int base = offs[t];
    for (int k = 0; k < w; k++) g_pos[base + k] = (t << 16) | (s + k);
    int total = offs[256], NT = (total + 127) >> 7;
    for (int idx = total + t; idx < NT * 128; idx += 256) g_pos[idx] = (int)0x80000000;
}

// fused: pack aw1 -> per-(kc,ncp) pair-layout tiles (N=128) + zero attns + pad ab1/aw2
// total pack elems: 24*8*2112 = 405504 -> grid 1584 x 256
__global__ void prep_packB(const float* __restrict__ aw1, const float* __restrict__ ab1,
                           const float* __restrict__ aw2) {
    int idx = blockIdx.x * 256 + threadIdx.x;
    if (idx < B_ * L_) g_attns[idx] = 0.f;
    if (idx < HP_) {
        g_ab1p[idx] = (idx < H_) ? ab1[idx] : 0.f;
        g_aw2p[idx] = (idx < H_) ? aw2[idx] : 0.f;
    }
    if (idx >= NKC * NCPN * BT_TILE) return;
    int tile = idx / BT_TILE, within = idx % BT_TILE;
    int kc = tile >> 3, ncp = tile & 7;
    int ks = within / BT_KSSTRIDE, rem = within % BT_KSSTRIDE;
    int t = rem / BT_TSTRIDE, n = rem % BT_TSTRIDE;
    float x = 0.f, y = 0.f;
    if (n < 128) {
        int col = ncp * 128 + n;
        if (col < H_) {
            int kr = kc * 32 + ks * 8 + t;
            x = aw1[(size_t)kr * H_ + col];
            y = aw1[(size_t)(kr + 4) * H_ + col];
        }
    }
    g_aw1pk2[idx] = make_float2(tfv(x), tfv(y));
}

__global__ void prep_sw1p(const float* __restrict__ sw1) {
    size_t i = (size_t)blockIdx.x * 256 + threadIdx.x;
    if (i < (size_t)XPAD * 1024) {
        int r = (int)(i >> 10), c2 = (int)(i & 1023);
        g_sw1p[i] = (r < XDIM) ? sw1[(size_t)r * 1024 + c2] : 0.f;
    }
}

// ---------------- attn: compacted tiles, paired-LDS.64 tf32 mma, 2 CTAs/SM ------
// grid 8192 = 1024 max tiles x 8 ncp; 256 threads (8 warps = 2m x 4n, warp 64x32)
// smem f2 layout: As0[0,2560) As1[2560,5120) Bs0[5120,7232) Bs1[7232,9344) pos
#define ATTN_SMEM (9344 * 8 + 128 * 4)

__global__ void __launch_bounds__(256, 2) attn_kernel(const float* __restrict__ E) {
    int unit = blockIdx.x;
    int tile = unit >> 3, ncp = unit & 7;
    if (tile >= g_ntiles) return;

    extern __shared__ float2 sm[];
    float2* As[2] = { sm, sm + 2560 };
    float2* Bs[2] = { sm + 5120, sm + 7232 };
    int* pos = (int*)(sm + 9344);

    int tid = threadIdx.x;
    if (tid < 128) pos[tid] = g_pos[tile * 128 + tid];
    __syncthreads();

    int warp = tid >> 5, lane = tid & 31, g = lane >> 2, tig = lane & 3;
    int wm = warp >> 2, wn = warp & 3;

    int arow = tid >> 1, ah = tid & 1;
    int p = pos[arow];
    int ab = (p >> 16) & 0x7FFF, al = p & 0xFFFF;
    const float* aptr = E + ((size_t)ab * L_ + al) * D_ + ah * 16;

    float c[4][4][4] = {};
    float4 va[4];

    // prolog kc=0
    {
        const float4* src = (const float4*)(g_aw1pk2 + (size_t)(0 * NCPN + ncp) * BT_TILE);
        float4* dstb = (float4*)Bs[0];
        #pragma unroll
        for (int k = 0; k < 5; k++) { int i = tid + k * 256; if (i < 1056) cp16(dstb + i, src + i); }
        CP_COMMIT;
        const float4* s4 = (const float4*)aptr;
        va[0] = s4[0]; va[1] = s4[1]; va[2] = s4[2]; va[3] = s4[3];
        float* v = (float*)va;
        #pragma unroll
        for (int ksl = 0; ksl < 2; ksl++) {
            int ks = 2 * ah + ksl;
            float4* d = (float4*)(As[0] + arow * A_RSTRIDE + ks * 4);
            d[0] = make_float4(v[8*ksl+0], v[8*ksl+4], v[8*ksl+1], v[8*ksl+5]);
            d[1] = make_float4(v[8*ksl+2], v[8*ksl+6], v[8*ksl+3], v[8*ksl+7]);
        }
        CP_WAIT0;
        __syncthreads();
    }

    for (int kc = 0; kc < NKC; kc++) {
        int cur = kc & 1, nxt = cur ^ 1;
        if (kc < NKC - 1) {
            const float4* src = (const float4*)(g_aw1pk2 + (size_t)((kc + 1) * NCPN + ncp) * BT_TILE);
            float4* dstb = (float4*)Bs[nxt];
            #pragma unroll
            for (int k = 0; k < 5; k++) { int i = tid + k * 256; if (i < 1056) cp16(dstb + i, src + i); }
            CP_COMMIT;
            const float4* s4 = (const float4*)(aptr + (kc + 1) * 32);
            va[0] = s4[0]; va[1] = s4[1]; va[2] = s4[2]; va[3] = s4[3];
        }
        const float2* Ac = As[cur];
        const float2* Bc = Bs[cur];
        #pragma unroll
        for (int ks = 0; ks < 4; ks++) {
            float2 afr[4][2];
            float2 bfr[4];
            #pragma unroll
            for (int i = 0; i < 4; i++) {
                int r0 = wm * 64 + i * 16 + g;
                afr[i][0] = Ac[r0 * A_RSTRIDE + ks * 4 + tig];
                afr[i][1] = Ac[(r0 + 8) * A_RSTRIDE + ks * 4 + tig];
            }
            #pragma unroll
            for (int j = 0; j < 4; j++) {
                int n = wn * 32 + j * 8 + g;
                bfr[j] = Bc[ks * BT_KSSTRIDE + tig * BT_TSTRIDE + n];
            }
            #pragma unroll
            for (int i = 0; i < 4; i++)
                #pragma unroll
                for (int j = 0; j < 4; j++)
                    mma_tf32(c[i][j],
                             __float_as_uint(afr[i][0].x), __float_as_uint(afr[i][1].x),
                             __float_as_uint(afr[i][0].y), __float_as_uint(afr[i][1].y),
                             __float_as_uint(bfr[j].x),    __float_as_uint(bfr[j].y));
        }
        if (kc < NKC - 1) {
            CP_WAIT0;
            __syncthreads();
            float* v = (float*)va;
            #pragma unroll
            for (int ksl = 0; ksl < 2; ksl++) {
                int ks = 2 * ah + ksl;
                float4* d = (float4*)(As[nxt] + arow * A_RSTRIDE + ks * 4);
                d[0] = make_float4(v[8*ksl+0], v[8*ksl+4], v[8*ksl+1], v[8*ksl+5]);
                d[1] = make_float4(v[8*ksl+2], v[8*ksl+6], v[8*ksl+3], v[8*ksl+7]);
            }
            __syncthreads();
        }
    }

    // epilogue: lrelu(c + b1) * aw2, reduce over this pass's 128 hidden cols
    int n0 = ncp * 128;
    #pragma unroll
    for (int i = 0; i < 4; i++) {
        float ra = 0.f, rb = 0.f;
        #pragma unroll
        for (int j = 0; j < 4; j++) {
            int col0 = n0 + wn * 32 + j * 8 + tig * 2;
            float b1a = g_ab1p[col0], b1b = g_ab1p[col0 + 1];
            float w2a = g_aw2p[col0], w2b = g_aw2p[col0 + 1];
            float z;
            z = c[i][j][0] + b1a; ra += (z > 0.f ? z : 0.01f * z) * w2a;
            z = c[i][j][1] + b1b; ra += (z > 0.f ? z : 0.01f * z) * w2b;
            z = c[i][j][2] + b1a; rb += (z > 0.f ? z : 0.01f * z) * w2a;
            z = c[i][j][3] + b1b; rb += (z > 0.f ? z : 0.01f * z) * w2b;
        }
        ra += __shfl_xor_sync(0xffffffffu, ra, 1);
        ra += __shfl_xor_sync(0xffffffffu, ra, 2);
        rb += __shfl_xor_sync(0xffffffffu, rb, 1);
        rb += __shfl_xor_sync(0xffffffffu, rb, 2);
        if (tig == 0) {
            int r0 = wm * 64 + i * 16 + g;
            int p0 = pos[r0], p1 = pos[r0 + 8];
            if (p0 >= 0) atomicAdd(&g_attns[((p0 >> 16) & 0x7FFF) * L_ + (p0 & 0xFFFF)], ra);
            if (p1 >= 0) atomicAdd(&g_attns[((p1 >> 16) & 0x7FFF) * L_ + (p1 & 0xFFFF)], rb);
        }
    }
}

// ---------------- softmax over span + weighted reduce + build concat x ----------
__global__ void __launch_bounds__(256) softmax_build(const float* __restrict__ E,
                                                     const float* __restrict__ width_emb) {
    int b = blockIdx.x;
    int tid = threadIdx.x, warp = tid >> 5, lane = tid & 31;
    int s = g_spans[b * 2], e = g_spans[b * 2 + 1];
    int width = e - s + 1;

    __shared__ float ws[L_];
    __shared__ float red[256];
    __shared__ float sacc[D_];

    float lm = -1e30f;
    for (int l = s + tid; l <= e; l += 256) lm = fmaxf(lm, g_attns[b * L_ + l]);
    red[tid] = lm; __syncthreads();
    for (int st = 128; st > 0; st >>= 1) {
        if (tid < st) red[tid] = fmaxf(red[tid], red[tid + st]);
        __syncthreads();
    }
    float mx = red[0];
    __syncthreads();
    float ls = 0.f;
    for (int l = s + tid; l <= e; l += 256) {
        float ev = __expf(g_attns[b * L_ + l] - mx);
        ws[l - s] = ev;
        ls += ev;
    }
    red[tid] = ls; __syncthreads();
    for (int st = 128; st > 0; st >>= 1) {
        if (tid < st) red[tid] += red[tid + st];
        __syncthreads();
    }
    float inv = 1.f / red[0];
    for (int d = tid; d < D_; d += 256) sacc[d] = 0.f;
    __syncthreads();

    float acc[24];
    #pragma unroll
    for (int c2 = 0; c2 < 24; c2++) acc[c2] = 0.f;
    const float* Ebase = E + (size_t)b * L_ * D_;
    for (int l = s + warp; l <= e; l += 8) {
        float wv = ws[l - s];
        const float* row = Ebase + (size_t)l * D_;
        #pragma unroll
        for (int c2 = 0; c2 < 24; c2++) acc[c2] += wv * row[c2 * 32 + lane];
    }
    #pragma unroll
    for (int c2 = 0; c2 < 24; c2++) atomicAdd(&sacc[c2 * 32 + lane], acc[c2]);
    __syncthreads();

    float* xb = g_x + (size_t)b * XPAD;
    for (int d = tid; d < D_; d += 256) xb[1536 + d] = sacc[d] * inv;

    const float* rs = Ebase + (size_t)s * D_;
    const float* re = Ebase + (size_t)e * D_;
    for (int d = tid; d < D_; d += 256) { xb[d] = rs[d]; xb[D_ + d] = re[d]; }

    if (tid < 20) {
        const int bins[15] = {1,2,3,4,5,6,7,8,12,16,20,24,32,64,128};
        int idx = 0;
        #pragma unroll
        for (int j = 0; j < 15; j++) idx += (width > bins[j]) ? 1 : 0;
        xb[2304 + tid] = width_emb[idx * 20 + tid];
    }
    if (tid < XPAD - XDIM) xb[XDIM + tid] = 0.f;
}

// ---------------- 3xTF32 GEMM with K-split partials -----------------------------
__global__ void __launch_bounds__(256) gemm_3x(const float* __restrict__ A,
                                               const float* __restrict__ Bw,
                                               float* __restrict__ part,
                                               int M, int N, int K, int S) {
    __shared__ float Ah[128][20], Al[128][20];
    __shared__ float Bh[16][136], Bl[16][136];
    int tid = threadIdx.x, warp = tid >> 5, lane = tid & 31, g = lane >> 2, tig = lane & 3;
    int wm = warp >> 2, wn = warp & 3;
    int bm = blockIdx.y * 128, bn = blockIdx.x * 128;
    int nch = K >> 4;
    int z = blockIdx.z;
    int c0 = (int)((long)nch * z / S), c1 = (int)((long)nch * (z + 1) / S);

    float c[4][4][4] = {};
    for (int ch = c0; ch < c1; ch++) {
        int k0 = ch * 16;
        {
            int r = tid >> 1, h = (tid & 1) * 8;
            const float* src = A + (size_t)(bm + r) * K + k0 + h;
            float4 v0 = *(const float4*)src, v1 = *(const float4*)(src + 4);
            float vv[8] = {v0.x, v0.y, v0.z, v0.w, v1.x, v1.y, v1.z, v1.w};
            #pragma unroll
            for (int q = 0; q < 8; q++) {
                float hi = tfv(vv[q]);
                Ah[r][h + q] = hi;
                Al[r][h + q] = tfv(vv[q] - hi);
            }
        }
        {
            int r = tid >> 4, cb = (tid & 15) * 8;
            const float* src = Bw + (size_t)(k0 + r) * N + bn + cb;
            float4 v0 = *(const float4*)src, v1 = *(const float4*)(src + 4);
            float vv[8] = {v0.x, v0.y, v0.z, v0.w, v1.x, v1.y, v1.z, v1.w};
            #pragma unroll
            for (int q = 0; q < 8; q++) {
                float hi = tfv(vv[q]);
                Bh[r][cb + q] = hi;
                Bl[r][cb + q] = tfv(vv[q] - hi);
            }
        }
        __syncthreads();
        #pragma unroll
        for (int ks = 0; ks < 2; ks++) {
            int k = ks * 8;
            uint32_t ah4[4][4], al4[4][4], bh2[4][2], bl2[4][2];
            #pragma unroll
            for (int i = 0; i < 4; i++) {
                int mr = wm * 64 + i * 16;
                ah4[i][0] = __float_as_uint(Ah[mr + g    ][k + tig    ]);
                ah4[i][1] = __float_as_uint(Ah[mr + g + 8][k + tig    ]);
                ah4[i][2] = __float_as_uint(Ah[mr + g    ][k + tig + 4]);
                ah4[i][3] = __float_as_uint(Ah[mr + g + 8][k + tig + 4]);
                al4[i][0] = __float_as_uint(Al[mr + g    ][k + tig    ]);
                al4[i][1] = __float_as_uint(Al[mr + g + 8][k + tig    ]);
                al4[i][2] = __float_as_uint(Al[mr + g    ][k + tig + 4]);
                al4[i][3] = __float_as_uint(Al[mr + g + 8][k + tig + 4]);
            }
            #pragma unroll
            for (int j = 0; j < 4; j++) {
                int n = wn * 32 + j * 8 + g;
                bh2[j][0] = __float_as_uint(Bh[k + tig    ][n]);
                bh2[j][1] = __float_as_uint(Bh[k + tig + 4][n]);
                bl2[j][0] = __float_as_uint(Bl[k + tig    ][n]);
                bl2[j][1] = __float_as_uint(Bl[k + tig + 4][n]);
            }
            #pragma unroll
            for (int i = 0; i < 4; i++)
                #pragma unroll
                for (int j = 0; j < 4; j++) {
                    mma_tf32(c[i][j], al4[i][0], al4[i][1], al4[i][2], al4[i][3], bh2[j][0], bh2[j][1]);
                    mma_tf32(c[i][j], ah4[i][0], ah4[i][1], ah4[i][2], ah4[i][3], bl2[j][0], bl2[j][1]);
                    mma_tf32(c[i][j], ah4[i][0], ah4[i][1], ah4[i][2], ah4[i][3], bh2[j][0], bh2[j][1]);
                }
        }
        __syncthreads();
    }
    float* dst = part + ((size_t)z * M + bm) * N + bn;
    #pragma unroll
    for (int i = 0; i < 4; i++)
        #pragma unroll
        for (int j = 0; j < 4; j++) {
            int row = wm * 64 + i * 16 + g, col = wn * 32 + j * 8 + tig * 2;
            dst[(size_t)row * N + col]       = c[i][j][0];
            dst[(size_t)row * N + col + 1]   = c[i][j][1];
            dst[(size_t)(row+8) * N + col]   = c[i][j][2];
            dst[(size_t)(row+8) * N + col+1] = c[i][j][3];
        }
}

template<int ACT>
__global__ void combine(const float* __restrict__ part, const float* __restrict__ bias,
                        float* __restrict__ out, int MN, int N, int S) {
    int i = blockIdx.x * 256 + threadIdx.x;
    if (i >= MN) return;
    float v = 0.f;
    for (int z = 0; z < S; z++) v += part[(size_t)z * MN + i];
    v += bias[i % N];
    if (ACT) v = v > 0.f ? v : 0.01f * v;
    out[i] = v;
}

// ---------------- small fp32 GEMM for the final 256x30 layer --------------------
__global__ void __launch_bounds__(256) gemm_last(const float* __restrict__ A,
                                                 const float* __restrict__ W,
                                                 const float* __restrict__ bias,
                                                 float* __restrict__ C) {
    int m = blockIdx.x;
    int tid = threadIdx.x;
    int col = tid % 30, seg = tid / 30;
    __shared__ float red[256];
    float v = 0.f;
    if (seg < 8) {
        const float* a = A + (size_t)m * 256 + seg * 32;
        const float* w = W + col;
        #pragma unroll
        for (int k = 0; k < 32; k++) v += a[k] * w[(size_t)(seg * 32 + k) * 30];
    }
    red[tid] = v;
    __syncthreads();
    if (tid < 30) {
        float acc = 0.f;
        #pragma unroll
        for (int s2 = 0; s2 < 8; s2++) acc += red[s2 * 30 + tid];
        C[(size_t)m * 30 + tid] = acc + bias[tid];
    }
}

// ---------------- launch ---------------------------------------------------------
extern "C" void kernel_launch(void* const* d_in, const int* in_sizes, int n_in,
                              void* d_out, int out_size) {
    const float* embeds    = (const float*)d_in[0];
    const int*   spans_raw = (const int*)d_in[1];
    const float* aw1       = (const float*)d_in[2];
    const float* ab1       = (const float*)d_in[3];
    const float* aw2       = (const float*)d_in[4];
    // d_in[5] = ab2 : uniform logit offset, softmax-invariant -> unused
    const float* width_emb = (const float*)d_in[6];
    const float* sw1 = (const float*)d_in[7];
    const float* sb1 = (const float*)d_in[8];
    const float* sw2 = (const float*)d_in[9];
    const float* sb2 = (const float*)d_in[10];
    const float* sw3 = (const float*)d_in[11];
    const float* sb3 = (const float*)d_in[12];
    const float* sw4 = (const float*)d_in[13];
    const float* sb4 = (const float*)d_in[14];
    float* out = (float*)d_out;

    float *x, *h1, *h2, *h3, *part, *sw1p;
    cudaGetSymbolAddress((void**)&x,    g_x);
    cudaGetSymbolAddress((void**)&h1,   g_h1);
    cudaGetSymbolAddress((void**)&h2,   g_h2);
    cudaGetSymbolAddress((void**)&h3,   g_h3);
    cudaGetSymbolAddress((void**)&part, g_part);
    cudaGetSymbolAddress((void**)&sw1p, g_sw1p);

    cudaFuncSetAttribute(attn_kernel, cudaFuncAttributeMaxDynamicSharedMemorySize, ATTN_SMEM);

    prep_spans<<<1, 256>>>(spans_raw);                                        // 1
    prep_compact<<<1, 256>>>();                                               // 2
    prep_packB<<<1584, 256>>>(aw1, ab1, aw2);                                 // 3
    attn_kernel<<<8192, 256, ATTN_SMEM>>>(embeds);                            // 4 <- profiled
    prep_sw1p<<<(XPAD * 1024 + 255) / 256, 256>>>(sw1);                       // 5
    softmax_build<<<B_, 256>>>(embeds, width_emb);                            // 6
    gemm_3x<<<dim3(8, 2, 8), 256>>>(x,  sw1p, part, 256, 1024, XPAD, 8);
    combine<1><<<(256 * 1024) / 256, 256>>>(part, sb1, h1, 256 * 1024, 1024, 8);
    gemm_3x<<<dim3(4, 2, 4), 256>>>(h1, sw2,  part, 256, 512, 1024, 4);
    combine<1><<<(256 * 512) / 256, 256>>>(part, sb2, h2, 256 * 512, 512, 4);
    gemm_3x<<<dim3(2, 2, 2), 256>>>(h2, sw3,  part, 256, 256, 512, 2);
    combine<1><<<(256 * 256) / 256, 256>>>(part, sb3, h3, 256 * 256, 256, 2);
    gemm_last<<<256, 256>>>(h3, sw4, sb4, out);
}

// round 8
// speedup vs baseline: 2.0254x; 1.0858x over previous
#include <cuda_runtime.h>
#include <cstdint>
#include <cstddef>

// Problem constants
#define B_ 256
#define L_ 512
#define D_ 768
#define H_ 1000
#define HP_ 1024
#define XDIM 2324
#define XPAD 2336

// attn tiling: block 128(M) x 128(N), K-chunks of 32, 8 ncp passes over 1024 hidden
#define NKC 24             // 768/32
#define NCPN 8             // 1024 / 128

// packed B tile geometry (float2 units), N=128 per tile
#define BT_TSTRIDE 132              // per tig-row stride (1056B == 32 mod 128 -> conflict-free)
#define BT_KSSTRIDE (4*BT_TSTRIDE)  // 528
#define BT_TILE (4*BT_KSSTRIDE)     // 2112 float2 per (kc,ncp) tile
#define A_FS 36                     // floats per A smem row (144B == 16 mod 128 -> LDS.32 1-phase)

// ---------------- scratch -------------------------------------------------------
__device__ int    g_spans[B_ * 2];
__device__ int    g_ntiles;
__device__ int    g_pos[B_ * L_];
__device__ float  g_attns[B_ * L_];
__device__ float  g_ab1p[HP_];
__device__ float  g_aw2p[HP_];
__device__ float2 g_aw1pk2[NKC * NCPN * BT_TILE];   // packed pair-layout aw1 tiles (tf32)
__device__ float  g_x [B_ * XPAD];
__device__ float  g_sw1p[XPAD * 1024];
__device__ float  g_part[8 * 256 * 1024];
__device__ float  g_h1[B_ * 1024];
__device__ float  g_h2[B_ * 512];
__device__ float  g_h3[B_ * 256];

__device__ __forceinline__ uint32_t f2tf(float x) {
    uint32_t r;
    asm("cvt.rna.tf32.f32 %0, %1;" : "=r"(r) : "f"(x));
    return r;
}
__device__ __forceinline__ float tfv(float x) { return __uint_as_float(f2tf(x)); }

__device__ __forceinline__ void cp16(void* smem_dst, const void* gsrc) {
    uint32_t s = (uint32_t)__cvta_generic_to_shared(smem_dst);
    asm volatile("cp.async.cg.shared.global [%0], [%1], 16;\n" :: "r"(s), "l"(gsrc));
}
#define CP_COMMIT asm volatile("cp.async.commit_group;\n" ::: "memory")
#define CP_WAIT0  asm volatile("cp.async.wait_group 0;\n" ::: "memory")

__device__ __forceinline__ void mma_tf32(float* c, uint32_t a0, uint32_t a1,
                                         uint32_t a2, uint32_t a3,
                                         uint32_t b0, uint32_t b1) {
    asm volatile(
        "mma.sync.aligned.m16n8k8.row.col.f32.tf32.tf32.f32 "
        "{%0,%1,%2,%3}, {%4,%5,%6,%7}, {%8,%9}, {%0,%1,%2,%3};\n"
        : "+f"(c[0]), "+f"(c[1]), "+f"(c[2]), "+f"(c[3])
        : "r"(a0), "r"(a1), "r"(a2), "r"(a3), "r"(b0), "r"(b1));
}

// ---------------- preps ---------------------------------------------------------
__global__ void prep_spans(const int* __restrict__ sp) {
    int t = threadIdx.x;
    int odd = sp[2 * t + 1];
    int any_odd = __syncthreads_or(odd != 0);
    if (any_odd) { g_spans[2 * t] = sp[2 * t];     g_spans[2 * t + 1] = sp[2 * t + 1]; }
    else         { g_spans[2 * t] = sp[4 * t];     g_spans[2 * t + 1] = sp[4 * t + 2]; }
}

__global__ void prep_compact() {
    __shared__ int offs[257];
    int t = threadIdx.x;
    int s = g_spans[2 * t], e = g_spans[2 * t + 1], w = e - s + 1;
    offs[t + 1] = w;
    if (t == 0) offs[0] = 0;
    __syncthreads();
    if (t == 0) {
        for (int i = 1; i <= 256; i++) offs[i] += offs[i - 1];
        g_ntiles = (offs[256] + 127) >> 7;
    }
    __syncthreads();
    int base = offs[t];
    for (int k = 0; k < w; k++) g_pos[base + k] = (t << 16) | (s + k);
    int total = offs[256], NT = (total + 127) >> 7;
    for (int idx = total + t; idx < NT * 128; idx += 256) g_pos[idx] = (int)0x80000000;
}

// fused: pack aw1 -> per-(kc,ncp) pair-layout tiles (N=128) + zero attns + pad ab1/aw2
__global__ void prep_packB(const float* __restrict__ aw1, const float* __restrict__ ab1,
                           const float* __restrict__ aw2) {
    int idx = blockIdx.x * 256 + threadIdx.x;
    if (idx < B_ * L_) g_attns[idx] = 0.f;
    if (idx < HP_) {
        g_ab1p[idx] = (idx < H_) ? ab1[idx] : 0.f;
        g_aw2p[idx] = (idx < H_) ? aw2[idx] : 0.f;
    }
    if (idx >= NKC * NCPN * BT_TILE) return;
    int tile = idx / BT_TILE, within = idx % BT_TILE;
    int kc = tile >> 3, ncp = tile & 7;
    int ks = within / BT_KSSTRIDE, rem = within % BT_KSSTRIDE;
    int t = rem / BT_TSTRIDE, n = rem % BT_TSTRIDE;
    float x = 0.f, y = 0.f;
    if (n < 128) {
        int col = ncp * 128 + n;
        if (col < H_) {
            int kr = kc * 32 + ks * 8 + t;
            x = aw1[(size_t)kr * H_ + col];
            y = aw1[(size_t)(kr + 4) * H_ + col];
        }
    }
    g_aw1pk2[idx] = make_float2(tfv(x), tfv(y));
}

__global__ void prep_sw1p(const float* __restrict__ sw1) {
    size_t i = (size_t)blockIdx.x * 256 + threadIdx.x;
    if (i < (size_t)XPAD * 1024) {
        int r = (int)(i >> 10), c2 = (int)(i & 1023);
        g_sw1p[i] = (r < XDIM) ? sw1[(size_t)r * 1024 + c2] : 0.f;
    }
}

// ---------------- attn: 4 warps 64x64, pure cp.async A+B, 2 CTAs/SM -------------
// grid 8192 = 1024 max tiles x 8 ncp; 128 threads (4 warps = 2m x 2n, warp 64x64)
// smem floats: A0[0,4608) A1[4608,9216) | B f2: B0[0,2112) B1[2112,4224) | pos
#define ATTN_SMEM ((9216 + 8448 + 128) * 4)

__global__ void __launch_bounds__(128, 2) attn_kernel(const float* __restrict__ E) {
    int unit = blockIdx.x;
    int tile = unit >> 3, ncp = unit & 7;
    if (tile >= g_ntiles) return;

    extern __shared__ float smf[];
    float*  Aa[2] = { smf, smf + 4608 };
    float2* Bb[2] = { (float2*)(smf + 9216), (float2*)(smf + 9216) + 2112 };
    int* pos = (int*)(smf + 9216 + 8448);

    int tid = threadIdx.x;
    int warp = tid >> 5, lane = tid & 31, g = lane >> 2, tig = lane & 3;
    int wm = warp >> 1, wn = warp & 1;

    int p = g_pos[tile * 128 + tid];
    pos[tid] = p;
    int ab = (p >> 16) & 0x7FFF, al = p & 0xFFFF;
    const float* arow = E + ((size_t)ab * L_ + al) * D_;
    __syncthreads();

    float c[4][8][4] = {};

    // prolog: fill buffers 0
    {
        const float4* srcB = (const float4*)(g_aw1pk2 + (size_t)(0 * NCPN + ncp) * BT_TILE);
        float4* dB = (float4*)Bb[0];
        #pragma unroll
        for (int k2 = 0; k2 < 9; k2++) { int i = tid + k2 * 128; if (i < 1056) cp16(dB + i, srcB + i); }
        float* dA = Aa[0] + tid * A_FS;
        #pragma unroll
        for (int q = 0; q < 8; q++) cp16(dA + q * 4, arow + q * 4);
        CP_COMMIT;
        CP_WAIT0;
        __syncthreads();
    }

    for (int kc = 0; kc < NKC; kc++) {
        int cur = kc & 1, nxt = cur ^ 1;
        if (kc < NKC - 1) {
            const float4* srcB = (const float4*)(g_aw1pk2 + (size_t)((kc + 1) * NCPN + ncp) * BT_TILE);
            float4* dB = (float4*)Bb[nxt];
            #pragma unroll
            for (int k2 = 0; k2 < 9; k2++) { int i = tid + k2 * 128; if (i < 1056) cp16(dB + i, srcB + i); }
            float* dA = Aa[nxt] + tid * A_FS;
            const float* sA = arow + (kc + 1) * 32;
            #pragma unroll
            for (int q = 0; q < 8; q++) cp16(dA + q * 4, sA + q * 4);
            CP_COMMIT;
        }
        const float*  Ac = Aa[cur];
        const float2* Bc = Bb[cur];
        #pragma unroll
        for (int ks = 0; ks < 4; ks++) {
            int k = ks * 8;
            float a0[4], a1[4], a2[4], a3[4];
            float2 bfr[8];
            #pragma unroll
            for (int i = 0; i < 4; i++) {
                int r0 = wm * 64 + i * 16 + g;
                a0[i] = Ac[r0 * A_FS + k + tig];
                a1[i] = Ac[(r0 + 8) * A_FS + k + tig];
                a2[i] = Ac[r0 * A_FS + k + tig + 4];
                a3[i] = Ac[(r0 + 8) * A_FS + k + tig + 4];
            }
            #pragma unroll
            for (int j = 0; j < 8; j++) {
                int n = wn * 64 + j * 8 + g;
                bfr[j] = Bc[ks * BT_KSSTRIDE + tig * BT_TSTRIDE + n];
            }
            #pragma unroll
            for (int i = 0; i < 4; i++)
                #pragma unroll
                for (int j = 0; j < 8; j++)
                    mma_tf32(c[i][j],
                             __float_as_uint(a0[i]), __float_as_uint(a1[i]),
                             __float_as_uint(a2[i]), __float_as_uint(a3[i]),
                             __float_as_uint(bfr[j].x), __float_as_uint(bfr[j].y));
        }
        if (kc < NKC - 1) CP_WAIT0;
        __syncthreads();
    }

    // epilogue: lrelu(c + b1) * aw2, reduce over this pass's 128 hidden cols
    int n0 = ncp * 128;
    #pragma unroll
    for (int i = 0; i < 4; i++) {
        float ra = 0.f, rb = 0.f;
        #pragma unroll
        for (int j = 0; j < 8; j++) {
            int col0 = n0 + wn * 64 + j * 8 + tig * 2;
            float b1a = g_ab1p[col0], b1b = g_ab1p[col0 + 1];
            float w2a = g_aw2p[col0], w2b = g_aw2p[col0 + 1];
            float z;
            z = c[i][j][0] + b1a; ra += (z > 0.f ? z : 0.01f * z) * w2a;
            z = c[i][j][1] + b1b; ra += (z > 0.f ? z : 0.01f * z) * w2b;
            z = c[i][j][2] + b1a; rb += (z > 0.f ? z : 0.01f * z) * w2a;
            z = c[i][j][3] + b1b; rb += (z > 0.f ? z : 0.01f * z) * w2b;
        }
        ra += __shfl_xor_sync(0xffffffffu, ra, 1);
        ra += __shfl_xor_sync(0xffffffffu, ra, 2);
        rb += __shfl_xor_sync(0xffffffffu, rb, 1);
        rb += __shfl_xor_sync(0xffffffffu, rb, 2);
        if (tig == 0) {
            int r0 = wm * 64 + i * 16 + g;
            int p0 = pos[r0], p1 = pos[r0 + 8];
            if (p0 >= 0) atomicAdd(&g_attns[((p0 >> 16) & 0x7FFF) * L_ + (p0 & 0xFFFF)], ra);
            if (p1 >= 0) atomicAdd(&g_attns[((p1 >> 16) & 0x7FFF) * L_ + (p1 & 0xFFFF)], rb);
        }
    }
}

// ---------------- softmax over span + weighted reduce + build concat x ----------
__global__ void __launch_bounds__(256) softmax_build(const float* __restrict__ E,
                                                     const float* __restrict__ width_emb) {
    int b = blockIdx.x;
    int tid = threadIdx.x, warp = tid >> 5, lane = tid & 31;
    int s = g_spans[b * 2], e = g_spans[b * 2 + 1];
    int width = e - s + 1;

    __shared__ float ws[L_];
    __shared__ float red[256];
    __shared__ float sacc[D_];

    float lm = -1e30f;
    for (int l = s + tid; l <= e; l += 256) lm = fmaxf(lm, g_attns[b * L_ + l]);
    red[tid] = lm; __syncthreads();
    for (int st = 128; st > 0; st >>= 1) {
        if (tid < st) red[tid] = fmaxf(red[tid], red[tid + st]);
        __syncthreads();
    }
    float mx = red[0];
    __syncthreads();
    float ls = 0.f;
    for (int l = s + tid; l <= e; l += 256) {
        float ev = __expf(g_attns[b * L_ + l] - mx);
        ws[l - s] = ev;
        ls += ev;
    }
    red[tid] = ls; __syncthreads();
    for (int st = 128; st > 0; st >>= 1) {
        if (tid < st) red[tid] += red[tid + st];
        __syncthreads();
    }
    float inv = 1.f / red[0];
    for (int d = tid; d < D_; d += 256) sacc[d] = 0.f;
    __syncthreads();

    float acc[24];
    #pragma unroll
    for (int c2 = 0; c2 < 24; c2++) acc[c2] = 0.f;
    const float* Ebase = E + (size_t)b * L_ * D_;
    for (int l = s + warp; l <= e; l += 8) {
        float wv = ws[l - s];
        const float* row = Ebase + (size_t)l * D_;
        #pragma unroll
        for (int c2 = 0; c2 < 24; c2++) acc[c2] += wv * row[c2 * 32 + lane];
    }
    #pragma unroll
    for (int c2 = 0; c2 < 24; c2++) atomicAdd(&sacc[c2 * 32 + lane], acc[c2]);
    __syncthreads();

    float* xb = g_x + (size_t)b * XPAD;
    for (int d = tid; d < D_; d += 256) xb[1536 + d] = sacc[d] * inv;

    const float* rs = Ebase + (size_t)s * D_;
    const float* re = Ebase + (size_t)e * D_;
    for (int d = tid; d < D_; d += 256) { xb[d] = rs[d]; xb[D_ + d] = re[d]; }

    if (tid < 20) {
        const int bins[15] = {1,2,3,4,5,6,7,8,12,16,20,24,32,64,128};
        int idx = 0;
        #pragma unroll
        for (int j = 0; j < 15; j++) idx += (width > bins[j]) ? 1 : 0;
        xb[2304 + tid] = width_emb[idx * 20 + tid];
    }
    if (tid < XPAD - XDIM) xb[XDIM + tid] = 0.f;
}

// ---------------- 3xTF32 GEMM with K-split partials -----------------------------
__global__ void __launch_bounds__(256) gemm_3x(const float* __restrict__ A,
                                               const float* __restrict__ Bw,
                                               float* __restrict__ part,
                                               int M, int N, int K, int S) {
    __shared__ float Ah[128][20], Al[128][20];
    __shared__ float Bh[16][136], Bl[16][136];
    int tid = threadIdx.x, warp = tid >> 5, lane = tid & 31, g = lane >> 2, tig = lane & 3;
    int wm = warp >> 2, wn = warp & 3;
    int bm = blockIdx.y * 128, bn = blockIdx.x * 128;
    int nch = K >> 4;
    int z = blockIdx.z;
    int c0 = (int)((long)nch * z / S), c1 = (int)((long)nch * (z + 1) / S);

    float c[4][4][4] = {};
    for (int ch = c0; ch < c1; ch++) {
        int k0 = ch * 16;
        {
            int r = tid >> 1, h = (tid & 1) * 8;
            const float* src = A + (size_t)(bm + r) * K + k0 + h;
            float4 v0 = *(const float4*)src, v1 = *(const float4*)(src + 4);
            float vv[8] = {v0.x, v0.y, v0.z, v0.w, v1.x, v1.y, v1.z, v1.w};
            #pragma unroll
            for (int q = 0; q < 8; q++) {
                float hi = tfv(vv[q]);
                Ah[r][h + q] = hi;
                Al[r][h + q] = tfv(vv[q] - hi);
            }
        }
        {
            int r = tid >> 4, cb = (tid & 15) * 8;
            const float* src = Bw + (size_t)(k0 + r) * N + bn + cb;
            float4 v0 = *(const float4*)src, v1 = *(const float4*)(src + 4);
            float vv[8] = {v0.x, v0.y, v0.z, v0.w, v1.x, v1.y, v1.z, v1.w};
            #pragma unroll
            for (int q = 0; q < 8; q++) {
                float hi = tfv(vv[q]);
                Bh[r][cb + q] = hi;
                Bl[r][cb + q] = tfv(vv[q] - hi);
            }
        }
        __syncthreads();
        #pragma unroll
        for (int ks = 0; ks < 2; ks++) {
            int k = ks * 8;
            uint32_t ah4[4][4], al4[4][4], bh2[4][2], bl2[4][2];
            #pragma unroll
            for (int i = 0; i < 4; i++) {
                int mr = wm * 64 + i * 16;
                ah4[i][0] = __float_as_uint(Ah[mr + g    ][k + tig    ]);
                ah4[i][1] = __float_as_uint(Ah[mr + g + 8][k + tig    ]);
                ah4[i][2] = __float_as_uint(Ah[mr + g    ][k + tig + 4]);
                ah4[i][3] = __float_as_uint(Ah[mr + g + 8][k + tig + 4]);
                al4[i][0] = __float_as_uint(Al[mr + g    ][k + tig    ]);
                al4[i][1] = __float_as_uint(Al[mr + g + 8][k + tig    ]);
                al4[i][2] = __float_as_uint(Al[mr + g    ][k + tig + 4]);
                al4[i][3] = __float_as_uint(Al[mr + g + 8][k + tig + 4]);
            }
            #pragma unroll
            for (int j = 0; j < 4; j++) {
                int n = wn * 32 + j * 8 + g;
                bh2[j][0] = __float_as_uint(Bh[k + tig    ][n]);
                bh2[j][1] = __float_as_uint(Bh[k + tig + 4][n]);
                bl2[j][0] = __float_as_uint(Bl[k + tig    ][n]);
                bl2[j][1] = __float_as_uint(Bl[k + tig + 4][n]);
            }
            #pragma unroll
            for (int i = 0; i < 4; i++)
                #pragma unroll
                for (int j = 0; j < 4; j++) {
                    mma_tf32(c[i][j], al4[i][0], al4[i][1], al4[i][2], al4[i][3], bh2[j][0], bh2[j][1]);
                    mma_tf32(c[i][j], ah4[i][0], ah4[i][1], ah4[i][2], ah4[i][3], bl2[j][0], bl2[j][1]);
                    mma_tf32(c[i][j], ah4[i][0], ah4[i][1], ah4[i][2], ah4[i][3], bh2[j][0], bh2[j][1]);
                }
        }
        __syncthreads();
    }
    float* dst = part + ((size_t)z * M + bm) * N + bn;
    #pragma unroll
    for (int i = 0; i < 4; i++)
        #pragma unroll
        for (int j = 0; j < 4; j++) {
            int row = wm * 64 + i * 16 + g, col = wn * 32 + j * 8 + tig * 2;
            dst[(size_t)row * N + col]       = c[i][j][0];
            dst[(size_t)row * N + col + 1]   = c[i][j][1];
            dst[(size_t)(row+8) * N + col]   = c[i][j][2];
            dst[(size_t)(row+8) * N + col+1] = c[i][j][3];
        }
}

template<int ACT>
__global__ void combine(const float* __restrict__ part, const float* __restrict__ bias,
                        float* __restrict__ out, int MN, int N, int S) {
    int i = blockIdx.x * 256 + threadIdx.x;
    if (i >= MN) return;
    float v = 0.f;
    for (int z = 0; z < S; z++) v += part[(size_t)z * MN + i];
    v += bias[i % N];
    if (ACT) v = v > 0.f ? v : 0.01f * v;
    out[i] = v;
}

// ---------------- small fp32 GEMM for the final 256x30 layer --------------------
__global__ void __launch_bounds__(256) gemm_last(const float* __restrict__ A,
                                                 const float* __restrict__ W,
                                                 const float* __restrict__ bias,
                                                 float* __restrict__ C) {
    int m = blockIdx.x;
    int tid = threadIdx.x;
    int col = tid % 30, seg = tid / 30;
    __shared__ float red[256];
    float v = 0.f;
    if (seg < 8) {
        const float* a = A + (size_t)m * 256 + seg * 32;
        const float* w = W + col;
        #pragma unroll
        for (int k = 0; k < 32; k++) v += a[k] * w[(size_t)(seg * 32 + k) * 30];
    }
    red[tid] = v;
    __syncthreads();
    if (tid < 30) {
        float acc = 0.f;
        #pragma unroll
        for (int s2 = 0; s2 < 8; s2++) acc += red[s2 * 30 + tid];
        C[(size_t)m * 30 + tid] = acc + bias[tid];
    }
}

// ---------------- launch ---------------------------------------------------------
extern "C" void kernel_launch(void* const* d_in, const int* in_sizes, int n_in,
                              void* d_out, int out_size) {
    const float* embeds    = (const float*)d_in[0];
    const int*   spans_raw = (const int*)d_in[1];
    const float* aw1       = (const float*)d_in[2];
    const float* ab1       = (const float*)d_in[3];
    const float* aw2       = (const float*)d_in[4];
    // d_in[5] = ab2 : uniform logit offset, softmax-invariant -> unused
    const float* width_emb = (const float*)d_in[6];
    const float* sw1 = (const float*)d_in[7];
    const float* sb1 = (const float*)d_in[8];
    const float* sw2 = (const float*)d_in[9];
    const float* sb2 = (const float*)d_in[10];
    const float* sw3 = (const float*)d_in[11];
    const float* sb3 = (const float*)d_in[12];
    const float* sw4 = (const float*)d_in[13];
    const float* sb4 = (const float*)d_in[14];
    float* out = (float*)d_out;

    float *x, *h1, *h2, *h3, *part, *sw1p;
    cudaGetSymbolAddress((void**)&x,    g_x);
    cudaGetSymbolAddress((void**)&h1,   g_h1);
    cudaGetSymbolAddress((void**)&h2,   g_h2);
    cudaGetSymbolAddress((void**)&h3,   g_h3);
    cudaGetSymbolAddress((void**)&part, g_part);
    cudaGetSymbolAddress((void**)&sw1p, g_sw1p);

    cudaFuncSetAttribute(attn_kernel, cudaFuncAttributeMaxDynamicSharedMemorySize, ATTN_SMEM);

    prep_spans<<<1, 256>>>(spans_raw);                                        // 1
    prep_compact<<<1, 256>>>();                                               // 2
    prep_packB<<<1584, 256>>>(aw1, ab1, aw2);                                 // 3
    attn_kernel<<<8192, 128, ATTN_SMEM>>>(embeds);                            // 4 <- profiled
    prep_sw1p<<<(XPAD * 1024 + 255) / 256, 256>>>(sw1);                       // 5
    softmax_build<<<B_, 256>>>(embeds, width_emb);                            // 6
    gemm_3x<<<dim3(8, 2, 8), 256>>>(x,  sw1p, part, 256, 1024, XPAD, 8);
    combine<1><<<(256 * 1024) / 256, 256>>>(part, sb1, h1, 256 * 1024, 1024, 8);
    gemm_3x<<<dim3(4, 2, 4), 256>>>(h1, sw2,  part, 256, 512, 1024, 4);
    combine<1><<<(256 * 512) / 256, 256>>>(part, sb2, h2, 256 * 512, 512, 4);
    gemm_3x<<<dim3(2, 2, 2), 256>>>(h2, sw3,  part, 256, 256, 512, 2);
    combine<1><<<(256 * 256) / 256, 256>>>(part, sb3, h3, 256 * 256, 256, 2);
    gemm_last<<<256, 256>>>(h3, sw4, sb4, out);
}

// round 9
// speedup vs baseline: 2.5555x; 1.2617x over previous
#include <cuda_runtime.h>
#include <cuda_fp16.h>
#include <cstdint>
#include <cstddef>

// Problem constants
#define B_ 256
#define L_ 512
#define D_ 768
#define H_ 1000
#define HP_ 1024
#define XDIM 2324
#define XPAD 2336

// attn tiling: block 128(M) x 128(N), K-chunks of 32 (2 x k16 MMA steps), 8 ncp passes
#define NKC 24             // 768/32
#define NCPN 8             // 1024 / 128
#define MAXT 1024          // max compacted tiles

// fp16 B tile image: per (kc,ncp): [ks(2)][tig(4)][n(132)][quad(4 halfs)] = 8448 B
#define BT_BYTES 8448
// fp16 A smem row: 32 halfs data + pad -> 80 B (banks 20g+tig -> conflict-free)
#define A_RSB 80

// ---------------- scratch -------------------------------------------------------
__device__ int    g_spans[B_ * 2];
__device__ int    g_ntiles;
__device__ int    g_pos[B_ * L_];
__device__ float  g_attns[B_ * L_];
__device__ float  g_ab1p[HP_];
__device__ float  g_aw2p[HP_];
__device__ unsigned char g_Bpk[NKC * NCPN * BT_BYTES];   // packed fp16 aw1 smem image
__device__ __half g_Ef16[MAXT * 128 * D_];               // compacted span rows, fp16
__device__ float  g_x [B_ * XPAD];
__device__ float  g_sw1p[XPAD * 1024];
__device__ float  g_part[8 * 256 * 1024];
__device__ float  g_h1[B_ * 1024];
__device__ float  g_h2[B_ * 512];
__device__ float  g_h3[B_ * 256];

__device__ __forceinline__ uint32_t f2tf(float x) {
    uint32_t r;
    asm("cvt.rna.tf32.f32 %0, %1;" : "=r"(r) : "f"(x));
    return r;
}
__device__ __forceinline__ float tfv(float x) { return __uint_as_float(f2tf(x)); }

__device__ __forceinline__ void cp16(void* smem_dst, const void* gsrc) {
    uint32_t s = (uint32_t)__cvta_generic_to_shared(smem_dst);
    asm volatile("cp.async.cg.shared.global [%0], [%1], 16;\n" :: "r"(s), "l"(gsrc));
}
#define CP_COMMIT asm volatile("cp.async.commit_group;\n" ::: "memory")
#define CP_WAIT0  asm volatile("cp.async.wait_group 0;\n" ::: "memory")

__device__ __forceinline__ void mma_tf32(float* c, uint32_t a0, uint32_t a1,
                                         uint32_t a2, uint32_t a3,
                                         uint32_t b0, uint32_t b1) {
    asm volatile(
        "mma.sync.aligned.m16n8k8.row.col.f32.tf32.tf32.f32 "
        "{%0,%1,%2,%3}, {%4,%5,%6,%7}, {%8,%9}, {%0,%1,%2,%3};\n"
        : "+f"(c[0]), "+f"(c[1]), "+f"(c[2]), "+f"(c[3])
        : "r"(a0), "r"(a1), "r"(a2), "r"(a3), "r"(b0), "r"(b1));
}

__device__ __forceinline__ void mma_f16(float* c, uint32_t a0, uint32_t a1,
                                        uint32_t a2, uint32_t a3,
                                        uint32_t b0, uint32_t b1) {
    asm volatile(
        "mma.sync.aligned.m16n8k16.row.col.f32.f16.f16.f32 "
        "{%0,%1,%2,%3}, {%4,%5,%6,%7}, {%8,%9}, {%0,%1,%2,%3};\n"
        : "+f"(c[0]), "+f"(c[1]), "+f"(c[2]), "+f"(c[3])
        : "r"(a0), "r"(a1), "r"(a2), "r"(a3), "r"(b0), "r"(b1));
}

// ---------------- preps ---------------------------------------------------------
__global__ void prep_spans(const int* __restrict__ sp) {
    int t = threadIdx.x;
    int odd = sp[2 * t + 1];
    int any_odd = __syncthreads_or(odd != 0);
    if (any_odd) { g_spans[2 * t] = sp[2 * t];     g_spans[2 * t + 1] = sp[2 * t + 1]; }
    else         { g_spans[2 * t] = sp[4 * t];     g_spans[2 * t + 1] = sp[4 * t + 2]; }
}

__global__ void prep_compact() {
    __shared__ int offs[257];
    int t = threadIdx.x;
    int s = g_spans[2 * t], e = g_spans[2 * t + 1], w = e - s + 1;
    offs[t + 1] = w;
    if (t == 0) offs[0] = 0;
    __syncthreads();
    if (t == 0) {
        for (int i = 1; i <= 256; i++) offs[i] += offs[i - 1];
        g_ntiles = (offs[256] + 127) >> 7;
    }
    __syncthreads();
    int base = offs[t];
    for (int k = 0; k < w; k++) g_pos[base + k] = (t << 16) | (s + k);
    int total = offs[256], NT = (total + 127) >> 7;
    for (int idx = total + t; idx < NT * 128; idx += 256) g_pos[idx] = (int)0x80000000;
}

// fused prep: y<8 -> convert active compacted rows to fp16; y>=8 -> pack aw1 fp16
// image + zero attns + pad ab1/aw2.  grid (1024, 12) x 256
__global__ void prep_all(const float* __restrict__ E, const float* __restrict__ aw1,
                         const float* __restrict__ ab1, const float* __restrict__ aw2) {
    int tid = threadIdx.x;
    if (blockIdx.y < 8) {
        int tile = blockIdx.x;
        if (tile >= g_ntiles) return;
        int row = blockIdx.y * 16 + (tid >> 4);
        int l16 = tid & 15;
        int p = g_pos[tile * 128 + row];
        uint2* dst = (uint2*)(g_Ef16 + ((size_t)(tile * 128 + row)) * D_ + l16 * 48);
        if (p < 0) {
            uint2 z = make_uint2(0u, 0u);
            #pragma unroll
            for (int q = 0; q < 12; q++) dst[q] = z;
        } else {
            const float* src = E + ((size_t)((p >> 16) & 0x7FFF) * L_ + (p & 0xFFFF)) * D_ + l16 * 48;
            #pragma unroll
            for (int q = 0; q < 12; q++) {
                float4 v = ((const float4*)src)[q];
                __half2 h0 = __floats2half2_rn(v.x, v.y);
                __half2 h1 = __floats2half2_rn(v.z, v.w);
                dst[q] = make_uint2(*(uint32_t*)&h0, *(uint32_t*)&h1);
            }
        }
        return;
    }
    int lin = ((blockIdx.y - 8) * 1024 + blockIdx.x) * 256 + tid;
    if (lin < B_ * L_) g_attns[lin] = 0.f;
    if (lin < HP_) {
        g_ab1p[lin] = (lin < H_) ? ab1[lin] : 0.f;
        g_aw2p[lin] = (lin < H_) ? aw2[lin] : 0.f;
    }
    if (lin >= NKC * NCPN * (BT_BYTES / 2)) return;
    int tile = lin / (BT_BYTES / 2), within = lin % (BT_BYTES / 2);
    int kc = tile >> 3, ncp = tile & 7;
    int ks = within / 2112, r2 = within % 2112;
    int tg = r2 / 528,  r3 = r2 % 528;
    int n = r3 >> 2, c = r3 & 3;
    float v = 0.f;
    if (n < 128) {
        int col = ncp * 128 + n;
        if (col < H_) {
            int k = kc * 32 + ks * 16 + 2 * tg + (c & 1) + ((c >> 1) << 3);
            v = aw1[(size_t)k * H_ + col];
        }
    }
    __half h = __float2half_rn(v);
    *(unsigned short*)(g_Bpk + (size_t)tile * BT_BYTES + ks * 4224 + tg * 1056 + n * 8 + c * 2)
        = *(unsigned short*)&h;
}

__global__ void prep_sw1p(const float* __restrict__ sw1) {
    size_t i = (size_t)blockIdx.x * 256 + threadIdx.x;
    if (i < (size_t)XPAD * 1024) {
        int r = (int)(i >> 10), c2 = (int)(i & 1023);
        g_sw1p[i] = (r < XDIM) ? sw1[(size_t)r * 1024 + c2] : 0.f;
    }
}

// ---------------- attn: 4 warps 64x64, fp16 m16n8k16, 2 CTAs/SM -----------------
// grid 8192 = 1024 tiles x 8 ncp; 128 threads (4 warps = 2m x 2n, warp 64x64)
// smem bytes: A0[0,10240) A1[10240,20480) B0[20480,28928) B1[28928,37376) pos[512]
#define ATTN_SMEM (37376 + 512)

__global__ void __launch_bounds__(128, 2) attn_kernel() {
    int unit = blockIdx.x;
    int tile = unit >> 3, ncp = unit & 7;
    if (tile >= g_ntiles) return;

    extern __shared__ char smc[];
    char* Abuf[2] = { smc, smc + 10240 };
    char* Bbuf[2] = { smc + 20480, smc + 28928 };
    int* pos = (int*)(smc + 37376);

    int tid = threadIdx.x;
    int warp = tid >> 5, lane = tid & 31, g = lane >> 2, tig = lane & 3;
    int wm = warp >> 1, wn = warp & 1;

    pos[tid] = g_pos[tile * 128 + tid];
    const __half* asrc = g_Ef16 + (size_t)tile * 128 * D_ + (size_t)tid * D_;
    const unsigned char* bbase = g_Bpk + (size_t)ncp * BT_BYTES;

    float c[4][8][4] = {};

    // prolog: fill buffers 0 (kc = 0)
    {
        const unsigned char* sB = bbase;   // kc=0 -> tile index ncp
        #pragma unroll
        for (int k2 = 0; k2 < 5; k2++) {
            int i = tid + k2 * 128;
            if (i < 528) cp16(Bbuf[0] + i * 16, sB + i * 16);
        }
        #pragma unroll
        for (int q = 0; q < 4; q++) cp16(Abuf[0] + tid * A_RSB + q * 16, asrc + q * 8);
        CP_COMMIT;
        CP_WAIT0;
        __syncthreads();
    }

    for (int kc = 0; kc < NKC; kc++) {
        int cur = kc & 1, nxt = cur ^ 1;
        if (kc < NKC - 1) {
            const unsigned char* sB = bbase + (size_t)(kc + 1) * NCPN * BT_BYTES;
            #pragma unroll
            for (int k2 = 0; k2 < 5; k2++) {
                int i = tid + k2 * 128;
                if (i < 528) cp16(Bbuf[nxt] + i * 16, sB + i * 16);
            }
            const __half* sA = asrc + (kc + 1) * 32;
            #pragma unroll
            for (int q = 0; q < 4; q++) cp16(Abuf[nxt] + tid * A_RSB + q * 16, sA + q * 8);
            CP_COMMIT;
        }
        const char* Ac = Abuf[cur];
        const char* Bc = Bbuf[cur];
        #pragma unroll
        for (int ks = 0; ks < 2; ks++) {
            uint32_t a[4][4];
            uint2 b[8];
            #pragma unroll
            for (int i = 0; i < 4; i++) {
                const char* pa = Ac + (wm * 64 + i * 16 + g) * A_RSB + ks * 32 + tig * 4;
                a[i][0] = *(const uint32_t*)pa;
                a[i][2] = *(const uint32_t*)(pa + 16);
                a[i][1] = *(const uint32_t*)(pa + 8 * A_RSB);
                a[i][3] = *(const uint32_t*)(pa + 8 * A_RSB + 16);
            }
            #pragma unroll
            for (int j = 0; j < 8; j++) {
                int n = wn * 64 + j * 8 + g;
                b[j] = *(const uint2*)(Bc + ks * 4224 + tig * 1056 + n * 8);
            }
            #pragma unroll
            for (int i = 0; i < 4; i++)
                #pragma unroll
                for (int j = 0; j < 8; j++)
                    mma_f16(c[i][j], a[i][0], a[i][1], a[i][2], a[i][3], b[j].x, b[j].y);
        }
        if (kc < NKC - 1) CP_WAIT0;
        __syncthreads();
    }

    // epilogue: lrelu(c + b1) * aw2, reduce over this pass's 128 hidden cols
    int n0 = ncp * 128;
    #pragma unroll
    for (int i = 0; i < 4; i++) {
        float ra = 0.f, rb = 0.f;
        #pragma unroll
        for (int j = 0; j < 8; j++) {
            int col0 = n0 + wn * 64 + j * 8 + tig * 2;
            float b1a = g_ab1p[col0], b1b = g_ab1p[col0 + 1];
            float w2a = g_aw2p[col0], w2b = g_aw2p[col0 + 1];
            float z;
            z = c[i][j][0] + b1a; ra += (z > 0.f ? z : 0.01f * z) * w2a;
            z = c[i][j][1] + b1b; ra += (z > 0.f ? z : 0.01f * z) * w2b;
            z = c[i][j][2] + b1a; rb += (z > 0.f ? z : 0.01f * z) * w2a;
            z = c[i][j][3] + b1b; rb += (z > 0.f ? z : 0.01f * z) * w2b;
        }
        ra += __shfl_xor_sync(0xffffffffu, ra, 1);
        ra += __shfl_xor_sync(0xffffffffu, ra, 2);
        rb += __shfl_xor_sync(0xffffffffu, rb, 1);
        rb += __shfl_xor_sync(0xffffffffu, rb, 2);
        if (tig == 0) {
            int r0 = wm * 64 + i * 16 + g;
            int p0 = pos[r0], p1 = pos[r0 + 8];
            if (p0 >= 0) atomicAdd(&g_attns[((p0 >> 16) & 0x7FFF) * L_ + (p0 & 0xFFFF)], ra);
            if (p1 >= 0) atomicAdd(&g_attns[((p1 >> 16) & 0x7FFF) * L_ + (p1 & 0xFFFF)], rb);
        }
    }
}

// ---------------- softmax over span + weighted reduce + build concat x ----------
__global__ void __launch_bounds__(256) softmax_build(const float* __restrict__ E,
                                                     const float* __restrict__ width_emb) {
    int b = blockIdx.x;
    int tid = threadIdx.x, warp = tid >> 5, lane = tid & 31;
    int s = g_spans[b * 2], e = g_spans[b * 2 + 1];
    int width = e - s + 1;

    __shared__ float ws[L_];
    __shared__ float red[256];
    __shared__ float sacc[D_];

    float lm = -1e30f;
    for (int l = s + tid; l <= e; l += 256) lm = fmaxf(lm, g_attns[b * L_ + l]);
    red[tid] = lm; __syncthreads();
    for (int st = 128; st > 0; st >>= 1) {
        if (tid < st) red[tid] = fmaxf(red[tid], red[tid + st]);
        __syncthreads();
    }
    float mx = red[0];
    __syncthreads();
    float ls = 0.f;
    for (int l = s + tid; l <= e; l += 256) {
        float ev = __expf(g_attns[b * L_ + l] - mx);
        ws[l - s] = ev;
        ls += ev;
    }
    red[tid] = ls; __syncthreads();
    for (int st = 128; st > 0; st >>= 1) {
        if (tid < st) red[tid] += red[tid + st];
        __syncthreads();
    }
    float inv = 1.f / red[0];
    for (int d = tid; d < D_; d += 256) sacc[d] = 0.f;
    __syncthreads();

    float acc[24];
    #pragma unroll
    for (int c2 = 0; c2 < 24; c2++) acc[c2] = 0.f;
    const float* Ebase = E + (size_t)b * L_ * D_;
    for (int l = s + warp; l <= e; l += 8) {
        float wv = ws[l - s];
        const float* row = Ebase + (size_t)l * D_;
        #pragma unroll
        for (int c2 = 0; c2 < 24; c2++) acc[c2] += wv * row[c2 * 32 + lane];
    }
    #pragma unroll
    for (int c2 = 0; c2 < 24; c2++) atomicAdd(&sacc[c2 * 32 + lane], acc[c2]);
    __syncthreads();

    float* xb = g_x + (size_t)b * XPAD;
    for (int d = tid; d < D_; d += 256) xb[1536 + d] = sacc[d] * inv;

    const float* rs = Ebase + (size_t)s * D_;
    const float* re = Ebase + (size_t)e * D_;
    for (int d = tid; d < D_; d += 256) { xb[d] = rs[d]; xb[D_ + d] = re[d]; }

    if (tid < 20) {
        const int bins[15] = {1,2,3,4,5,6,7,8,12,16,20,24,32,64,128};
        int idx = 0;
        #pragma unroll
        for (int j = 0; j < 15; j++) idx += (width > bins[j]) ? 1 : 0;
        xb[2304 + tid] = width_emb[idx * 20 + tid];
    }
    if (tid < XPAD - XDIM) xb[XDIM + tid] = 0.f;
}

// ---------------- 3xTF32 GEMM with K-split partials -----------------------------
__global__ void __launch_bounds__(256) gemm_3x(const float* __restrict__ A,
                                               const float* __restrict__ Bw,
                                               float* __restrict__ part,
                                               int M, int N, int K, int S) {
    __shared__ float Ah[128][20], Al[128][20];
    __shared__ float Bh[16][136], Bl[16][136];
    int tid = threadIdx.x, warp = tid >> 5, lane = tid & 31, g = lane >> 2, tig = lane & 3;
    int wm = warp >> 2, wn = warp & 3;
    int bm = blockIdx.y * 128, bn = blockIdx.x * 128;
    int nch = K >> 4;
    int z = blockIdx.z;
    int c0 = (int)((long)nch * z / S), c1 = (int)((long)nch * (z + 1) / S);

    float c[4][4][4] = {};
    for (int ch = c0; ch < c1; ch++) {
        int k0 = ch * 16;
        {
            int r = tid >> 1, h = (tid & 1) * 8;
            const float* src = A + (size_t)(bm + r) * K + k0 + h;
            float4 v0 = *(const float4*)src, v1 = *(const float4*)(src + 4);
            float vv[8] = {v0.x, v0.y, v0.z, v0.w, v1.x, v1.y, v1.z, v1.w};
            #pragma unroll
            for (int q = 0; q < 8; q++) {
                float hi = tfv(vv[q]);
                Ah[r][h + q] = hi;
                Al[r][h + q] = tfv(vv[q] - hi);
            }
        }
        {
            int r = tid >> 4, cb = (tid & 15) * 8;
            const float* src = Bw + (size_t)(k0 + r) * N + bn + cb;
            float4 v0 = *(const float4*)src, v1 = *(const float4*)(src + 4);
            float vv[8] = {v0.x, v0.y, v0.z, v0.w, v1.x, v1.y, v1.z, v1.w};
            #pragma unroll
            for (int q = 0; q < 8; q++) {
                float hi = tfv(vv[q]);
                Bh[r][cb + q] = hi;
                Bl[r][cb + q] = tfv(vv[q] - hi);
            }
        }
        __syncthreads();
        #pragma unroll
        for (int ks = 0; ks < 2; ks++) {
            int k = ks * 8;
            uint32_t ah4[4][4], al4[4][4], bh2[4][2], bl2[4][2];
            #pragma unroll
            for (int i = 0; i < 4; i++) {
                int mr = wm * 64 + i * 16;
                ah4[i][0] = __float_as_uint(Ah[mr + g    ][k + tig    ]);
                ah4[i][1] = __float_as_uint(Ah[mr + g + 8][k + tig    ]);
                ah4[i][2] = __float_as_uint(Ah[mr + g    ][k + tig + 4]);
                ah4[i][3] = __float_as_uint(Ah[mr + g + 8][k + tig + 4]);
                al4[i][0] = __float_as_uint(Al[mr + g    ][k + tig    ]);
                al4[i][1] = __float_as_uint(Al[mr + g + 8][k + tig    ]);
                al4[i][2] = __float_as_uint(Al[mr + g    ][k + tig + 4]);
                al4[i][3] = __float_as_uint(Al[mr + g + 8][k + tig + 4]);
            }
            #pragma unroll
            for (int j = 0; j < 4; j++) {
                int n = wn * 32 + j * 8 + g;
                bh2[j][0] = __float_as_uint(Bh[k + tig    ][n]);
                bh2[j][1] = __float_as_uint(Bh[k + tig + 4][n]);
                bl2[j][0] = __float_as_uint(Bl[k + tig    ][n]);
                bl2[j][1] = __float_as_uint(Bl[k + tig + 4][n]);
            }
            #pragma unroll
            for (int i = 0; i < 4; i++)
                #pragma unroll
                for (int j = 0; j < 4; j++) {
                    mma_tf32(c[i][j], al4[i][0], al4[i][1], al4[i][2], al4[i][3], bh2[j][0], bh2[j][1]);
                    mma_tf32(c[i][j], ah4[i][0], ah4[i][1], ah4[i][2], ah4[i][3], bl2[j][0], bl2[j][1]);
                    mma_tf32(c[i][j], ah4[i][0], ah4[i][1], ah4[i][2], ah4[i][3], bh2[j][0], bh2[j][1]);
                }
        }
        __syncthreads();
    }
    float* dst = part + ((size_t)z * M + bm) * N + bn;
    #pragma unroll
    for (int i = 0; i < 4; i++)
        #pragma unroll
        for (int j = 0; j < 4; j++) {
            int row = wm * 64 + i * 16 + g, col = wn * 32 + j * 8 + tig * 2;
            dst[(size_t)row * N + col]       = c[i][j][0];
            dst[(size_t)row * N + col + 1]   = c[i][j][1];
            dst[(size_t)(row+8) * N + col]   = c[i][j][2];
            dst[(size_t)(row+8) * N + col+1] = c[i][j][3];
        }
}

template<int ACT>
__global__ void combine(const float* __restrict__ part, const float* __restrict__ bias,
                        float* __restrict__ out, int MN, int N, int S) {
    int i = blockIdx.x * 256 + threadIdx.x;
    if (i >= MN) return;
    float v = 0.f;
    for (int z = 0; z < S; z++) v += part[(size_t)z * MN + i];
    v += bias[i % N];
    if (ACT) v = v > 0.f ? v : 0.01f * v;
    out[i] = v;
}

// ---------------- small fp32 GEMM for the final 256x30 layer --------------------
__global__ void __launch_bounds__(256) gemm_last(const float* __restrict__ A,
                                                 const float* __restrict__ W,
                                                 const float* __restrict__ bias,
                                                 float* __restrict__ C) {
    int m = blockIdx.x;
    int tid = threadIdx.x;
    int col = tid % 30, seg = tid / 30;
    __shared__ float red[256];
    float v = 0.f;
    if (seg < 8) {
        const float* a = A + (size_t)m * 256 + seg * 32;
        const float* w = W + col;
        #pragma unroll
        for (int k = 0; k < 32; k++) v += a[k] * w[(size_t)(seg * 32 + k) * 30];
    }
    red[tid] = v;
    __syncthreads();
    if (tid < 30) {
        float acc = 0.f;
        #pragma unroll
        for (int s2 = 0; s2 < 8; s2++) acc += red[s2 * 30 + tid];
        C[(size_t)m * 30 + tid] = acc + bias[tid];
    }
}

// ---------------- launch ---------------------------------------------------------
extern "C" void kernel_launch(void* const* d_in, const int* in_sizes, int n_in,
                              void* d_out, int out_size) {
    const float* embeds    = (const float*)d_in[0];
    const int*   spans_raw = (const int*)d_in[1];
    const float* aw1       = (const float*)d_in[2];
    const float* ab1       = (const float*)d_in[3];
    const float* aw2       = (const float*)d_in[4];
    // d_in[5] = ab2 : uniform logit offset, softmax-invariant -> unused
    const float* width_emb = (const float*)d_in[6];
    const float* sw1 = (const float*)d_in[7];
    const float* sb1 = (const float*)d_in[8];
    const float* sw2 = (const float*)d_in[9];
    const float* sb2 = (const float*)d_in[10];
    const float* sw3 = (const float*)d_in[11];
    const float* sb3 = (const float*)d_in[12];
    const float* sw4 = (const float*)d_in[13];
    const float* sb4 = (const float*)d_in[14];
    float* out = (float*)d_out;

    float *x, *h1, *h2, *h3, *part, *sw1p;
    cudaGetSymbolAddress((void**)&x,    g_x);
    cudaGetSymbolAddress((void**)&h1,   g_h1);
    cudaGetSymbolAddress((void**)&h2,   g_h2);
    cudaGetSymbolAddress((void**)&h3,   g_h3);
    cudaGetSymbolAddress((void**)&part, g_part);
    cudaGetSymbolAddress((void**)&sw1p, g_sw1p);

    prep_spans<<<1, 256>>>(spans_raw);                                        // 1
    prep_compact<<<1, 256>>>();                                               // 2
    prep_all<<<dim3(1024, 12), 256>>>(embeds, aw1, ab1, aw2);                 // 3
    attn_kernel<<<8192, 128, ATTN_SMEM>>>();                                  // 4 <- profiled
    prep_sw1p<<<(XPAD * 1024 + 255) / 256, 256>>>(sw1);                       // 5
    softmax_build<<<B_, 256>>>(embeds, width_emb);                            // 6
    gemm_3x<<<dim3(8, 2, 8), 256>>>(x,  sw1p, part, 256, 1024, XPAD, 8);
    combine<1><<<(256 * 1024) / 256, 256>>>(part, sb1, h1, 256 * 1024, 1024, 8);
    gemm_3x<<<dim3(4, 2, 4), 256>>>(h1, sw2,  part, 256, 512, 1024, 4);
    combine<1><<<(256 * 512) / 256, 256>>>(part, sb2, h2, 256 * 512, 512, 4);
    gemm_3x<<<dim3(2, 2, 2), 256>>>(h2, sw3,  part, 256, 256, 512, 2);
    combine<1><<<(256 * 256) / 256, 256>>>(part, sb3, h3, 256 * 256, 256, 2);
    gemm_last<<<256, 256>>>(h3, sw4, sb4, out);
}

// round 11
// speedup vs baseline: 2.8155x; 1.1017x over previous
#include <cuda_runtime.h>
#include <cuda_fp16.h>
#include <cstdint>
#include <cstddef>

// Problem constants
#define B_ 256
#define L_ 512
#define D_ 768
#define H_ 1000
#define HP_ 1024
#define XDIM 2324
#define XPAD 2336

// attn tiling: block 128(M) x 128(N), K-chunks of 32 (2 x k16 MMA steps), 8 ncp passes
#define NKC 24             // 768/32
#define NCPN 8             // 1024 / 128
#define MAXT 1024          // max compacted tiles

// fp16 B tile image: per (kc,ncp): [ks(2)][tig(4)][n(132)][quad(4 halfs)] = 8448 B
#define BT_BYTES 8448
// fp16 A smem row: 32 halfs data + pad -> 80 B (banks 20g+tig -> conflict-free)
#define A_RSB 80

#define MLPS 16            // MLP K-split factor

// ---------------- scratch -------------------------------------------------------
__device__ int    g_spans[B_ * 2];
__device__ int    g_ntiles;
__device__ int    g_pos[B_ * L_];
__device__ float  g_attns[B_ * L_];
__device__ float  g_ab1p[HP_];
__device__ float  g_aw2p[HP_];
__device__ unsigned char g_Bpk[NKC * NCPN * BT_BYTES];   // packed fp16 aw1 smem image
__device__ __half g_Ef16[MAXT * 128 * D_];               // compacted span rows, fp16
__device__ float  g_x [B_ * XPAD];
__device__ float  g_sw1p[XPAD * 1024];
__device__ float  g_part[MLPS * 256 * 1024];
__device__ float  g_h1[B_ * 1024];
__device__ float  g_h2[B_ * 512];
__device__ float  g_h3[B_ * 256];

__device__ __forceinline__ uint32_t f2tf(float x) {
    uint32_t r;
    asm("cvt.rna.tf32.f32 %0, %1;" : "=r"(r) : "f"(x));
    return r;
}
__device__ __forceinline__ float tfv(float x) { return __uint_as_float(f2tf(x)); }

__device__ __forceinline__ void cp16(void* smem_dst, const void* gsrc) {
    uint32_t s = (uint32_t)__cvta_generic_to_shared(smem_dst);
    asm volatile("cp.async.cg.shared.global [%0], [%1], 16;\n" :: "r"(s), "l"(gsrc));
}
#define CP_COMMIT asm volatile("cp.async.commit_group;\n" ::: "memory")
#define CP_WAIT0  asm volatile("cp.async.wait_group 0;\n" ::: "memory")

__device__ __forceinline__ void mma_tf32(float* c, uint32_t a0, uint32_t a1,
                                         uint32_t a2, uint32_t a3,
                                         uint32_t b0, uint32_t b1) {
    asm volatile(
        "mma.sync.aligned.m16n8k8.row.col.f32.tf32.tf32.f32 "
        "{%0,%1,%2,%3}, {%4,%5,%6,%7}, {%8,%9}, {%0,%1,%2,%3};\n"
        : "+f"(c[0]), "+f"(c[1]), "+f"(c[2]), "+f"(c[3])
        : "r"(a0), "r"(a1), "r"(a2), "r"(a3), "r"(b0), "r"(b1));
}

__device__ __forceinline__ void mma_f16(float* c, uint32_t a0, uint32_t a1,
                                        uint32_t a2, uint32_t a3,
                                        uint32_t b0, uint32_t b1) {
    asm volatile(
        "mma.sync.aligned.m16n8k16.row.col.f32.f16.f16.f32 "
        "{%0,%1,%2,%3}, {%4,%5,%6,%7}, {%8,%9}, {%0,%1,%2,%3};\n"
        : "+f"(c[0]), "+f"(c[1]), "+f"(c[2]), "+f"(c[3])
        : "r"(a0), "r"(a1), "r"(a2), "r"(a3), "r"(b0), "r"(b1));
}

// ---------------- fused spans normalize + compaction ----------------------------
__global__ void prep_sc(const int* __restrict__ sp) {
    __shared__ int offs[257];
    int t = threadIdx.x;
    int odd = sp[2 * t + 1];
    int any_odd = __syncthreads_or(odd != 0);
    int s, e;
    if (any_odd) { s = sp[2 * t]; e = sp[2 * t + 1]; }
    else         { s = sp[4 * t]; e = sp[4 * t + 2]; }
    g_spans[2 * t] = s; g_spans[2 * t + 1] = e;
    int w = e - s + 1;
    offs[t + 1] = w;
    if (t == 0) offs[0] = 0;
    __syncthreads();
    if (t == 0) {
        for (int i = 1; i <= 256; i++) offs[i] += offs[i - 1];
        g_ntiles = (offs[256] + 127) >> 7;
    }
    __syncthreads();
    int base = offs[t];
    for (int k = 0; k < w; k++) g_pos[base + k] = (t << 16) | (s + k);
    int total = offs[256], NT = (total + 127) >> 7;
    for (int idx = total + t; idx < NT * 128; idx += 256) g_pos[idx] = (int)0x80000000;
}

// fused prep: y<8 -> compacted rows to fp16; y in [8,12) -> aw1 fp16 pack (coalesced)
// + zero attns + pad ab1/aw2; y in [12,22) -> sw1 padded copy.  grid (1024, 22) x 256
__global__ void prep_all(const float* __restrict__ E, const float* __restrict__ aw1,
                         const float* __restrict__ ab1, const float* __restrict__ aw2,
                         const float* __restrict__ sw1) {
    int tid = threadIdx.x;
    if (blockIdx.y < 8) {
        int tile = blockIdx.x;
        if (tile >= g_ntiles) return;
        int row = blockIdx.y * 16 + (tid >> 4);
        int l16 = tid & 15;
        int p = g_pos[tile * 128 + row];
        uint2* dst = (uint2*)(g_Ef16 + ((size_t)(tile * 128 + row)) * D_ + l16 * 48);
        if (p < 0) {
            uint2 z = make_uint2(0u, 0u);
            #pragma unroll
            for (int q = 0; q < 12; q++) dst[q] = z;
        } else {
            const float* src = E + ((size_t)((p >> 16) & 0x7FFF) * L_ + (p & 0xFFFF)) * D_ + l16 * 48;
            #pragma unroll
            for (int q = 0; q < 12; q++) {
                float4 v = ((const float4*)src)[q];
                __half2 h0 = __floats2half2_rn(v.x, v.y);
                __half2 h1 = __floats2half2_rn(v.z, v.w);
                dst[q] = make_uint2(*(uint32_t*)&h0, *(uint32_t*)&h1);
            }
        }
        return;
    }
    if (blockIdx.y < 12) {
        int lin = ((blockIdx.y - 8) * 1024 + blockIdx.x) * 256 + tid;
        if (lin < B_ * L_) g_attns[lin] = 0.f;
        if (lin < HP_) {
            g_ab1p[lin] = (lin < H_) ? ab1[lin] : 0.f;
            g_aw2p[lin] = (lin < H_) ? aw2[lin] : 0.f;
        }
        if (lin >= NKC * NCPN * (BT_BYTES / 2)) return;
        int tile = lin / (BT_BYTES / 2), within = lin % (BT_BYTES / 2);
        int kc = tile >> 3, ncp = tile & 7;
        // n-fastest mapping: within = ((ks*4 + tg)*4 + c)*132 + n  -> coalesced aw1 reads
        int n  = within % 132;
        int t4 = within / 132;
        int c  = t4 & 3;
        int t5 = t4 >> 2;
        int tg = t5 & 3;
        int ks = t5 >> 2;
        float v = 0.f;
        if (n < 128) {
            int col = ncp * 128 + n;
            if (col < H_) {
                int k = kc * 32 + ks * 16 + 2 * tg + (c & 1) + ((c >> 1) << 3);
                v = aw1[(size_t)k * H_ + col];
            }
        }
        __half h = __float2half_rn(v);
        *(unsigned short*)(g_Bpk + (size_t)tile * BT_BYTES + ks * 4224 + tg * 1056 + n * 8 + c * 2)
            = *(unsigned short*)&h;
        return;
    }
    size_t i = ((size_t)(blockIdx.y - 12) * 1024 + blockIdx.x) * 256 + tid;
    if (i < (size_t)XPAD * 1024) {
        int r = (int)(i >> 10), c2 = (int)(i & 1023);
        g_sw1p[i] = (r < XDIM) ? sw1[(size_t)r * 1024 + c2] : 0.f;
    }
}

// ---------------- attn: 4 warps 64x64, fp16 m16n8k16, 2 CTAs/SM -----------------
// grid 8192 = 1024 tiles x 8 ncp; 128 threads (4 warps = 2m x 2n, warp 64x64)
// smem bytes: A0[0,10240) A1[10240,20480) B0[20480,28928) B1[28928,37376) pos[512]
#define ATTN_SMEM (37376 + 512)

__global__ void __launch_bounds__(128, 2) attn_kernel() {
    int unit = blockIdx.x;
    int tile = unit >> 3, ncp = unit & 7;
    if (tile >= g_ntiles) return;

    extern __shared__ char smc[];
    char* Abuf[2] = { smc, smc + 10240 };
    char* Bbuf[2] = { smc + 20480, smc + 28928 };
    int* pos = (int*)(smc + 37376);

    int tid = threadIdx.x;
    int warp = tid >> 5, lane = tid & 31, g = lane >> 2, tig = lane & 3;
    int wm = warp >> 1, wn = warp & 1;

    pos[tid] = g_pos[tile * 128 + tid];
    const __half* asrc = g_Ef16 + (size_t)tile * 128 * D_ + (size_t)tid * D_;
    const unsigned char* bbase = g_Bpk + (size_t)ncp * BT_BYTES;

    float c[4][8][4] = {};

    // prolog: fill buffers 0 (kc = 0)
    {
        const unsigned char* sB = bbase;
        #pragma unroll
        for (int k2 = 0; k2 < 5; k2++) {
            int i = tid + k2 * 128;
            if (i < 528) cp16(Bbuf[0] + i * 16, sB + i * 16);
        }
        #pragma unroll
        for (int q = 0; q < 4; q++) cp16(Abuf[0] + tid * A_RSB + q * 16, asrc + q * 8);
        CP_COMMIT;
        CP_WAIT0;
        __syncthreads();
    }

    for (int kc = 0; kc < NKC; kc++) {
        int cur = kc & 1, nxt = cur ^ 1;
        if (kc < NKC - 1) {
            const unsigned char* sB = bbase + (size_t)(kc + 1) * NCPN * BT_BYTES;
            #pragma unroll
            for (int k2 = 0; k2 < 5; k2++) {
                int i = tid + k2 * 128;
                if (i < 528) cp16(Bbuf[nxt] + i * 16, sB + i * 16);
            }
            const __half* sA = asrc + (kc + 1) * 32;
            #pragma unroll
            for (int q = 0; q < 4; q++) cp16(Abuf[nxt] + tid * A_RSB + q * 16, sA + q * 8);
            CP_COMMIT;
        }
        const char* Ac = Abuf[cur];
        const char* Bc = Bbuf[cur];
        #pragma unroll
        for (int ks = 0; ks < 2; ks++) {
            uint32_t a[4][4];
            uint2 b[8];
            #pragma unroll
            for (int i = 0; i < 4; i++) {
                const char* pa = Ac + (wm * 64 + i * 16 + g) * A_RSB + ks * 32 + tig * 4;
                a[i][0] = *(const uint32_t*)pa;
                a[i][2] = *(const uint32_t*)(pa + 16);
                a[i][1] = *(const uint32_t*)(pa + 8 * A_RSB);
                a[i][3] = *(const uint32_t*)(pa + 8 * A_RSB + 16);
            }
            #pragma unroll
            for (int j = 0; j < 8; j++) {
                int n = wn * 64 + j * 8 + g;
                b[j] = *(const uint2*)(Bc + ks * 4224 + tig * 1056 + n * 8);
            }
            #pragma unroll
            for (int i = 0; i < 4; i++)
                #pragma unroll
                for (int j = 0; j < 8; j++)
                    mma_f16(c[i][j], a[i][0], a[i][1], a[i][2], a[i][3], b[j].x, b[j].y);
        }
        if (kc < NKC - 1) CP_WAIT0;
        __syncthreads();
    }

    // epilogue: lrelu(c + b1) * aw2, reduce over this pass's 128 hidden cols
    int n0 = ncp * 128;
    #pragma unroll
    for (int i = 0; i < 4; i++) {
        float ra = 0.f, rb = 0.f;
        #pragma unroll
        for (int j = 0; j < 8; j++) {
            int col0 = n0 + wn * 64 + j * 8 + tig * 2;
            float b1a = g_ab1p[col0], b1b = g_ab1p[col0 + 1];
            float w2a = g_aw2p[col0], w2b = g_aw2p[col0 + 1];
            float z;
            z = c[i][j][0] + b1a; ra += (z > 0.f ? z : 0.01f * z) * w2a;
            z = c[i][j][1] + b1b; ra += (z > 0.f ? z : 0.01f * z) * w2b;
            z = c[i][j][2] + b1a; rb += (z > 0.f ? z : 0.01f * z) * w2a;
            z = c[i][j][3] + b1b; rb += (z > 0.f ? z : 0.01f * z) * w2b;
        }
        ra += __shfl_xor_sync(0xffffffffu, ra, 1);
        ra += __shfl_xor_sync(0xffffffffu, ra, 2);
        rb += __shfl_xor_sync(0xffffffffu, rb, 1);
        rb += __shfl_xor_sync(0xffffffffu, rb, 2);
        if (tig == 0) {
            int r0 = wm * 64 + i * 16 + g;
            int p0 = pos[r0], p1 = pos[r0 + 8];
            if (p0 >= 0) atomicAdd(&g_attns[((p0 >> 16) & 0x7FFF) * L_ + (p0 & 0xFFFF)], ra);
            if (p1 >= 0) atomicAdd(&g_attns[((p1 >> 16) & 0x7FFF) * L_ + (p1 & 0xFFFF)], rb);
        }
    }
}

// ---------------- softmax over span + weighted reduce + build concat x ----------
__global__ void __launch_bounds__(256) softmax_build(const float* __restrict__ E,
                                                     const float* __restrict__ width_emb) {
    int b = blockIdx.x;
    int tid = threadIdx.x, warp = tid >> 5, lane = tid & 31;
    int s = g_spans[b * 2], e = g_spans[b * 2 + 1];
    int width = e - s + 1;

    __shared__ float ws[L_];
    __shared__ float red[256];
    __shared__ float sacc[D_];

    float lm = -1e30f;
    for (int l = s + tid; l <= e; l += 256) lm = fmaxf(lm, g_attns[b * L_ + l]);
    red[tid] = lm; __syncthreads();
    for (int st = 128; st > 0; st >>= 1) {
        if (tid < st) red[tid] = fmaxf(red[tid], red[tid + st]);
        __syncthreads();
    }
    float mx = red[0];
    __syncthreads();
    float ls = 0.f;
    for (int l = s + tid; l <= e; l += 256) {
        float ev = __expf(g_attns[b * L_ + l] - mx);
        ws[l - s] = ev;
        ls += ev;
    }
    red[tid] = ls; __syncthreads();
    for (int st = 128; st > 0; st >>= 1) {
        if (tid < st) red[tid] += red[tid + st];
        __syncthreads();
    }
    float inv = 1.f / red[0];
    for (int d = tid; d < D_; d += 256) sacc[d] = 0.f;
    __syncthreads();

    float acc[24];
    #pragma unroll
    for (int c2 = 0; c2 < 24; c2++) acc[c2] = 0.f;
    const float* Ebase = E + (size_t)b * L_ * D_;
    for (int l = s + warp; l <= e; l += 8) {
        float wv = ws[l - s];
        const float* row = Ebase + (size_t)l * D_;
        #pragma unroll
        for (int c2 = 0; c2 < 24; c2++) acc[c2] += wv * row[c2 * 32 + lane];
    }
    #pragma unroll
    for (int c2 = 0; c2 < 24; c2++) atomicAdd(&sacc[c2 * 32 + lane], acc[c2]);
    __syncthreads();

    float* xb = g_x + (size_t)b * XPAD;
    for (int d = tid; d < D_; d += 256) xb[1536 + d] = sacc[d] * inv;

    const float* rs = Ebase + (size_t)s * D_;
    const float* re = Ebase + (size_t)e * D_;
    for (int d = tid; d < D_; d += 256) { xb[d] = rs[d]; xb[D_ + d] = re[d]; }

    if (tid < 20) {
        const int bins[15] = {1,2,3,4,5,6,7,8,12,16,20,24,32,64,128};
        int idx = 0;
        #pragma unroll
        for (int j = 0; j < 15; j++) idx += (width > bins[j]) ? 1 : 0;
        xb[2304 + tid] = width_emb[idx * 20 + tid];
    }
    if (tid < XPAD - XDIM) xb[XDIM + tid] = 0.f;
}

// ---------------- 3xTF32 GEMM with K-split partials -----------------------------
__global__ void __launch_bounds__(256) gemm_3x(const float* __restrict__ A,
                                               const float* __restrict__ Bw,
                                               float* __restrict__ part,
                                               int M, int N, int K, int S) {
    __shared__ float Ah[128][20], Al[128][20];
    __shared__ float Bh[16][136], Bl[16][136];
    int tid = threadIdx.x, warp = tid >> 5, lane = tid & 31, g = lane >> 2, tig = lane & 3;
    int wm = warp >> 2, wn = warp & 3;
    int bm = blockIdx.y * 128, bn = blockIdx.x * 128;
    int nch = K >> 4;
    int z = blockIdx.z;
    int c0 = (int)((long)nch * z / S), c1 = (int)((long)nch * (z + 1) / S);

    float c[4][4][4] = {};
    for (int ch = c0; ch < c1; ch++) {
        int k0 = ch * 16;
        {
            int r = tid >> 1, h = (tid & 1) * 8;
            const float* src = A + (size_t)(bm + r) * K + k0 + h;
            float4 v0 = *(const float4*)src, v1 = *(const float4*)(src + 4);
            float vv[8] = {v0.x, v0.y, v0.z, v0.w, v1.x, v1.y, v1.z, v1.w};
            #pragma unroll
            for (int q = 0; q < 8; q++) {
                float hi = tfv(vv[q]);
                Ah[r][h + q] = hi;
                Al[r][h + q] = tfv(vv[q] - hi);
            }
        }
        {
            int r = tid >> 4, cb = (tid & 15) * 8;
            const float* src = Bw + (size_t)(k0 + r) * N + bn + cb;
            float4 v0 = *(const float4*)src, v1 = *(const float4*)(src + 4);
            float vv[8] = {v0.x, v0.y, v0.z, v0.w, v1.x, v1.y, v1.z, v1.w};
            #pragma unroll
            for (int q = 0; q < 8; q++) {
                float hi = tfv(vv[q]);
                Bh[r][cb + q] = hi;
                Bl[r][cb + q] = tfv(vv[q] - hi);
            }
        }
        __syncthreads();
        #pragma unroll
        for (int ks = 0; ks < 2; ks++) {
            int k = ks * 8;
            uint32_t ah4[4][4], al4[4][4], bh2[4][2], bl2[4][2];
            #pragma unroll
            for (int i = 0; i < 4; i++) {
                int mr = wm * 64 + i * 16;
                ah4[i][0] = __float_as_uint(Ah[mr + g    ][k + tig    ]);
                ah4[i][1] = __float_as_uint(Ah[mr + g + 8][k + tig    ]);
                ah4[i][2] = __float_as_uint(Ah[mr + g    ][k + tig + 4]);
                ah4[i][3] = __float_as_uint(Ah[mr + g + 8][k + tig + 4]);
                al4[i][0] = __float_as_uint(Al[mr + g    ][k + tig    ]);
                al4[i][1] = __float_as_uint(Al[mr + g + 8][k + tig    ]);
                al4[i][2] = __float_as_uint(Al[mr + g    ][k + tig + 4]);
                al4[i][3] = __float_as_uint(Al[mr + g + 8][k + tig + 4]);
            }
            #pragma unroll
            for (int j = 0; j < 4; j++) {
                int n = wn * 32 + j * 8 + g;
                bh2[j][0] = __float_as_uint(Bh[k + tig    ][n]);
                bh2[j][1] = __float_as_uint(Bh[k + tig + 4][n]);
                bl2[j][0] = __float_as_uint(Bl[k + tig    ][n]);
                bl2[j][1] = __float_as_uint(Bl[k + tig + 4][n]);
            }
            #pragma unroll
            for (int i = 0; i < 4; i++)
                #pragma unroll
                for (int j = 0; j < 4; j++) {
                    mma_tf32(c[i][j], al4[i][0], al4[i][1], al4[i][2], al4[i][3], bh2[j][0], bh2[j][1]);
                    mma_tf32(c[i][j], ah4[i][0], ah4[i][1], ah4[i][2], ah4[i][3], bl2[j][0], bl2[j][1]);
                    mma_tf32(c[i][j], ah4[i][0], ah4[i][1], ah4[i][2], ah4[i][3], bh2[j][0], bh2[j][1]);
                }
        }
        __syncthreads();
    }
    float* dst = part + ((size_t)z * M + bm) * N + bn;
    #pragma unroll
    for (int i = 0; i < 4; i++)
        #pragma unroll
        for (int j = 0; j < 4; j++) {
            int row = wm * 64 + i * 16 + g, col = wn * 32 + j * 8 + tig * 2;
            dst[(size_t)row * N + col]       = c[i][j][0];
            dst[(size_t)row * N + col + 1]   = c[i][j][1];
            dst[(size_t)(row+8) * N + col]   = c[i][j][2];
            dst[(size_t)(row+8) * N + col+1] = c[i][j][3];
        }
}

template<int ACT>
__global__ void combine(const float* __restrict__ part, const float* __restrict__ bias,
                        float* __restrict__ out, int MN, int N, int S) {
    int i = blockIdx.x * 256 + threadIdx.x;
    if (i >= MN) return;
    float v = 0.f;
    for (int z = 0; z < S; z++) v += part[(size_t)z * MN + i];
    v += bias[i % N];
    if (ACT) v = v > 0.f ? v : 0.01f * v;
    out[i] = v;
}

// ---------------- small fp32 GEMM for the final 256x30 layer --------------------
__global__ void __launch_bounds__(256) gemm_last(const float* __restrict__ A,
                                                 const float* __restrict__ W,
                                                 const float* __restrict__ bias,
                                                 float* __restrict__ C) {
    int m = blockIdx.x;
    int tid = threadIdx.x;
    int col = tid % 30, seg = tid / 30;
    __shared__ float red[256];
    float v = 0.f;
    if (seg < 8) {
        const float* a = A + (size_t)m * 256 + seg * 32;
        const float* w = W + col;
        #pragma unroll
        for (int k = 0; k < 32; k++) v += a[k] * w[(size_t)(seg * 32 + k) * 30];
    }
    red[tid] = v;
    __syncthreads();
    if (tid < 30) {
        float acc = 0.f;
        #pragma unroll
        for (int s2 = 0; s2 < 8; s2++) acc += red[s2 * 30 + tid];
        C[(size_t)m * 30 + tid] = acc + bias[tid];
    }
}

// ---------------- launch ---------------------------------------------------------
extern "C" void kernel_launch(void* const* d_in, const int* in_sizes, int n_in,
                              void* d_out, int out_size) {
    const float* embeds    = (const float*)d_in[0];
    const int*   spans_raw = (const int*)d_in[1];
    const float* aw1       = (const float*)d_in[2];
    const float* ab1       = (const float*)d_in[3];
    const float* aw2       = (const float*)d_in[4];
    // d_in[5] = ab2 : uniform logit offset, softmax-invariant -> unused
    const float* width_emb = (const float*)d_in[6];
    const float* sw1 = (const float*)d_in[7];
    const float* sb1 = (const float*)d_in[8];
    const float* sw2 = (const float*)d_in[9];
    const float* sb2 = (const float*)d_in[10];
    const float* sw3 = (const float*)d_in[11];
    const float* sb3 = (const float*)d_in[12];
    const float* sw4 = (const float*)d_in[13];
    const float* sb4 = (const float*)d_in[14];
    float* out = (float*)d_out;

    float *x, *h1, *h2, *h3, *part, *sw1p;
    cudaGetSymbolAddress((void**)&x,    g_x);
    cudaGetSymbolAddress((void**)&h1,   g_h1);
    cudaGetSymbolAddress((void**)&h2,   g_h2);
    cudaGetSymbolAddress((void**)&h3,   g_h3);
    cudaGetSymbolAddress((void**)&part, g_part);
    cudaGetSymbolAddress((void**)&sw1p, g_sw1p);

    prep_sc<<<1, 256>>>(spans_raw);                                           // 1
    prep_all<<<dim3(1024, 22), 256>>>(embeds, aw1, ab1, aw2, sw1);            // 2
    attn_kernel<<<8192, 128, ATTN_SMEM>>>();                                  // 3
    softmax_build<<<B_, 256>>>(embeds, width_emb);                            // 4 <- profiled
    gemm_3x<<<dim3(8, 2, MLPS), 256>>>(x,  sw1p, part, 256, 1024, XPAD, MLPS);
    combine<1><<<(256 * 1024) / 256, 256>>>(part, sb1, h1, 256 * 1024, 1024, MLPS);
    gemm_3x<<<dim3(4, 2, MLPS), 256>>>(h1, sw2,  part, 256, 512, 1024, MLPS);
    combine<1><<<(256 * 512) / 256, 256>>>(part, sb2, h2, 256 * 512, 512, MLPS);
    gemm_3x<<<dim3(2, 2, MLPS), 256>>>(h2, sw3,  part, 256, 256, 512, MLPS);
    combine<1><<<(256 * 256) / 256, 256>>>(part, sb3, h3, 256 * 256, 256, MLPS);
    gemm_last<<<256, 256>>>(h3, sw4, sb4, out);
}

// round 12
// speedup vs baseline: 3.4562x; 1.2276x over previous
#include <cuda_runtime.h>
#include <cuda_fp16.h>
#include <cstdint>
#include <cstddef>

// Problem constants
#define B_ 256
#define L_ 512
#define D_ 768
#define H_ 1000
#define HP_ 1024
#define XDIM 2324
#define XPAD 2336

// attn tiling: block 128(M) x 128(N), K-chunks of 32 (2 x k16 MMA steps), 8 ncp passes
#define NKC 24             // 768/32
#define NCPN 8             // 1024 / 128
#define MAXT 1024          // max compacted tiles

// fp16 B tile image: per (kc,ncp): [ks(2)][tig(4)][n(132)][quad(4 halfs)] = 8448 B
#define BT_BYTES 8448
// fp16 A smem row: 32 halfs data + pad -> 80 B (banks 20g+tig -> conflict-free)
#define A_RSB 80

#define MLPS 16            // MLP K-split factor

// ---------------- scratch -------------------------------------------------------
__device__ int    g_spans[B_ * 2];
__device__ int    g_ntiles;
__device__ int    g_pos[B_ * L_];
__device__ float  g_attns[B_ * L_];
__device__ float  g_ab1p[HP_];
__device__ float  g_aw2p[HP_];
__device__ unsigned char g_Bpk[NKC * NCPN * BT_BYTES];   // packed fp16 aw1 smem image
__device__ __half g_Ef16[MAXT * 128 * D_];               // compacted span rows, fp16
__device__ float  g_x [B_ * XPAD];
__device__ float  g_sw1p[XPAD * 1024];
__device__ float  g_part[MLPS * 256 * 1024];
__device__ float  g_h1[B_ * 1024];
__device__ float  g_h2[B_ * 512];
__device__ float  g_h3[B_ * 256];

__device__ __forceinline__ uint32_t f2tf(float x) {
    uint32_t r;
    asm("cvt.rna.tf32.f32 %0, %1;" : "=r"(r) : "f"(x));
    return r;
}
__device__ __forceinline__ float tfv(float x) { return __uint_as_float(f2tf(x)); }

__device__ __forceinline__ void cp16(void* smem_dst, const void* gsrc) {
    uint32_t s = (uint32_t)__cvta_generic_to_shared(smem_dst);
    asm volatile("cp.async.cg.shared.global [%0], [%1], 16;\n" :: "r"(s), "l"(gsrc));
}
#define CP_COMMIT asm volatile("cp.async.commit_group;\n" ::: "memory")
#define CP_WAIT0  asm volatile("cp.async.wait_group 0;\n" ::: "memory")

__device__ __forceinline__ void mma_tf32(float* c, uint32_t a0, uint32_t a1,
                                         uint32_t a2, uint32_t a3,
                                         uint32_t b0, uint32_t b1) {
    asm volatile(
        "mma.sync.aligned.m16n8k8.row.col.f32.tf32.tf32.f32 "
        "{%0,%1,%2,%3}, {%4,%5,%6,%7}, {%8,%9}, {%0,%1,%2,%3};\n"
        : "+f"(c[0]), "+f"(c[1]), "+f"(c[2]), "+f"(c[3])
        : "r"(a0), "r"(a1), "r"(a2), "r"(a3), "r"(b0), "r"(b1));
}

__device__ __forceinline__ void mma_f16(float* c, uint32_t a0, uint32_t a1,
                                        uint32_t a2, uint32_t a3,
                                        uint32_t b0, uint32_t b1) {
    asm volatile(
        "mma.sync.aligned.m16n8k16.row.col.f32.f16.f16.f32 "
        "{%0,%1,%2,%3}, {%4,%5,%6,%7}, {%8,%9}, {%0,%1,%2,%3};\n"
        : "+f"(c[0]), "+f"(c[1]), "+f"(c[2]), "+f"(c[3])
        : "r"(a0), "r"(a1), "r"(a2), "r"(a3), "r"(b0), "r"(b1));
}

// ---------------- fused spans normalize + compaction ----------------------------
__global__ void prep_sc(const int* __restrict__ sp) {
    __shared__ int offs[257];
    int t = threadIdx.x;
    int odd = sp[2 * t + 1];
    int any_odd = __syncthreads_or(odd != 0);
    int s, e;
    if (any_odd) { s = sp[2 * t]; e = sp[2 * t + 1]; }
    else         { s = sp[4 * t]; e = sp[4 * t + 2]; }
    g_spans[2 * t] = s; g_spans[2 * t + 1] = e;
    int w = e - s + 1;
    offs[t + 1] = w;
    if (t == 0) offs[0] = 0;
    __syncthreads();
    if (t == 0) {
        for (int i = 1; i <= 256; i++) offs[i] += offs[i - 1];
        g_ntiles = (offs[256] + 127) >> 7;
    }
    __syncthreads();
    int base = offs[t];
    for (int k = 0; k < w; k++) g_pos[base + k] = (t << 16) | (s + k);
    int total = offs[256], NT = (total + 127) >> 7;
    for (int idx = total + t; idx < NT * 128; idx += 256) g_pos[idx] = (int)0x80000000;
}

// fused prep: y<8 -> compacted rows to fp16; y in [8,12) -> aw1 fp16 pack (coalesced)
// + zero attns + pad ab1/aw2; y in [12,22) -> sw1 padded copy.  grid (1024, 22) x 256
__global__ void prep_all(const float* __restrict__ E, const float* __restrict__ aw1,
                         const float* __restrict__ ab1, const float* __restrict__ aw2,
                         const float* __restrict__ sw1) {
    int tid = threadIdx.x;
    if (blockIdx.y < 8) {
        int tile = blockIdx.x;
        if (tile >= g_ntiles) return;
        int row = blockIdx.y * 16 + (tid >> 4);
        int l16 = tid & 15;
        int p = g_pos[tile * 128 + row];
        uint2* dst = (uint2*)(g_Ef16 + ((size_t)(tile * 128 + row)) * D_ + l16 * 48);
        if (p < 0) {
            uint2 z = make_uint2(0u, 0u);
            #pragma unroll
            for (int q = 0; q < 12; q++) dst[q] = z;
        } else {
            const float* src = E + ((size_t)((p >> 16) & 0x7FFF) * L_ + (p & 0xFFFF)) * D_ + l16 * 48;
            #pragma unroll
            for (int q = 0; q < 12; q++) {
                float4 v = ((const float4*)src)[q];
                __half2 h0 = __floats2half2_rn(v.x, v.y);
                __half2 h1 = __floats2half2_rn(v.z, v.w);
                dst[q] = make_uint2(*(uint32_t*)&h0, *(uint32_t*)&h1);
            }
        }
        return;
    }
    if (blockIdx.y < 12) {
        int lin = ((blockIdx.y - 8) * 1024 + blockIdx.x) * 256 + tid;
        if (lin < B_ * L_) g_attns[lin] = 0.f;
        if (lin < HP_) {
            g_ab1p[lin] = (lin < H_) ? ab1[lin] : 0.f;
            g_aw2p[lin] = (lin < H_) ? aw2[lin] : 0.f;
        }
        if (lin >= NKC * NCPN * (BT_BYTES / 2)) return;
        int tile = lin / (BT_BYTES / 2), within = lin % (BT_BYTES / 2);
        int kc = tile >> 3, ncp = tile & 7;
        int n  = within % 132;
        int t4 = within / 132;
        int c  = t4 & 3;
        int t5 = t4 >> 2;
        int tg = t5 & 3;
        int ks = t5 >> 2;
        float v = 0.f;
        if (n < 128) {
            int col = ncp * 128 + n;
            if (col < H_) {
                int k = kc * 32 + ks * 16 + 2 * tg + (c & 1) + ((c >> 1) << 3);
                v = aw1[(size_t)k * H_ + col];
            }
        }
        __half h = __float2half_rn(v);
        *(unsigned short*)(g_Bpk + (size_t)tile * BT_BYTES + ks * 4224 + tg * 1056 + n * 8 + c * 2)
            = *(unsigned short*)&h;
        return;
    }
    size_t i = ((size_t)(blockIdx.y - 12) * 1024 + blockIdx.x) * 256 + tid;
    if (i < (size_t)XPAD * 1024) {
        int r = (int)(i >> 10), c2 = (int)(i & 1023);
        g_sw1p[i] = (r < XDIM) ? sw1[(size_t)r * 1024 + c2] : 0.f;
    }
}

// ---------------- attn: 4 warps 64x64, fp16 m16n8k16, 2 CTAs/SM -----------------
#define ATTN_SMEM (37376 + 512)

__global__ void __launch_bounds__(128, 2) attn_kernel() {
    int unit = blockIdx.x;
    int tile = unit >> 3, ncp = unit & 7;
    if (tile >= g_ntiles) return;

    extern __shared__ char smc[];
    char* Abuf[2] = { smc, smc + 10240 };
    char* Bbuf[2] = { smc + 20480, smc + 28928 };
    int* pos = (int*)(smc + 37376);

    int tid = threadIdx.x;
    int warp = tid >> 5, lane = tid & 31, g = lane >> 2, tig = lane & 3;
    int wm = warp >> 1, wn = warp & 1;

    pos[tid] = g_pos[tile * 128 + tid];
    const __half* asrc = g_Ef16 + (size_t)tile * 128 * D_ + (size_t)tid * D_;
    const unsigned char* bbase = g_Bpk + (size_t)ncp * BT_BYTES;

    float c[4][8][4] = {};

    {
        const unsigned char* sB = bbase;
        #pragma unroll
        for (int k2 = 0; k2 < 5; k2++) {
            int i = tid + k2 * 128;
            if (i < 528) cp16(Bbuf[0] + i * 16, sB + i * 16);
        }
        #pragma unroll
        for (int q = 0; q < 4; q++) cp16(Abuf[0] + tid * A_RSB + q * 16, asrc + q * 8);
        CP_COMMIT;
        CP_WAIT0;
        __syncthreads();
    }

    for (int kc = 0; kc < NKC; kc++) {
        int cur = kc & 1, nxt = cur ^ 1;
        if (kc < NKC - 1) {
            const unsigned char* sB = bbase + (size_t)(kc + 1) * NCPN * BT_BYTES;
            #pragma unroll
            for (int k2 = 0; k2 < 5; k2++) {
                int i = tid + k2 * 128;
                if (i < 528) cp16(Bbuf[nxt] + i * 16, sB + i * 16);
            }
            const __half* sA = asrc + (kc + 1) * 32;
            #pragma unroll
            for (int q = 0; q < 4; q++) cp16(Abuf[nxt] + tid * A_RSB + q * 16, sA + q * 8);
            CP_COMMIT;
        }
        const char* Ac = Abuf[cur];
        const char* Bc = Bbuf[cur];
        #pragma unroll
        for (int ks = 0; ks < 2; ks++) {
            uint32_t a[4][4];
            uint2 b[8];
            #pragma unroll
            for (int i = 0; i < 4; i++) {
                const char* pa = Ac + (wm * 64 + i * 16 + g) * A_RSB + ks * 32 + tig * 4;
                a[i][0] = *(const uint32_t*)pa;
                a[i][2] = *(const uint32_t*)(pa + 16);
                a[i][1] = *(const uint32_t*)(pa + 8 * A_RSB);
                a[i][3] = *(const uint32_t*)(pa + 8 * A_RSB + 16);
            }
            #pragma unroll
            for (int j = 0; j < 8; j++) {
                int n = wn * 64 + j * 8 + g;
                b[j] = *(const uint2*)(Bc + ks * 4224 + tig * 1056 + n * 8);
            }
            #pragma unroll
            for (int i = 0; i < 4; i++)
                #pragma unroll
                for (int j = 0; j < 8; j++)
                    mma_f16(c[i][j], a[i][0], a[i][1], a[i][2], a[i][3], b[j].x, b[j].y);
        }
        if (kc < NKC - 1) CP_WAIT0;
        __syncthreads();
    }

    int n0 = ncp * 128;
    #pragma unroll
    for (int i = 0; i < 4; i++) {
        float ra = 0.f, rb = 0.f;
        #pragma unroll
        for (int j = 0; j < 8; j++) {
            int col0 = n0 + wn * 64 + j * 8 + tig * 2;
            float b1a = g_ab1p[col0], b1b = g_ab1p[col0 + 1];
            float w2a = g_aw2p[col0], w2b = g_aw2p[col0 + 1];
            float z;
            z = c[i][j][0] + b1a; ra += (z > 0.f ? z : 0.01f * z) * w2a;
            z = c[i][j][1] + b1b; ra += (z > 0.f ? z : 0.01f * z) * w2b;
            z = c[i][j][2] + b1a; rb += (z > 0.f ? z : 0.01f * z) * w2a;
            z = c[i][j][3] + b1b; rb += (z > 0.f ? z : 0.01f * z) * w2b;
        }
        ra += __shfl_xor_sync(0xffffffffu, ra, 1);
        ra += __shfl_xor_sync(0xffffffffu, ra, 2);
        rb += __shfl_xor_sync(0xffffffffu, rb, 1);
        rb += __shfl_xor_sync(0xffffffffu, rb, 2);
        if (tig == 0) {
            int r0 = wm * 64 + i * 16 + g;
            int p0 = pos[r0], p1 = pos[r0 + 8];
            if (p0 >= 0) atomicAdd(&g_attns[((p0 >> 16) & 0x7FFF) * L_ + (p0 & 0xFFFF)], ra);
            if (p1 >= 0) atomicAdd(&g_attns[((p1 >> 16) & 0x7FFF) * L_ + (p1 & 0xFFFF)], rb);
        }
    }
}

// ---------------- softmax + weighted sum, split 3 dim-chunks per batch ----------
// grid (B_, 3), 256 threads. Each block: recompute softmax over span (cheap),
// then weighted-sum 256 dims. Chunk 0 also writes se / width emb / pad.
__global__ void __launch_bounds__(256) sm_wsum(const float* __restrict__ E,
                                               const float* __restrict__ width_emb) {
    int b = blockIdx.x, chunk = blockIdx.y;
    int tid = threadIdx.x;
    int s = g_spans[b * 2], e = g_spans[b * 2 + 1];
    int width = e - s + 1;

    __shared__ float ws[L_];
    __shared__ float red[256];

    float lm = -1e30f;
    for (int l = s + tid; l <= e; l += 256) lm = fmaxf(lm, g_attns[b * L_ + l]);
    red[tid] = lm; __syncthreads();
    for (int st = 128; st > 0; st >>= 1) {
        if (tid < st) red[tid] = fmaxf(red[tid], red[tid + st]);
        __syncthreads();
    }
    float mx = red[0];
    __syncthreads();
    float ls = 0.f;
    for (int l = s + tid; l <= e; l += 256) {
        float ev = __expf(g_attns[b * L_ + l] - mx);
        ws[l - s] = ev;
        ls += ev;
    }
    red[tid] = ls; __syncthreads();
    for (int st = 128; st > 0; st >>= 1) {
        if (tid < st) red[tid] += red[tid + st];
        __syncthreads();
    }
    float inv = 1.f / red[0];

    float* xb = g_x + (size_t)b * XPAD;
    const float* Ebase = E + (size_t)b * L_ * D_;

    // weighted sum for this block's 256 dims
    int d = chunk * 256 + tid;
    const float* col = Ebase + (size_t)s * D_ + d;
    float acc = 0.f;
    #pragma unroll 4
    for (int l = 0; l < width; l++) acc += ws[l] * col[(size_t)l * D_];
    xb[1536 + d] = acc * inv;

    if (chunk == 0) {
        const float* rs = Ebase + (size_t)s * D_;
        const float* re = Ebase + (size_t)e * D_;
        for (int dd = tid; dd < D_; dd += 256) { xb[dd] = rs[dd]; xb[D_ + dd] = re[dd]; }
        if (tid < 20) {
            const int bins[15] = {1,2,3,4,5,6,7,8,12,16,20,24,32,64,128};
            int idx = 0;
            #pragma unroll
            for (int j = 0; j < 15; j++) idx += (width > bins[j]) ? 1 : 0;
            xb[2304 + tid] = width_emb[idx * 20 + tid];
        }
        if (tid < XPAD - XDIM) xb[XDIM + tid] = 0.f;
    }
}

// ---------------- 3xTF32 GEMM with K-split partials -----------------------------
__global__ void __launch_bounds__(256) gemm_3x(const float* __restrict__ A,
                                               const float* __restrict__ Bw,
                                               float* __restrict__ part,
                                               int M, int N, int K, int S) {
    __shared__ float Ah[128][20], Al[128][20];
    __shared__ float Bh[16][136], Bl[16][136];
    int tid = threadIdx.x, warp = tid >> 5, lane = tid & 31, g = lane >> 2, tig = lane & 3;
    int wm = warp >> 2, wn = warp & 3;
    int bm = blockIdx.y * 128, bn = blockIdx.x * 128;
    int nch = K >> 4;
    int z = blockIdx.z;
    int c0 = (int)((long)nch * z / S), c1 = (int)((long)nch * (z + 1) / S);

    float c[4][4][4] = {};
    for (int ch = c0; ch < c1; ch++) {
        int k0 = ch * 16;
        {
            int r = tid >> 1, h = (tid & 1) * 8;
            const float* src = A + (size_t)(bm + r) * K + k0 + h;
            float4 v0 = *(const float4*)src, v1 = *(const float4*)(src + 4);
            float vv[8] = {v0.x, v0.y, v0.z, v0.w, v1.x, v1.y, v1.z, v1.w};
            #pragma unroll
            for (int q = 0; q < 8; q++) {
                float hi = tfv(vv[q]);
                Ah[r][h + q] = hi;
                Al[r][h + q] = tfv(vv[q] - hi);
            }
        }
        {
            int r = tid >> 4, cb = (tid & 15) * 8;
            const float* src = Bw + (size_t)(k0 + r) * N + bn + cb;
            float4 v0 = *(const float4*)src, v1 = *(const float4*)(src + 4);
            float vv[8] = {v0.x, v0.y, v0.z, v0.w, v1.x, v1.y, v1.z, v1.w};
            #pragma unroll
            for (int q = 0; q < 8; q++) {
                float hi = tfv(vv[q]);
                Bh[r][cb + q] = hi;
                Bl[r][cb + q] = tfv(vv[q] - hi);
            }
        }
        __syncthreads();
        #pragma unroll
        for (int ks = 0; ks < 2; ks++) {
            int k = ks * 8;
            uint32_t ah4[4][4], al4[4][4], bh2[4][2], bl2[4][2];
            #pragma unroll
            for (int i = 0; i < 4; i++) {
                int mr = wm * 64 + i * 16;
                ah4[i][0] = __float_as_uint(Ah[mr + g    ][k + tig    ]);
                ah4[i][1] = __float_as_uint(Ah[mr + g + 8][k + tig    ]);
                ah4[i][2] = __float_as_uint(Ah[mr + g    ][k + tig + 4]);
                ah4[i][3] = __float_as_uint(Ah[mr + g + 8][k + tig + 4]);
                al4[i][0] = __float_as_uint(Al[mr + g    ][k + tig    ]);
                al4[i][1] = __float_as_uint(Al[mr + g + 8][k + tig    ]);
                al4[i][2] = __float_as_uint(Al[mr + g    ][k + tig + 4]);
                al4[i][3] = __float_as_uint(Al[mr + g + 8][k + tig + 4]);
            }
            #pragma unroll
            for (int j = 0; j < 4; j++) {
                int n = wn * 32 + j * 8 + g;
                bh2[j][0] = __float_as_uint(Bh[k + tig    ][n]);
                bh2[j][1] = __float_as_uint(Bh[k + tig + 4][n]);
                bl2[j][0] = __float_as_uint(Bl[k + tig    ][n]);
                bl2[j][1] = __float_as_uint(Bl[k + tig + 4][n]);
            }
            #pragma unroll
            for (int i = 0; i < 4; i++)
                #pragma unroll
                for (int j = 0; j < 4; j++) {
                    mma_tf32(c[i][j], al4[i][0], al4[i][1], al4[i][2], al4[i][3], bh2[j][0], bh2[j][1]);
                    mma_tf32(c[i][j], ah4[i][0], ah4[i][1], ah4[i][2], ah4[i][3], bl2[j][0], bl2[j][1]);
                    mma_tf32(c[i][j], ah4[i][0], ah4[i][1], ah4[i][2], ah4[i][3], bh2[j][0], bh2[j][1]);
                }
        }
        __syncthreads();
    }
    float* dst = part + ((size_t)z * M + bm) * N + bn;
    #pragma unroll
    for (int i = 0; i < 4; i++)
        #pragma unroll
        for (int j = 0; j < 4; j++) {
            int row = wm * 64 + i * 16 + g, col = wn * 32 + j * 8 + tig * 2;
            dst[(size_t)row * N + col]       = c[i][j][0];
            dst[(size_t)row * N + col + 1]   = c[i][j][1];
            dst[(size_t)(row+8) * N + col]   = c[i][j][2];
            dst[(size_t)(row+8) * N + col+1] = c[i][j][3];
        }
}

template<int ACT>
__global__ void combine(const float* __restrict__ part, const float* __restrict__ bias,
                        float* __restrict__ out, int MN, int N, int S) {
    int i = blockIdx.x * 256 + threadIdx.x;
    if (i >= MN) return;
    float v = 0.f;
    for (int z = 0; z < S; z++) v += part[(size_t)z * MN + i];
    v += bias[i % N];
    if (ACT) v = v > 0.f ? v : 0.01f * v;
    out[i] = v;
}

// ---------------- small fp32 GEMM for the final 256x30 layer --------------------
__global__ void __launch_bounds__(256) gemm_last(const float* __restrict__ A,
                                                 const float* __restrict__ W,
                                                 const float* __restrict__ bias,
                                                 float* __restrict__ C) {
    int m = blockIdx.x;
    int tid = threadIdx.x;
    int col = tid % 30, seg = tid / 30;
    __shared__ float red[256];
    float v = 0.f;
    if (seg < 8) {
        const float* a = A + (size_t)m * 256 + seg * 32;
        const float* w = W + col;
        #pragma unroll
        for (int k = 0; k < 32; k++) v += a[k] * w[(size_t)(seg * 32 + k) * 30];
    }
    red[tid] = v;
    __syncthreads();
    if (tid < 30) {
        float acc = 0.f;
        #pragma unroll
        for (int s2 = 0; s2 < 8; s2++) acc += red[s2 * 30 + tid];
        C[(size_t)m * 30 + tid] = acc + bias[tid];
    }
}

// ---------------- launch ---------------------------------------------------------
extern "C" void kernel_launch(void* const* d_in, const int* in_sizes, int n_in,
                              void* d_out, int out_size) {
    const float* embeds    = (const float*)d_in[0];
    const int*   spans_raw = (const int*)d_in[1];
    const float* aw1       = (const float*)d_in[2];
    const float* ab1       = (const float*)d_in[3];
    const float* aw2       = (const float*)d_in[4];
    // d_in[5] = ab2 : uniform logit offset, softmax-invariant -> unused
    const float* width_emb = (const float*)d_in[6];
    const float* sw1 = (const float*)d_in[7];
    const float* sb1 = (const float*)d_in[8];
    const float* sw2 = (const float*)d_in[9];
    const float* sb2 = (const float*)d_in[10];
    const float* sw3 = (const float*)d_in[11];
    const float* sb3 = (const float*)d_in[12];
    const float* sw4 = (const float*)d_in[13];
    const float* sb4 = (const float*)d_in[14];
    float* out = (float*)d_out;

    float *x, *h1, *h2, *h3, *part, *sw1p;
    cudaGetSymbolAddress((void**)&x,    g_x);
    cudaGetSymbolAddress((void**)&h1,   g_h1);
    cudaGetSymbolAddress((void**)&h2,   g_h2);
    cudaGetSymbolAddress((void**)&h3,   g_h3);
    cudaGetSymbolAddress((void**)&part, g_part);
    cudaGetSymbolAddress((void**)&sw1p, g_sw1p);

    prep_sc<<<1, 256>>>(spans_raw);                                           // 1
    prep_all<<<dim3(1024, 22), 256>>>(embeds, aw1, ab1, aw2, sw1);            // 2
    attn_kernel<<<8192, 128, ATTN_SMEM>>>();                                  // 3
    sm_wsum<<<dim3(B_, 3), 256>>>(embeds, width_emb);                         // 4 <- profiled
    gemm_3x<<<dim3(8, 2, MLPS), 256>>>(x,  sw1p, part, 256, 1024, XPAD, MLPS);
    combine<1><<<(256 * 1024) / 256, 256>>>(part, sb1, h1, 256 * 1024, 1024, MLPS);
    gemm_3x<<<dim3(4, 2, MLPS), 256>>>(h1, sw2,  part, 256, 512, 1024, MLPS);
    combine<1><<<(256 * 512) / 256, 256>>>(part, sb2, h2, 256 * 512, 512, MLPS);
    gemm_3x<<<dim3(2, 2, MLPS), 256>>>(h2, sw3,  part, 256, 256, 512, MLPS);
    combine<1><<<(256 * 256) / 256, 256>>>(part, sb3, h3, 256 * 256, 256, MLPS);
    gemm_last<<<256, 256>>>(h3, sw4, sb4, out);
}

// round 14
// speedup vs baseline: 3.9762x; 1.1505x over previous
#include <cuda_runtime.h>
#include <cuda_fp16.h>
#include <cstdint>
#include <cstddef>

// Problem constants
#define B_ 256
#define L_ 512
#define D_ 768
#define H_ 1000
#define HP_ 1024
#define XDIM 2324
#define XPAD 2336

// attn tiling: block 128(M) x 128(N), K-chunks of 32 (2 x k16 MMA steps), 8 ncp passes
#define NKC 24             // 768/32
#define NCPN 8             // 1024 / 128
#define MAXT 1024          // max compacted tiles

// fp16 B tile image: per (kc,ncp): [ks(2)][tig(4)][n(132)][quad(4 halfs)] = 8448 B
#define BT_BYTES 8448
// fp16 A smem row: 32 halfs data + pad -> 80 B (banks 20g+tig -> conflict-free)
#define A_RSB 80

#define MLPS 16            // MLP K-split factor

// ---------------- scratch -------------------------------------------------------
__device__ int    g_spans[B_ * 2];
__device__ int    g_offs[B_];
__device__ int    g_ntiles;
__device__ int    g_pos[B_ * L_];
__device__ float  g_attns[B_ * L_];
__device__ float  g_ab1p[HP_];
__device__ float  g_aw2p[HP_];
__device__ unsigned char g_Bpk[NKC * NCPN * BT_BYTES];   // packed fp16 aw1 smem image
__device__ __half g_Ef16[MAXT * 128 * D_];               // compacted span rows, fp16
__device__ float  g_x [B_ * XPAD];
__device__ float  g_sw1p[XPAD * 1024];
__device__ float  g_part[MLPS * 256 * 1024];
__device__ float  g_h1[B_ * 1024];
__device__ float  g_h2[B_ * 512];
__device__ float  g_h3[B_ * 256];

__device__ __forceinline__ uint32_t f2tf(float x) {
    uint32_t r;
    asm("cvt.rna.tf32.f32 %0, %1;" : "=r"(r) : "f"(x));
    return r;
}
__device__ __forceinline__ float tfv(float x) { return __uint_as_float(f2tf(x)); }

__device__ __forceinline__ void cp16(void* smem_dst, const void* gsrc) {
    uint32_t s = (uint32_t)__cvta_generic_to_shared(smem_dst);
    asm volatile("cp.async.cg.shared.global [%0], [%1], 16;\n" :: "r"(s), "l"(gsrc));
}
#define CP_COMMIT asm volatile("cp.async.commit_group;\n" ::: "memory")
#define CP_WAIT0  asm volatile("cp.async.wait_group 0;\n" ::: "memory")

__device__ __forceinline__ void mma_tf32(float* c, uint32_t a0, uint32_t a1,
                                         uint32_t a2, uint32_t a3,
                                         uint32_t b0, uint32_t b1) {
    asm volatile(
        "mma.sync.aligned.m16n8k8.row.col.f32.tf32.tf32.f32 "
        "{%0,%1,%2,%3}, {%4,%5,%6,%7}, {%8,%9}, {%0,%1,%2,%3};\n"
        : "+f"(c[0]), "+f"(c[1]), "+f"(c[2]), "+f"(c[3])
        : "r"(a0), "r"(a1), "r"(a2), "r"(a3), "r"(b0), "r"(b1));
}

__device__ __forceinline__ void mma_f16(float* c, uint32_t a0, uint32_t a1,
                                        uint32_t a2, uint32_t a3,
                                        uint32_t b0, uint32_t b1) {
    asm volatile(
        "mma.sync.aligned.m16n8k16.row.col.f32.f16.f16.f32 "
        "{%0,%1,%2,%3}, {%4,%5,%6,%7}, {%8,%9}, {%0,%1,%2,%3};\n"
        : "+f"(c[0]), "+f"(c[1]), "+f"(c[2]), "+f"(c[3])
        : "r"(a0), "r"(a1), "r"(a2), "r"(a3), "r"(b0), "r"(b1));
}

// ---------------- fused spans normalize + compaction ----------------------------
__global__ void prep_sc(const int* __restrict__ sp) {
    __shared__ int offs[257];
    int t = threadIdx.x;
    int odd = sp[2 * t + 1];
    int any_odd = __syncthreads_or(odd != 0);
    int s, e;
    if (any_odd) { s = sp[2 * t]; e = sp[2 * t + 1]; }
    else         { s = sp[4 * t]; e = sp[4 * t + 2]; }
    g_spans[2 * t] = s; g_spans[2 * t + 1] = e;
    int w = e - s + 1;
    offs[t + 1] = w;
    if (t == 0) offs[0] = 0;
    __syncthreads();
    if (t == 0) {
        for (int i = 1; i <= 256; i++) offs[i] += offs[i - 1];
        g_ntiles = (offs[256] + 127) >> 7;
    }
    __syncthreads();
    int base = offs[t];
    g_offs[t] = base;
    for (int k = 0; k < w; k++) g_pos[base + k] = (t << 16) | (s + k);
    int total = offs[256], NT = (total + 127) >> 7;
    for (int idx = total + t; idx < NT * 128; idx += 256) g_pos[idx] = (int)0x80000000;
}

// fused prep: y<8 -> compacted rows to fp16; y in [8,12) -> aw1 fp16 pack (coalesced)
// + zero attns + zero g_x + pad ab1/aw2; y in [12,22) -> sw1 padded copy.
__global__ void prep_all(const float* __restrict__ E, const float* __restrict__ aw1,
                         const float* __restrict__ ab1, const float* __restrict__ aw2,
                         const float* __restrict__ sw1) {
    int tid = threadIdx.x;
    if (blockIdx.y < 8) {
        int tile = blockIdx.x;
        if (tile >= g_ntiles) return;
        int row = blockIdx.y * 16 + (tid >> 4);
        int l16 = tid & 15;
        int p = g_pos[tile * 128 + row];
        uint2* dst = (uint2*)(g_Ef16 + ((size_t)(tile * 128 + row)) * D_ + l16 * 48);
        if (p < 0) {
            uint2 z = make_uint2(0u, 0u);
            #pragma unroll
            for (int q = 0; q < 12; q++) dst[q] = z;
        } else {
            const float* src = E + ((size_t)((p >> 16) & 0x7FFF) * L_ + (p & 0xFFFF)) * D_ + l16 * 48;
            #pragma unroll
            for (int q = 0; q < 12; q++) {
                float4 v = ((const float4*)src)[q];
                __half2 h0 = __floats2half2_rn(v.x, v.y);
                __half2 h1 = __floats2half2_rn(v.z, v.w);
                dst[q] = make_uint2(*(uint32_t*)&h0, *(uint32_t*)&h1);
            }
        }
        return;
    }
    if (blockIdx.y < 12) {
        int lin = ((blockIdx.y - 8) * 1024 + blockIdx.x) * 256 + tid;
        if (lin < B_ * L_) g_attns[lin] = 0.f;
        if (lin < B_ * XPAD) g_x[lin] = 0.f;
        if (lin < HP_) {
            g_ab1p[lin] = (lin < H_) ? ab1[lin] : 0.f;
            g_aw2p[lin] = (lin < H_) ? aw2[lin] : 0.f;
        }
        if (lin >= NKC * NCPN * (BT_BYTES / 2)) return;
        int tile = lin / (BT_BYTES / 2), within = lin % (BT_BYTES / 2);
        int kc = tile >> 3, ncp = tile & 7;
        int n  = within % 132;
        int t4 = within / 132;
        int c  = t4 & 3;
        int t5 = t4 >> 2;
        int tg = t5 & 3;
        int ks = t5 >> 2;
        float v = 0.f;
        if (n < 128) {
            int col = ncp * 128 + n;
            if (col < H_) {
                int k = kc * 32 + ks * 16 + 2 * tg + (c & 1) + ((c >> 1) << 3);
                v = aw1[(size_t)k * H_ + col];
            }
        }
        __half h = __float2half_rn(v);
        *(unsigned short*)(g_Bpk + (size_t)tile * BT_BYTES + ks * 4224 + tg * 1056 + n * 8 + c * 2)
            = *(unsigned short*)&h;
        return;
    }
    size_t i = ((size_t)(blockIdx.y - 12) * 1024 + blockIdx.x) * 256 + tid;
    if (i < (size_t)XPAD * 1024) {
        int r = (int)(i >> 10), c2 = (int)(i & 1023);
        g_sw1p[i] = (r < XDIM) ? sw1[(size_t)r * 1024 + c2] : 0.f;
    }
}

// ---------------- attn: 4 warps 64x64, fp16 m16n8k16, 2 CTAs/SM -----------------
#define ATTN_SMEM (37376 + 512)

__global__ void __launch_bounds__(128, 2) attn_kernel() {
    int unit = blockIdx.x;
    int tile = unit >> 3, ncp = unit & 7;
    if (tile >= g_ntiles) return;

    extern __shared__ char smc[];
    char* Abuf[2] = { smc, smc + 10240 };
    char* Bbuf[2] = { smc + 20480, smc + 28928 };
    int* pos = (int*)(smc + 37376);

    int tid = threadIdx.x;
    int warp = tid >> 5, lane = tid & 31, g = lane >> 2, tig = lane & 3;
    int wm = warp >> 1, wn = warp & 1;

    pos[tid] = g_pos[tile * 128 + tid];
    const __half* asrc = g_Ef16 + (size_t)tile * 128 * D_ + (size_t)tid * D_;
    const unsigned char* bbase = g_Bpk + (size_t)ncp * BT_BYTES;

    float c[4][8][4] = {};

    {
        const unsigned char* sB = bbase;
        #pragma unroll
        for (int k2 = 0; k2 < 5; k2++) {
            int i = tid + k2 * 128;
            if (i < 528) cp16(Bbuf[0] + i * 16, sB + i * 16);
        }
        #pragma unroll
        for (int q = 0; q < 4; q++) cp16(Abuf[0] + tid * A_RSB + q * 16, asrc + q * 8);
        CP_COMMIT;
        CP_WAIT0;
        __syncthreads();
    }

    for (int kc = 0; kc < NKC; kc++) {
        int cur = kc & 1, nxt = cur ^ 1;
        if (kc < NKC - 1) {
            const unsigned char* sB = bbase + (size_t)(kc + 1) * NCPN * BT_BYTES;
            #pragma unroll
            for (int k2 = 0; k2 < 5; k2++) {
                int i = tid + k2 * 128;
                if (i < 528) cp16(Bbuf[nxt] + i * 16, sB + i * 16);
            }
            const __half* sA = asrc + (kc + 1) * 32;
            #pragma unroll
            for (int q = 0; q < 4; q++) cp16(Abuf[nxt] + tid * A_RSB + q * 16, sA + q * 8);
            CP_COMMIT;
        }
        const char* Ac = Abuf[cur];
        const char* Bc = Bbuf[cur];
        #pragma unroll
        for (int ks = 0; ks < 2; ks++) {
            uint32_t a[4][4];
            uint2 b[8];
            #pragma unroll
            for (int i = 0; i < 4; i++) {
                const char* pa = Ac + (wm * 64 + i * 16 + g) * A_RSB + ks * 32 + tig * 4;
                a[i][0] = *(const uint32_t*)pa;
                a[i][2] = *(const uint32_t*)(pa + 16);
                a[i][1] = *(const uint32_t*)(pa + 8 * A_RSB);
                a[i][3] = *(const uint32_t*)(pa + 8 * A_RSB + 16);
            }
            #pragma unroll
            for (int j = 0; j < 8; j++) {
                int n = wn * 64 + j * 8 + g;
                b[j] = *(const uint2*)(Bc + ks * 4224 + tig * 1056 + n * 8);
            }
            #pragma unroll
            for (int i = 0; i < 4; i++)
                #pragma unroll
                for (int j = 0; j < 8; j++)
                    mma_f16(c[i][j], a[i][0], a[i][1], a[i][2], a[i][3], b[j].x, b[j].y);
        }
        if (kc < NKC - 1) CP_WAIT0;
        __syncthreads();
    }

    int n0 = ncp * 128;
    #pragma unroll
    for (int i = 0; i < 4; i++) {
        float ra = 0.f, rb = 0.f;
        #pragma unroll
        for (int j = 0; j < 8; j++) {
            int col0 = n0 + wn * 64 + j * 8 + tig * 2;
            float b1a = g_ab1p[col0], b1b = g_ab1p[col0 + 1];
            float w2a = g_aw2p[col0], w2b = g_aw2p[col0 + 1];
            float z;
            z = c[i][j][0] + b1a; ra += (z > 0.f ? z : 0.01f * z) * w2a;
            z = c[i][j][1] + b1b; ra += (z > 0.f ? z : 0.01f * z) * w2b;
            z = c[i][j][2] + b1a; rb += (z > 0.f ? z : 0.01f * z) * w2a;
            z = c[i][j][3] + b1b; rb += (z > 0.f ? z : 0.01f * z) * w2b;
        }
        ra += __shfl_xor_sync(0xffffffffu, ra, 1);
        ra += __shfl_xor_sync(0xffffffffu, ra, 2);
        rb += __shfl_xor_sync(0xffffffffu, rb, 1);
        rb += __shfl_xor_sync(0xffffffffu, rb, 2);
        if (tig == 0) {
            int r0 = wm * 64 + i * 16 + g;
            int p0 = pos[r0], p1 = pos[r0 + 8];
            if (p0 >= 0) atomicAdd(&g_attns[((p0 >> 16) & 0x7FFF) * L_ + (p0 & 0xFFFF)], ra);
            if (p1 >= 0) atomicAdd(&g_attns[((p1 >> 16) & 0x7FFF) * L_ + (p1 & 0xFFFF)], rb);
        }
    }
}

// ---------------- softmax + weighted sum over compacted fp16 rows ---------------
// grid (B_, 4), 384 threads: each block recomputes the span softmax (cheap), then
// weighted-sums a quarter of the span over all 768 dims (2 per thread, half2),
// atomicAdd into zero-initialized g_x. z==0 block also writes se/width_emb.
__global__ void __launch_bounds__(384) sm_wsum(const float* __restrict__ E,
                                               const float* __restrict__ width_emb) {
    int b = blockIdx.x, z = blockIdx.y;
    int tid = threadIdx.x;
    int s = g_spans[b * 2], e = g_spans[b * 2 + 1];
    int width = e - s + 1;

    __shared__ float ws[L_];
    __shared__ float red[384];

    float lm = -1e30f;
    for (int l = s + tid; l <= e; l += 384) lm = fmaxf(lm, g_attns[b * L_ + l]);
    red[tid] = lm; __syncthreads();
    for (int st = 192; st > 3; st >>= 1) {
        if (tid < st) red[tid] = fmaxf(red[tid], red[tid + st]);
        __syncthreads();
    }
    if (tid == 0) {
        float m2 = red[0];
        #pragma unroll
        for (int q = 1; q < 6; q++) m2 = fmaxf(m2, red[q]);
        red[0] = m2;
    }
    __syncthreads();
    float mx = red[0];
    __syncthreads();
    float ls = 0.f;
    for (int l = s + tid; l <= e; l += 384) {
        float ev = __expf(g_attns[b * L_ + l] - mx);
        ws[l - s] = ev;
        ls += ev;
    }
    red[tid] = ls; __syncthreads();
    for (int st = 192; st > 3; st >>= 1) {
        if (tid < st) red[tid] += red[tid + st];
        __syncthreads();
    }
    if (tid == 0) {
        float s2 = red[0];
        #pragma unroll
        for (int q = 1; q < 6; q++) s2 += red[q];
        red[0] = s2;
    }
    __syncthreads();
    float inv = 1.f / red[0];

    float* xb = g_x + (size_t)b * XPAD;

    // weighted sum: this block handles span quarter [l0,l1) x all 768 dims
    int l0 = (width * z) >> 2, l1 = (width * (z + 1)) >> 2;
    const __half2* base = (const __half2*)(g_Ef16 + (size_t)(g_offs[b] + l0) * D_) + tid;
    float a0 = 0.f, a1 = 0.f;
    for (int l = l0; l < l1; l++) {
        float wv = ws[l];
        float2 f = __half22float2(*base);
        base += D_ / 2;
        a0 += wv * f.x;
        a1 += wv * f.y;
    }
    atomicAdd(&xb[1536 + 2 * tid],     a0 * inv);
    atomicAdd(&xb[1536 + 2 * tid + 1], a1 * inv);

    if (z == 0) {
        const float* Ebase = E + (size_t)b * L_ * D_;
        const float* rs = Ebase + (size_t)s * D_;
        const float* re = Ebase + (size_t)e * D_;
        for (int dd = tid; dd < D_; dd += 384) { xb[dd] = rs[dd]; xb[D_ + dd] = re[dd]; }
        if (tid < 20) {
            const int bins[15] = {1,2,3,4,5,6,7,8,12,16,20,24,32,64,128};
            int idx = 0;
            #pragma unroll
            for (int j = 0; j < 15; j++) idx += (width > bins[j]) ? 1 : 0;
            xb[2304 + tid] = width_emb[idx * 20 + tid];
        }
        // pad region [XDIM, XPAD) already zeroed by prep_all
    }
}

// ---------------- 3xTF32 GEMM with K-split partials -----------------------------
__global__ void __launch_bounds__(256) gemm_3x(const float* __restrict__ A,
                                               const float* __restrict__ Bw,
                                               float* __restrict__ part,
                                               int M, int N, int K, int S) {
    __shared__ float Ah[128][20], Al[128][20];
    __shared__ float Bh[16][136], Bl[16][136];
    int tid = threadIdx.x, warp = tid >> 5, lane = tid & 31, g = lane >> 2, tig = lane & 3;
    int wm = warp >> 2, wn = warp & 3;
    int bm = blockIdx.y * 128, bn = blockIdx.x * 128;
    int nch = K >> 4;
    int z = blockIdx.z;
    int c0 = (int)((long)nch * z / S), c1 = (int)((long)nch * (z + 1) / S);

    float c[4][4][4] = {};
    for (int ch = c0; ch < c1; ch++) {
        int k0 = ch * 16;
        {
            int r = tid >> 1, h = (tid & 1) * 8;
            const float* src = A + (size_t)(bm + r) * K + k0 + h;
            float4 v0 = *(const float4*)src, v1 = *(const float4*)(src + 4);
            float vv[8] = {v0.x, v0.y, v0.z, v0.w, v1.x, v1.y, v1.z, v1.w};
            #pragma unroll
            for (int q = 0; q < 8; q++) {
                float hi = tfv(vv[q]);
                Ah[r][h + q] = hi;
                Al[r][h + q] = tfv(vv[q] - hi);
            }
        }
        {
            int r = tid >> 4, cb = (tid & 15) * 8;
            const float* src = Bw + (size_t)(k0 + r) * N + bn + cb;
            float4 v0 = *(const float4*)src, v1 = *(const float4*)(src + 4);
            float vv[8] = {v0.x, v0.y, v0.z, v0.w, v1.x, v1.y, v1.z, v1.w};
            #pragma unroll
            for (int q = 0; q < 8; q++) {
                float hi = tfv(vv[q]);
                Bh[r][cb + q] = hi;
                Bl[r][cb + q] = tfv(vv[q] - hi);
            }
        }
        __syncthreads();
        #pragma unroll
        for (int ks = 0; ks < 2; ks++) {
            int k = ks * 8;
            uint32_t ah4[4][4], al4[4][4], bh2[4][2], bl2[4][2];
            #pragma unroll
            for (int i = 0; i < 4; i++) {
                int mr = wm * 64 + i * 16;
                ah4[i][0] = __float_as_uint(Ah[mr + g    ][k + tig    ]);
                ah4[i][1] = __float_as_uint(Ah[mr + g + 8][k + tig    ]);
                ah4[i][2] = __float_as_uint(Ah[mr + g    ][k + tig + 4]);
                ah4[i][3] = __float_as_uint(Ah[mr + g + 8][k + tig + 4]);
                al4[i][0] = __float_as_uint(Al[mr + g    ][k + tig    ]);
                al4[i][1] = __float_as_uint(Al[mr + g + 8][k + tig    ]);
                al4[i][2] = __float_as_uint(Al[mr + g    ][k + tig + 4]);
                al4[i][3] = __float_as_uint(Al[mr + g + 8][k + tig + 4]);
            }
            #pragma unroll
            for (int j = 0; j < 4; j++) {
                int n = wn * 32 + j * 8 + g;
                bh2[j][0] = __float_as_uint(Bh[k + tig    ][n]);
                bh2[j][1] = __float_as_uint(Bh[k + tig + 4][n]);
                bl2[j][0] = __float_as_uint(Bl[k + tig    ][n]);
                bl2[j][1] = __float_as_uint(Bl[k + tig + 4][n]);
            }
            #pragma unroll
            for (int i = 0; i < 4; i++)
                #pragma unroll
                for (int j = 0; j < 4; j++) {
                    mma_tf32(c[i][j], al4[i][0], al4[i][1], al4[i][2], al4[i][3], bh2[j][0], bh2[j][1]);
                    mma_tf32(c[i][j], ah4[i][0], ah4[i][1], ah4[i][2], ah4[i][3], bl2[j][0], bl2[j][1]);
                    mma_tf32(c[i][j], ah4[i][0], ah4[i][1], ah4[i][2], ah4[i][3], bh2[j][0], bh2[j][1]);
                }
        }
        __syncthreads();
    }
    float* dst = part + ((size_t)z * M + bm) * N + bn;
    #pragma unroll
    for (int i = 0; i < 4; i++)
        #pragma unroll
        for (int j = 0; j < 4; j++) {
            int row = wm * 64 + i * 16 + g, col = wn * 32 + j * 8 + tig * 2;
            dst[(size_t)row * N + col]       = c[i][j][0];
            dst[(size_t)row * N + col + 1]   = c[i][j][1];
            dst[(size_t)(row+8) * N + col]   = c[i][j][2];
            dst[(size_t)(row+8) * N + col+1] = c[i][j][3];
        }
}

template<int ACT>
__global__ void combine(const float* __restrict__ part, const float* __restrict__ bias,
                        float* __restrict__ out, int MN, int N, int S) {
    int i = blockIdx.x * 256 + threadIdx.x;
    if (i >= MN) return;
    float v = 0.f;
    for (int z = 0; z < S; z++) v += part[(size_t)z * MN + i];
    v += bias[i % N];
    if (ACT) v = v > 0.f ? v : 0.01f * v;
    out[i] = v;
}

// ---------------- small fp32 GEMM for the final 256x30 layer --------------------
__global__ void __launch_bounds__(256) gemm_last(const float* __restrict__ A,
                                                 const float* __restrict__ W,
                                                 const float* __restrict__ bias,
                                                 float* __restrict__ C) {
    int m = blockIdx.x;
    int tid = threadIdx.x;
    int col = tid % 30, seg = tid / 30;
    __shared__ float red[256];
    float v = 0.f;
    if (seg < 8) {
        const float* a = A + (size_t)m * 256 + seg * 32;
        const float* w = W + col;
        #pragma unroll
        for (int k = 0; k < 32; k++) v += a[k] * w[(size_t)(seg * 32 + k) * 30];
    }
    red[tid] = v;
    __syncthreads();
    if (tid < 30) {
        float acc = 0.f;
        #pragma unroll
        for (int s2 = 0; s2 < 8; s2++) acc += red[s2 * 30 + tid];
        C[(size_t)m * 30 + tid] = acc + bias[tid];
    }
}

// ---------------- launch ---------------------------------------------------------
extern "C" void kernel_launch(void* const* d_in, const int* in_sizes, int n_in,
                              void* d_out, int out_size) {
    const float* embeds    = (const float*)d_in[0];
    const int*   spans_raw = (const int*)d_in[1];
    const float* aw1       = (const float*)d_in[2];
    const float* ab1       = (const float*)d_in[3];
    const float* aw2       = (const float*)d_in[4];
    // d_in[5] = ab2 : uniform logit offset, softmax-invariant -> unused
    const float* width_emb = (const float*)d_in[6];
    const float* sw1 = (const float*)d_in[7];
    const float* sb1 = (const float*)d_in[8];
    const float* sw2 = (const float*)d_in[9];
    const float* sb2 = (const float*)d_in[10];
    const float* sw3 = (const float*)d_in[11];
    const float* sb3 = (const float*)d_in[12];
    const float* sw4 = (const float*)d_in[13];
    const float* sb4 = (const float*)d_in[14];
    float* out = (float*)d_out;

    float *x, *h1, *h2, *h3, *part, *sw1p;
    cudaGetSymbolAddress((void**)&x,    g_x);
    cudaGetSymbolAddress((void**)&h1,   g_h1);
    cudaGetSymbolAddress((void**)&h2,   g_h2);
    cudaGetSymbolAddress((void**)&h3,   g_h3);
    cudaGetSymbolAddress((void**)&part, g_part);
    cudaGetSymbolAddress((void**)&sw1p, g_sw1p);

    prep_sc<<<1, 256>>>(spans_raw);                                           // 1
    prep_all<<<dim3(1024, 22), 256>>>(embeds, aw1, ab1, aw2, sw1);            // 2
    attn_kernel<<<8192, 128, ATTN_SMEM>>>();                                  // 3
    sm_wsum<<<dim3(B_, 4), 384>>>(embeds, width_emb);                         // 4 <- profiled
    gemm_3x<<<dim3(8, 2, MLPS), 256>>>(x,  sw1p, part, 256, 1024, XPAD, MLPS);
    combine<1><<<(256 * 1024) / 256, 256>>>(part, sb1, h1, 256 * 1024, 1024, MLPS);
    gemm_3x<<<dim3(4, 2, MLPS), 256>>>(h1, sw2,  part, 256, 512, 1024, MLPS);
    combine<1><<<(256 * 512) / 256, 256>>>(part, sb2, h2, 256 * 512, 512, MLPS);
    gemm_3x<<<dim3(2, 2, MLPS), 256>>>(h2, sw3,  part, 256, 256, 512, MLPS);
    combine<1><<<(256 * 256) / 256, 256>>>(part, sb3, h3, 256 * 256, 256, MLPS);
    gemm_last<<<256, 256>>>(h3, sw4, sb4, out);
}

// round 15
// speedup vs baseline: 4.4946x; 1.1304x over previous
#include <cuda_runtime.h>
#include <cuda_fp16.h>
#include <cstdint>
#include <cstddef>

// Problem constants
#define B_ 256
#define L_ 512
#define D_ 768
#define H_ 1000
#define HP_ 1024
#define XDIM 2324
#define XPAD 2336

// attn tiling: block 128(M) x 128(N), K-chunks of 32 (2 x k16 MMA steps), 8 ncp passes
#define NKC 24             // 768/32
#define NCPN 8             // 1024 / 128
#define MAXT 1024          // max compacted tiles

// fp16 B tile image: per (kc,ncp): [ks(2)][tig(4)][n(132)][quad(4 halfs)] = 8448 B
#define BT_BYTES 8448
// fp16 A smem row: 32 halfs data + pad -> 80 B (banks 20g+tig -> conflict-free)
#define A_RSB 80

#define MLPS 16            // MLP K-split factor

// ---------------- scratch -------------------------------------------------------
__device__ int    g_spans[B_ * 2];
__device__ int    g_offs[B_];
__device__ int    g_ntiles;
__device__ int    g_pos[B_ * L_];
__device__ float  g_attns[B_ * L_];
__device__ float  g_ab1p[HP_];
__device__ float  g_aw2p[HP_];
__device__ unsigned char g_Bpk[NKC * NCPN * BT_BYTES];   // packed fp16 aw1 smem image
__device__ __half g_Ef16[MAXT * 128 * D_];               // compacted span rows, fp16
__device__ float  g_x [B_ * XPAD];
__device__ float  g_sw1p[XPAD * 1024];
__device__ float  g_part[MLPS * 256 * 1024];
__device__ float  g_h1[B_ * 1024];
__device__ float  g_h2[B_ * 512];
__device__ float  g_h3[B_ * 256];

__device__ __forceinline__ void cp16(void* smem_dst, const void* gsrc) {
    uint32_t s = (uint32_t)__cvta_generic_to_shared(smem_dst);
    asm volatile("cp.async.cg.shared.global [%0], [%1], 16;\n" :: "r"(s), "l"(gsrc));
}
#define CP_COMMIT asm volatile("cp.async.commit_group;\n" ::: "memory")
#define CP_WAIT0  asm volatile("cp.async.wait_group 0;\n" ::: "memory")

__device__ __forceinline__ void mma_f16(float* c, uint32_t a0, uint32_t a1,
                                        uint32_t a2, uint32_t a3,
                                        uint32_t b0, uint32_t b1) {
    asm volatile(
        "mma.sync.aligned.m16n8k16.row.col.f32.f16.f16.f32 "
        "{%0,%1,%2,%3}, {%4,%5,%6,%7}, {%8,%9}, {%0,%1,%2,%3};\n"
        : "+f"(c[0]), "+f"(c[1]), "+f"(c[2]), "+f"(c[3])
        : "r"(a0), "r"(a1), "r"(a2), "r"(a3), "r"(b0), "r"(b1));
}

// split one float into (hi, lo) fp16 pair
__device__ __forceinline__ void h_split(float x, __half& hi, __half& lo) {
    hi = __float2half_rn(x);
    lo = __float2half_rn(x - __half2float(hi));
}

// ---------------- fused spans normalize + compaction ----------------------------
__global__ void prep_sc(const int* __restrict__ sp) {
    __shared__ int offs[257];
    int t = threadIdx.x;
    int odd = sp[2 * t + 1];
    int any_odd = __syncthreads_or(odd != 0);
    int s, e;
    if (any_odd) { s = sp[2 * t]; e = sp[2 * t + 1]; }
    else         { s = sp[4 * t]; e = sp[4 * t + 2]; }
    g_spans[2 * t] = s; g_spans[2 * t + 1] = e;
    int w = e - s + 1;
    offs[t + 1] = w;
    if (t == 0) offs[0] = 0;
    __syncthreads();
    if (t == 0) {
        for (int i = 1; i <= 256; i++) offs[i] += offs[i - 1];
        g_ntiles = (offs[256] + 127) >> 7;
    }
    __syncthreads();
    int base = offs[t];
    g_offs[t] = base;
    for (int k = 0; k < w; k++) g_pos[base + k] = (t << 16) | (s + k);
    int total = offs[256], NT = (total + 127) >> 7;
    for (int idx = total + t; idx < NT * 128; idx += 256) g_pos[idx] = (int)0x80000000;
}

// fused prep: y<8 -> compacted rows to fp16 (coalesced); y in [8,12) -> aw1 fp16
// pack + zero attns + zero g_x + pad ab1/aw2; y in [12,22) -> sw1 padded copy.
__global__ void prep_all(const float* __restrict__ E, const float* __restrict__ aw1,
                         const float* __restrict__ ab1, const float* __restrict__ aw2,
                         const float* __restrict__ sw1) {
    int tid = threadIdx.x;
    if (blockIdx.y < 8) {
        int tile = blockIdx.x;
        if (tile >= g_ntiles) return;
        int row = blockIdx.y * 16 + (tid >> 4);
        int l16 = tid & 15;
        int p = g_pos[tile * 128 + row];
        uint2* dst = (uint2*)(g_Ef16 + ((size_t)(tile * 128 + row)) * D_);
        if (p < 0) {
            uint2 z = make_uint2(0u, 0u);
            #pragma unroll
            for (int q = 0; q < 12; q++) dst[q * 16 + l16] = z;
        } else {
            const float4* src = (const float4*)(E + ((size_t)((p >> 16) & 0x7FFF) * L_ + (p & 0xFFFF)) * D_);
            #pragma unroll
            for (int q = 0; q < 12; q++) {
                int f = q * 16 + l16;          // coalesced: warp covers 16 consecutive float4
                float4 v = src[f];
                __half2 h0 = __floats2half2_rn(v.x, v.y);
                __half2 h1 = __floats2half2_rn(v.z, v.w);
                dst[f] = make_uint2(*(uint32_t*)&h0, *(uint32_t*)&h1);
            }
        }
        return;
    }
    if (blockIdx.y < 12) {
        int lin = ((blockIdx.y - 8) * 1024 + blockIdx.x) * 256 + tid;
        if (lin < B_ * L_) g_attns[lin] = 0.f;
        if (lin < B_ * XPAD) g_x[lin] = 0.f;
        if (lin < HP_) {
            g_ab1p[lin] = (lin < H_) ? ab1[lin] : 0.f;
            g_aw2p[lin] = (lin < H_) ? aw2[lin] : 0.f;
        }
        if (lin >= NKC * NCPN * (BT_BYTES / 2)) return;
        int tile = lin / (BT_BYTES / 2), within = lin % (BT_BYTES / 2);
        int kc = tile >> 3, ncp = tile & 7;
        int n  = within % 132;
        int t4 = within / 132;
        int c  = t4 & 3;
        int t5 = t4 >> 2;
        int tg = t5 & 3;
        int ks = t5 >> 2;
        float v = 0.f;
        if (n < 128) {
            int col = ncp * 128 + n;
            if (col < H_) {
                int k = kc * 32 + ks * 16 + 2 * tg + (c & 1) + ((c >> 1) << 3);
                v = aw1[(size_t)k * H_ + col];
            }
        }
        __half h = __float2half_rn(v);
        *(unsigned short*)(g_Bpk + (size_t)tile * BT_BYTES + ks * 4224 + tg * 1056 + n * 8 + c * 2)
            = *(unsigned short*)&h;
        return;
    }
    size_t i = ((size_t)(blockIdx.y - 12) * 1024 + blockIdx.x) * 256 + tid;
    if (i < (size_t)XPAD * 1024) {
        int r = (int)(i >> 10), c2 = (int)(i & 1023);
        g_sw1p[i] = (r < XDIM) ? sw1[(size_t)r * 1024 + c2] : 0.f;
    }
}

// ---------------- attn: 4 warps 64x64, fp16 m16n8k16, 2 CTAs/SM -----------------
#define ATTN_SMEM (37376 + 512)

__global__ void __launch_bounds__(128, 2) attn_kernel() {
    int unit = blockIdx.x;
    int tile = unit >> 3, ncp = unit & 7;
    if (tile >= g_ntiles) return;

    extern __shared__ char smc[];
    char* Abuf[2] = { smc, smc + 10240 };
    char* Bbuf[2] = { smc + 20480, smc + 28928 };
    int* pos = (int*)(smc + 37376);

    int tid = threadIdx.x;
    int warp = tid >> 5, lane = tid & 31, g = lane >> 2, tig = lane & 3;
    int wm = warp >> 1, wn = warp & 1;

    pos[tid] = g_pos[tile * 128 + tid];
    const __half* asrc = g_Ef16 + (size_t)tile * 128 * D_ + (size_t)tid * D_;
    const unsigned char* bbase = g_Bpk + (size_t)ncp * BT_BYTES;

    float c[4][8][4] = {};

    {
        const unsigned char* sB = bbase;
        #pragma unroll
        for (int k2 = 0; k2 < 5; k2++) {
            int i = tid + k2 * 128;
            if (i < 528) cp16(Bbuf[0] + i * 16, sB + i * 16);
        }
        #pragma unroll
        for (int q = 0; q < 4; q++) cp16(Abuf[0] + tid * A_RSB + q * 16, asrc + q * 8);
        CP_COMMIT;
        CP_WAIT0;
        __syncthreads();
    }

    for (int kc = 0; kc < NKC; kc++) {
        int cur = kc & 1, nxt = cur ^ 1;
        if (kc < NKC - 1) {
            const unsigned char* sB = bbase + (size_t)(kc + 1) * NCPN * BT_BYTES;
            #pragma unroll
            for (int k2 = 0; k2 < 5; k2++) {
                int i = tid + k2 * 128;
                if (i < 528) cp16(Bbuf[nxt] + i * 16, sB + i * 16);
            }
            const __half* sA = asrc + (kc + 1) * 32;
            #pragma unroll
            for (int q = 0; q < 4; q++) cp16(Abuf[nxt] + tid * A_RSB + q * 16, sA + q * 8);
            CP_COMMIT;
        }
        const char* Ac = Abuf[cur];
        const char* Bc = Bbuf[cur];
        #pragma unroll
        for (int ks = 0; ks < 2; ks++) {
            uint32_t a[4][4];
            uint2 b[8];
            #pragma unroll
            for (int i = 0; i < 4; i++) {
                const char* pa = Ac + (wm * 64 + i * 16 + g) * A_RSB + ks * 32 + tig * 4;
                a[i][0] = *(const uint32_t*)pa;
                a[i][2] = *(const uint32_t*)(pa + 16);
                a[i][1] = *(const uint32_t*)(pa + 8 * A_RSB);
                a[i][3] = *(const uint32_t*)(pa + 8 * A_RSB + 16);
            }
            #pragma unroll
            for (int j = 0; j < 8; j++) {
                int n = wn * 64 + j * 8 + g;
                b[j] = *(const uint2*)(Bc + ks * 4224 + tig * 1056 + n * 8);
            }
            #pragma unroll
            for (int i = 0; i < 4; i++)
                #pragma unroll
                for (int j = 0; j < 8; j++)
                    mma_f16(c[i][j], a[i][0], a[i][1], a[i][2], a[i][3], b[j].x, b[j].y);
        }
        if (kc < NKC - 1) CP_WAIT0;
        __syncthreads();
    }

    int n0 = ncp * 128;
    #pragma unroll
    for (int i = 0; i < 4; i++) {
        float ra = 0.f, rb = 0.f;
        #pragma unroll
        for (int j = 0; j < 8; j++) {
            int col0 = n0 + wn * 64 + j * 8 + tig * 2;
            float b1a = g_ab1p[col0], b1b = g_ab1p[col0 + 1];
            float w2a = g_aw2p[col0], w2b = g_aw2p[col0 + 1];
            float z;
            z = c[i][j][0] + b1a; ra += (z > 0.f ? z : 0.01f * z) * w2a;
            z = c[i][j][1] + b1b; ra += (z > 0.f ? z : 0.01f * z) * w2b;
            z = c[i][j][2] + b1a; rb += (z > 0.f ? z : 0.01f * z) * w2a;
            z = c[i][j][3] + b1b; rb += (z > 0.f ? z : 0.01f * z) * w2b;
        }
        ra += __shfl_xor_sync(0xffffffffu, ra, 1);
        ra += __shfl_xor_sync(0xffffffffu, ra, 2);
        rb += __shfl_xor_sync(0xffffffffu, rb, 1);
        rb += __shfl_xor_sync(0xffffffffu, rb, 2);
        if (tig == 0) {
            int r0 = wm * 64 + i * 16 + g;
            int p0 = pos[r0], p1 = pos[r0 + 8];
            if (p0 >= 0) atomicAdd(&g_attns[((p0 >> 16) & 0x7FFF) * L_ + (p0 & 0xFFFF)], ra);
            if (p1 >= 0) atomicAdd(&g_attns[((p1 >> 16) & 0x7FFF) * L_ + (p1 & 0xFFFF)], rb);
        }
    }
}

// ---------------- softmax + weighted sum over compacted fp16 rows ---------------
__global__ void __launch_bounds__(384) sm_wsum(const float* __restrict__ E,
                                               const float* __restrict__ width_emb) {
    int b = blockIdx.x, z = blockIdx.y;
    int tid = threadIdx.x;
    int s = g_spans[b * 2], e = g_spans[b * 2 + 1];
    int width = e - s + 1;

    __shared__ float ws[L_];
    __shared__ float red[384];

    float lm = -1e30f;
    for (int l = s + tid; l <= e; l += 384) lm = fmaxf(lm, g_attns[b * L_ + l]);
    red[tid] = lm; __syncthreads();
    for (int st = 192; st > 3; st >>= 1) {
        if (tid < st) red[tid] = fmaxf(red[tid], red[tid + st]);
        __syncthreads();
    }
    if (tid == 0) {
        float m2 = red[0];
        #pragma unroll
        for (int q = 1; q < 6; q++) m2 = fmaxf(m2, red[q]);
        red[0] = m2;
    }
    __syncthreads();
    float mx = red[0];
    __syncthreads();
    float ls = 0.f;
    for (int l = s + tid; l <= e; l += 384) {
        float ev = __expf(g_attns[b * L_ + l] - mx);
        ws[l - s] = ev;
        ls += ev;
    }
    red[tid] = ls; __syncthreads();
    for (int st = 192; st > 3; st >>= 1) {
        if (tid < st) red[tid] += red[tid + st];
        __syncthreads();
    }
    if (tid == 0) {
        float s2 = red[0];
        #pragma unroll
        for (int q = 1; q < 6; q++) s2 += red[q];
        red[0] = s2;
    }
    __syncthreads();
    float inv = 1.f / red[0];

    float* xb = g_x + (size_t)b * XPAD;

    int l0 = (width * z) >> 2, l1 = (width * (z + 1)) >> 2;
    const __half2* base = (const __half2*)(g_Ef16 + (size_t)(g_offs[b] + l0) * D_) + tid;
    float a0 = 0.f, a1 = 0.f;
    for (int l = l0; l < l1; l++) {
        float wv = ws[l];
        float2 f = __half22float2(*base);
        base += D_ / 2;
        a0 += wv * f.x;
        a1 += wv * f.y;
    }
    atomicAdd(&xb[1536 + 2 * tid],     a0 * inv);
    atomicAdd(&xb[1536 + 2 * tid + 1], a1 * inv);

    if (z == 0) {
        const float* Ebase = E + (size_t)b * L_ * D_;
        const float* rs = Ebase + (size_t)s * D_;
        const float* re = Ebase + (size_t)e * D_;
        for (int dd = tid; dd < D_; dd += 384) { xb[dd] = rs[dd]; xb[D_ + dd] = re[dd]; }
        if (tid < 20) {
            const int bins[15] = {1,2,3,4,5,6,7,8,12,16,20,24,32,64,128};
            int idx = 0;
            #pragma unroll
            for (int j = 0; j < 15; j++) idx += (width > bins[j]) ? 1 : 0;
            xb[2304 + tid] = width_emb[idx * 20 + tid];
        }
    }
}

// ---------------- fp16 3-pass GEMM with K-split partials ------------------------
// block 128(M)x128(N), 128 threads (4 warps 2x2, warp 64x64), K-chunk 32.
// A,W fp32; runtime hi/lo fp16 split; c += al*bh + ah*bl + ah*bh (fp32 accum).
// Layouts identical to attn_kernel's proven A/B fragment layouts.
__global__ void __launch_bounds__(128) gemm_f16(const float* __restrict__ A,
                                                const float* __restrict__ W,
                                                float* __restrict__ part,
                                                int M, int N, int K, int S) {
    __shared__ char Ah[10240], Al[10240];    // 128 rows x 80B
    __shared__ char Bh[BT_BYTES], Bl[BT_BYTES];
    int tid = threadIdx.x;
    int warp = tid >> 5, lane = tid & 31, g = lane >> 2, tig = lane & 3;
    int wm = warp >> 1, wn = warp & 1;
    int bm = blockIdx.y * 128, bn = blockIdx.x * 128;
    int nch = K >> 5;
    int z = blockIdx.z;
    int c0 = (int)((long)nch * z / S), c1 = (int)((long)nch * (z + 1) / S);

    // B-store mapping for this thread: owns k-row r = tid>>2, n range (tid&3)*32
    int br = tid >> 2, bnseg = (tid & 3) * 32;
    int bks = br >> 4, bkk = br & 15;
    int btg = (bkk & 7) >> 1;
    int bcc = (bkk & 1) | ((bkk >> 3) << 1);
    uint32_t bbase_off = bks * 4224 + btg * 1056 + bcc * 2;

    float c[4][8][4] = {};

    for (int ch = c0; ch < c1; ch++) {
        int k0 = ch * 32;
        // A: thread owns row tid; 32 floats -> hi/lo halves, k-contiguous
        {
            const float4* src = (const float4*)(A + (size_t)(bm + tid) * K + k0);
            #pragma unroll
            for (int u = 0; u < 8; u++) {
                float4 v = src[u];
                __half h0, h1, h2, h3, l0h, l1h, l2h, l3h;
                h_split(v.x, h0, l0h); h_split(v.y, h1, l1h);
                h_split(v.z, h2, l2h); h_split(v.w, h3, l3h);
                __half2 hp0 = __halves2half2(h0, h1), hp1 = __halves2half2(h2, h3);
                __half2 lp0 = __halves2half2(l0h, l1h), lp1 = __halves2half2(l2h, l3h);
                *(uint32_t*)(Ah + tid * A_RSB + u * 8)     = *(uint32_t*)&hp0;
                *(uint32_t*)(Ah + tid * A_RSB + u * 8 + 4) = *(uint32_t*)&hp1;
                *(uint32_t*)(Al + tid * A_RSB + u * 8)     = *(uint32_t*)&lp0;
                *(uint32_t*)(Al + tid * A_RSB + u * 8 + 4) = *(uint32_t*)&lp1;
            }
        }
        // B: thread owns k-row br, 32 n values -> quad-packed halves
        {
            const float4* src = (const float4*)(W + (size_t)(k0 + br) * N + bn + bnseg);
            #pragma unroll
            for (int u = 0; u < 8; u++) {
                float4 v = src[u];
                float vv[4] = {v.x, v.y, v.z, v.w};
                #pragma unroll
                for (int q = 0; q < 4; q++) {
                    int n = bnseg + u * 4 + q;
                    __half hh, ll;
                    h_split(vv[q], hh, ll);
                    *(unsigned short*)(Bh + bbase_off + n * 8) = *(unsigned short*)&hh;
                    *(unsigned short*)(Bl + bbase_off + n * 8) = *(unsigned short*)&ll;
                }
            }
        }
        __syncthreads();
        #pragma unroll
        for (int ks = 0; ks < 2; ks++) {
            uint32_t ah[4][4], al[4][4];
            uint2 bh[8], bl[8];
            #pragma unroll
            for (int i = 0; i < 4; i++) {
                int off = (wm * 64 + i * 16 + g) * A_RSB + ks * 32 + tig * 4;
                ah[i][0] = *(const uint32_t*)(Ah + off);
                ah[i][2] = *(const uint32_t*)(Ah + off + 16);
                ah[i][1] = *(const uint32_t*)(Ah + off + 8 * A_RSB);
                ah[i][3] = *(const uint32_t*)(Ah + off + 8 * A_RSB + 16);
                al[i][0] = *(const uint32_t*)(Al + off);
                al[i][2] = *(const uint32_t*)(Al + off + 16);
                al[i][1] = *(const uint32_t*)(Al + off + 8 * A_RSB);
                al[i][3] = *(const uint32_t*)(Al + off + 8 * A_RSB + 16);
            }
            #pragma unroll
            for (int j = 0; j < 8; j++) {
                int n = wn * 64 + j * 8 + g;
                bh[j] = *(const uint2*)(Bh + ks * 4224 + tig * 1056 + n * 8);
                bl[j] = *(const uint2*)(Bl + ks * 4224 + tig * 1056 + n * 8);
            }
            #pragma unroll
            for (int i = 0; i < 4; i++)
                #pragma unroll
                for (int j = 0; j < 8; j++) {
                    mma_f16(c[i][j], al[i][0], al[i][1], al[i][2], al[i][3], bh[j].x, bh[j].y);
                    mma_f16(c[i][j], ah[i][0], ah[i][1], ah[i][2], ah[i][3], bl[j].x, bl[j].y);
                    mma_f16(c[i][j], ah[i][0], ah[i][1], ah[i][2], ah[i][3], bh[j].x, bh[j].y);
                }
        }
        __syncthreads();
    }
    float* dst = part + ((size_t)z * M + bm) * N + bn;
    #pragma unroll
    for (int i = 0; i < 4; i++)
        #pragma unroll
        for (int j = 0; j < 8; j++) {
            int row = wm * 64 + i * 16 + g, col = wn * 64 + j * 8 + tig * 2;
            dst[(size_t)row * N + col]       = c[i][j][0];
            dst[(size_t)row * N + col + 1]   = c[i][j][1];
            dst[(size_t)(row+8) * N + col]   = c[i][j][2];
            dst[(size_t)(row+8) * N + col+1] = c[i][j][3];
        }
}

template<int ACT>
__global__ void combine(const float* __restrict__ part, const float* __restrict__ bias,
                        float* __restrict__ out, int MN, int N, int S) {
    int i = blockIdx.x * 256 + threadIdx.x;
    if (i >= MN) return;
    float v = 0.f;
    for (int z = 0; z < S; z++) v += part[(size_t)z * MN + i];
    v += bias[i % N];
    if (ACT) v = v > 0.f ? v : 0.01f * v;
    out[i] = v;
}

// ---------------- small fp32 GEMM for the final 256x30 layer --------------------
__global__ void __launch_bounds__(256) gemm_last(const float* __restrict__ A,
                                                 const float* __restrict__ W,
                                                 const float* __restrict__ bias,
                                                 float* __restrict__ C) {
    int m = blockIdx.x;
    int tid = threadIdx.x;
    int col = tid % 30, seg = tid / 30;
    __shared__ float red[256];
    float v = 0.f;
    if (seg < 8) {
        const float* a = A + (size_t)m * 256 + seg * 32;
        const float* w = W + col;
        #pragma unroll
        for (int k = 0; k < 32; k++) v += a[k] * w[(size_t)(seg * 32 + k) * 30];
    }
    red[tid] = v;
    __syncthreads();
    if (tid < 30) {
        float acc = 0.f;
        #pragma unroll
        for (int s2 = 0; s2 < 8; s2++) acc += red[s2 * 30 + tid];
        C[(size_t)m * 30 + tid] = acc + bias[tid];
    }
}

// ---------------- launch ---------------------------------------------------------
extern "C" void kernel_launch(void* const* d_in, const int* in_sizes, int n_in,
                              void* d_out, int out_size) {
    const float* embeds    = (const float*)d_in[0];
    const int*   spans_raw = (const int*)d_in[1];
    const float* aw1       = (const float*)d_in[2];
    const float* ab1       = (const float*)d_in[3];
    const float* aw2       = (const float*)d_in[4];
    // d_in[5] = ab2 : uniform logit offset, softmax-invariant -> unused
    const float* width_emb = (const float*)d_in[6];
    const float* sw1 = (const float*)d_in[7];
    const float* sb1 = (const float*)d_in[8];
    const float* sw2 = (const float*)d_in[9];
    const float* sb2 = (const float*)d_in[10];
    const float* sw3 = (const float*)d_in[11];
    const float* sb3 = (const float*)d_in[12];
    const float* sw4 = (const float*)d_in[13];
    const float* sb4 = (const float*)d_in[14];
    float* out = (float*)d_out;

    float *x, *h1, *h2, *h3, *part, *sw1p;
    cudaGetSymbolAddress((void**)&x,    g_x);
    cudaGetSymbolAddress((void**)&h1,   g_h1);
    cudaGetSymbolAddress((void**)&h2,   g_h2);
    cudaGetSymbolAddress((void**)&h3,   g_h3);
    cudaGetSymbolAddress((void**)&part, g_part);
    cudaGetSymbolAddress((void**)&sw1p, g_sw1p);

    prep_sc<<<1, 256>>>(spans_raw);                                           // 1
    prep_all<<<dim3(1024, 22), 256>>>(embeds, aw1, ab1, aw2, sw1);            // 2
    attn_kernel<<<8192, 128, ATTN_SMEM>>>();                                  // 3
    sm_wsum<<<dim3(B_, 4), 384>>>(embeds, width_emb);                         // 4 <- profiled
    gemm_f16<<<dim3(8, 2, MLPS), 128>>>(x,  sw1p, part, 256, 1024, XPAD, MLPS);
    combine<1><<<(256 * 1024) / 256, 256>>>(part, sb1, h1, 256 * 1024, 1024, MLPS);
    gemm_f16<<<dim3(4, 2, MLPS), 128>>>(h1, sw2,  part, 256, 512, 1024, MLPS);
    combine<1><<<(256 * 512) / 256, 256>>>(part, sb2, h2, 256 * 512, 512, MLPS);
    gemm_f16<<<dim3(2, 2, MLPS), 128>>>(h2, sw3,  part, 256, 256, 512, MLPS);
    combine<1><<<(256 * 256) / 256, 256>>>(part, sb3, h3, 256 * 256, 256, MLPS);
    gemm_last<<<256, 256>>>(h3, sw4, sb4, out);
}